// round 1
// baseline (speedup 1.0000x reference)
#include <cuda_runtime.h>
#include <math.h>

#define BSZ 2
#define SEQ 2048
#define DIMM 1024
#define CCH 1024
#define NHH 16
#define HDD 64
#define MROWS (BSZ*SEQ)   // 4096

// ---------------- scratch (device globals; no runtime allocation) ----------------
__device__ float g_q[MROWS*CCH];
__device__ float g_k[MROWS*CCH];
__device__ float g_v[MROWS*CCH];
__device__ float g_qc[MROWS*CCH];
__device__ float g_kc[MROWS*CCH];
__device__ float g_vc[MROWS*CCH];
__device__ float g_ao[MROWS*CCH];

// ---------------- GEMM: C[m,n] = (A[m,:] . W[n,:]) + bias[n], optional SiLU ------
// A: [M,K] row-major, W: [N,K] row-major, C: [M,N] row-major. M=4096,N=1024,K=1024.
struct GArgs { const float* A; const float* W; const float* bias; float* C; };

template<bool SILU>
__global__ void __launch_bounds__(256) gemm_nt_k(GArgs ga0, GArgs ga1, GArgs ga2)
{
    GArgs ga = (blockIdx.z == 0) ? ga0 : ((blockIdx.z == 1) ? ga1 : ga2);
    const int K = DIMM;

    __shared__ float As[16][128];
    __shared__ float Bs[16][128];

    int tid = threadIdx.x;
    int tx = tid & 15;
    int ty = tid >> 4;
    int m0 = blockIdx.y * 128;
    int n0 = blockIdx.x * 128;

    const float* A = ga.A + (size_t)m0 * K;
    const float* W = ga.W + (size_t)n0 * K;

    float acc[8][8];
    #pragma unroll
    for (int i = 0; i < 8; i++)
        #pragma unroll
        for (int j = 0; j < 8; j++) acc[i][j] = 0.f;

    int lk = (tid & 3) * 4;   // 0,4,8,12
    int lr = tid >> 2;        // 0..63

    for (int kk = 0; kk < K; kk += 16) {
        float4 a0 = *(const float4*)(A + (size_t)lr * K + kk + lk);
        float4 a1 = *(const float4*)(A + (size_t)(lr + 64) * K + kk + lk);
        float4 b0 = *(const float4*)(W + (size_t)lr * K + kk + lk);
        float4 b1 = *(const float4*)(W + (size_t)(lr + 64) * K + kk + lk);
        __syncthreads();
        As[lk + 0][lr] = a0.x; As[lk + 1][lr] = a0.y; As[lk + 2][lr] = a0.z; As[lk + 3][lr] = a0.w;
        As[lk + 0][lr + 64] = a1.x; As[lk + 1][lr + 64] = a1.y; As[lk + 2][lr + 64] = a1.z; As[lk + 3][lr + 64] = a1.w;
        Bs[lk + 0][lr] = b0.x; Bs[lk + 1][lr] = b0.y; Bs[lk + 2][lr] = b0.z; Bs[lk + 3][lr] = b0.w;
        Bs[lk + 0][lr + 64] = b1.x; Bs[lk + 1][lr + 64] = b1.y; Bs[lk + 2][lr + 64] = b1.z; Bs[lk + 3][lr + 64] = b1.w;
        __syncthreads();

        #pragma unroll
        for (int k = 0; k < 16; k++) {
            float a[8], bb[8];
            *(float4*)&a[0]  = *(const float4*)&As[k][ty * 8];
            *(float4*)&a[4]  = *(const float4*)&As[k][ty * 8 + 4];
            *(float4*)&bb[0] = *(const float4*)&Bs[k][tx * 8];
            *(float4*)&bb[4] = *(const float4*)&Bs[k][tx * 8 + 4];
            #pragma unroll
            for (int i = 0; i < 8; i++)
                #pragma unroll
                for (int j = 0; j < 8; j++)
                    acc[i][j] = fmaf(a[i], bb[j], acc[i][j]);
        }
    }

    #pragma unroll
    for (int i = 0; i < 8; i++) {
        int m = m0 + ty * 8 + i;
        float* orow = ga.C + (size_t)m * CCH + n0 + tx * 8;
        float vb[8];
        #pragma unroll
        for (int j = 0; j < 8; j++) {
            float vv = acc[i][j] + ga.bias[n0 + tx * 8 + j];
            if (SILU) vv = vv / (1.f + __expf(-vv));
            vb[j] = vv;
        }
        *(float4*)orow       = *(float4*)&vb[0];
        *(float4*)(orow + 4) = *(float4*)&vb[4];
    }
}

// ---------------- depthwise conv k=3 pad=1 over sequence (per batch) -------------
__global__ void dwconv_k(const float* iq, const float* ik, const float* iv,
                         const float* wqd, const float* wkd, const float* wvd,
                         const float* bqd, const float* bkd, const float* bvd,
                         float* oq, float* ok, float* ov)
{
    int z = blockIdx.y;
    const float* in = (z == 0) ? iq : ((z == 1) ? ik : iv);
    const float* w  = (z == 0) ? wqd : ((z == 1) ? wkd : wvd);
    const float* bb = (z == 0) ? bqd : ((z == 1) ? bkd : bvd);
    float* out      = (z == 0) ? oq : ((z == 1) ? ok : ov);

    int idx = blockIdx.x * blockDim.x + threadIdx.x;
    if (idx >= MROWS * CCH) return;
    int c = idx & (CCH - 1);
    int m = idx >> 10;
    int s = m & (SEQ - 1);

    float w0 = w[c * 3 + 0], w1 = w[c * 3 + 1], w2 = w[c * 3 + 2];
    float val = in[idx] * w1 + bb[c];
    if (s > 0)        val += in[idx - CCH] * w0;
    if (s < SEQ - 1)  val += in[idx + CCH] * w2;
    out[idx] = val;
}

// ---------------- per-head L2 normalize (in place) for q and k -------------------
__global__ void l2norm_k(float* q, float* k)
{
    float* p = (blockIdx.y == 0) ? q : k;
    int warp = threadIdx.x >> 5;
    int lane = threadIdx.x & 31;
    int g = blockIdx.x * 8 + warp;          // 0 .. MROWS*NHH-1 (groups of 64 contiguous)
    float* row = p + (size_t)g * HDD;
    float x0 = row[lane], x1 = row[lane + 32];
    float ss = x0 * x0 + x1 * x1;
    #pragma unroll
    for (int o = 16; o; o >>= 1) ss += __shfl_xor_sync(0xffffffffu, ss, o);
    float inv = 1.f / fmaxf(sqrtf(ss), 1e-12f);
    row[lane]      = x0 * inv;
    row[lane + 32] = x1 * inv;
}

// ---------------- flash attention (fp32, cosine attn, softmax over K) ------------
#define APAD 68
#define ASMEM (4 * 64 * APAD * 4)

__global__ void __launch_bounds__(256) attn_k(const float* __restrict__ Q,
                                              const float* __restrict__ K,
                                              const float* __restrict__ V,
                                              const int* __restrict__ mask,
                                              float* __restrict__ O)
{
    // grid: (S/64, NH, B)
    int qt = blockIdx.x, h = blockIdx.y, b = blockIdx.z;
    extern __shared__ float sm[];
    float* Qs = sm;                 // [d][r] transposed
    float* Ks = Qs + 64 * APAD;     // [d][c] transposed
    float* Vs = Ks + 64 * APAD;     // [c][d] natural
    float* Ps = Vs + 64 * APAD;     // [c][r] transposed
    __shared__ int s_mask[64];

    int tid = threadIdx.x;
    int tx = tid & 15;
    int ty = tid >> 4;

    // load Q tile (already L2-normalized) transposed
    {
        size_t base = ((size_t)(b * SEQ + qt * 64)) * CCH + h * HDD;
        for (int idx = tid; idx < 64 * 64; idx += 256) {
            int r = idx >> 6, d = idx & 63;
            Qs[d * APAD + r] = Q[base + (size_t)r * CCH + d];
        }
    }

    float m_i[4], l_i[4], o[4][4];
    #pragma unroll
    for (int i = 0; i < 4; i++) {
        m_i[i] = -1e30f; l_i[i] = 0.f;
        #pragma unroll
        for (int j = 0; j < 4; j++) o[i][j] = 0.f;
    }

    for (int jt = 0; jt < SEQ / 64; jt++) {
        __syncthreads();   // guard Ks/Vs/Ps reuse from previous iteration
        size_t base = ((size_t)(b * SEQ + jt * 64)) * CCH + h * HDD;
        for (int idx = tid; idx < 64 * 64; idx += 256) {
            int c = idx >> 6, d = idx & 63;
            float kv = K[base + (size_t)c * CCH + d];
            Ks[d * APAD + c] = kv;
            Vs[c * APAD + d] = V[base + (size_t)c * CCH + d];
        }
        if (tid < 64) s_mask[tid] = mask[b * SEQ + jt * 64 + tid];
        __syncthreads();

        // S = Q K^T  (4x4 microtile, thread layout 16x16)
        float s[4][4];
        #pragma unroll
        for (int i = 0; i < 4; i++)
            #pragma unroll
            for (int j = 0; j < 4; j++) s[i][j] = 0.f;

        #pragma unroll 4
        for (int k = 0; k < 64; k++) {
            float4 aq = *(const float4*)&Qs[k * APAD + ty * 4];
            float4 bk = *(const float4*)&Ks[k * APAD + tx * 4];
            float av[4] = {aq.x, aq.y, aq.z, aq.w};
            float bv[4] = {bk.x, bk.y, bk.z, bk.w};
            #pragma unroll
            for (int i = 0; i < 4; i++)
                #pragma unroll
                for (int j = 0; j < 4; j++)
                    s[i][j] = fmaf(av[i], bv[j], s[i][j]);
        }

        // scale + mask
        #pragma unroll
        for (int j = 0; j < 4; j++) {
            bool ok = s_mask[tx * 4 + j] != 0;
            #pragma unroll
            for (int i = 0; i < 4; i++)
                s[i][j] = ok ? s[i][j] * 0.125f : -1e30f;
        }

        // streaming softmax (row reduction across the 16 tx lanes)
        #pragma unroll
        for (int i = 0; i < 4; i++) {
            float mx = fmaxf(fmaxf(s[i][0], s[i][1]), fmaxf(s[i][2], s[i][3]));
            #pragma unroll
            for (int off = 8; off; off >>= 1)
                mx = fmaxf(mx, __shfl_xor_sync(0xffffffffu, mx, off));
            float m_new = fmaxf(m_i[i], mx);
            float alpha = __expf(m_i[i] - m_new);
            float rs = 0.f;
            #pragma unroll
            for (int j = 0; j < 4; j++) {
                float p = __expf(s[i][j] - m_new);
                s[i][j] = p;
                rs += p;
            }
            #pragma unroll
            for (int off = 8; off; off >>= 1)
                rs += __shfl_xor_sync(0xffffffffu, rs, off);
            l_i[i] = l_i[i] * alpha + rs;
            m_i[i] = m_new;
            #pragma unroll
            for (int j = 0; j < 4; j++) o[i][j] *= alpha;
            // store P transposed: Ps[c][r]
            #pragma unroll
            for (int j = 0; j < 4; j++)
                Ps[(tx * 4 + j) * APAD + ty * 4 + i] = s[i][j];
        }
        __syncthreads();

        // O += P V
        #pragma unroll 4
        for (int c = 0; c < 64; c++) {
            float4 pv = *(const float4*)&Ps[c * APAD + ty * 4];
            float4 vv = *(const float4*)&Vs[c * APAD + tx * 4];
            float pa[4] = {pv.x, pv.y, pv.z, pv.w};
            float vb[4] = {vv.x, vv.y, vv.z, vv.w};
            #pragma unroll
            for (int i = 0; i < 4; i++)
                #pragma unroll
                for (int j = 0; j < 4; j++)
                    o[i][j] = fmaf(pa[i], vb[j], o[i][j]);
        }
    }

    // epilogue
    #pragma unroll
    for (int i = 0; i < 4; i++) {
        float inv = 1.f / l_i[i];
        int r = qt * 64 + ty * 4 + i;
        float vb[4];
        #pragma unroll
        for (int j = 0; j < 4; j++) vb[j] = o[i][j] * inv;
        float* dst = O + ((size_t)(b * SEQ + r)) * CCH + h * HDD + tx * 4;
        *(float4*)dst = *(float4*)&vb[0];
    }
}

// ---------------- host launcher ---------------------------------------------------
extern "C" void kernel_launch(void* const* d_in, const int* in_sizes, int n_in,
                              void* d_out, int out_size)
{
    const float* x    = (const float*)d_in[0];
    const int*   mask = (const int*)d_in[1];
    const float* wq   = (const float*)d_in[2];
    const float* bq   = (const float*)d_in[3];
    const float* wk   = (const float*)d_in[4];
    const float* bk   = (const float*)d_in[5];
    const float* wv   = (const float*)d_in[6];
    const float* bv   = (const float*)d_in[7];
    const float* qdww = (const float*)d_in[8];
    const float* qdwb = (const float*)d_in[9];
    const float* qpww = (const float*)d_in[10];
    const float* qpwb = (const float*)d_in[11];
    const float* kdww = (const float*)d_in[12];
    const float* kdwb = (const float*)d_in[13];
    const float* kpww = (const float*)d_in[14];
    const float* kpwb = (const float*)d_in[15];
    const float* vdww = (const float*)d_in[16];
    const float* vdwb = (const float*)d_in[17];
    const float* vpww = (const float*)d_in[18];
    const float* vpwb = (const float*)d_in[19];
    const float* wo   = (const float*)d_in[20];
    const float* bo   = (const float*)d_in[21];
    float* out = (float*)d_out;

    float *q, *k, *v, *qc, *kc, *vc, *ao;
    cudaGetSymbolAddress((void**)&q,  g_q);
    cudaGetSymbolAddress((void**)&k,  g_k);
    cudaGetSymbolAddress((void**)&v,  g_v);
    cudaGetSymbolAddress((void**)&qc, g_qc);
    cudaGetSymbolAddress((void**)&kc, g_kc);
    cudaGetSymbolAddress((void**)&vc, g_vc);
    cudaGetSymbolAddress((void**)&ao, g_ao);

    cudaFuncSetAttribute(attn_k, cudaFuncAttributeMaxDynamicSharedMemorySize, ASMEM);

    dim3 gemm_grid3(8, 32, 3);
    dim3 gemm_grid1(8, 32, 1);

    // 1) QKV projection + SiLU
    gemm_nt_k<true><<<gemm_grid3, 256>>>(GArgs{x, wq, bq, q},
                                         GArgs{x, wk, bk, k},
                                         GArgs{x, wv, bv, v});

    // 2) depthwise conv k=3 over sequence
    dwconv_k<<<dim3((MROWS * CCH) / 256, 3), 256>>>(q, k, v,
                                                    qdww, kdww, vdww,
                                                    qdwb, kdwb, vdwb,
                                                    qc, kc, vc);

    // 3) pointwise 1x1 conv (GEMM, no activation)
    gemm_nt_k<false><<<gemm_grid3, 256>>>(GArgs{qc, qpww, qpwb, q},
                                          GArgs{kc, kpww, kpwb, k},
                                          GArgs{vc, vpww, vpwb, v});

    // 4) per-head L2 normalize q, k
    l2norm_k<<<dim3((MROWS * NHH) / 8, 2), 256>>>(q, k);

    // 5) flash attention
    attn_k<<<dim3(SEQ / 64, NHH, BSZ), 256, ASMEM>>>(q, k, v, mask, ao);

    // 6) output projection -> d_out
    gemm_nt_k<false><<<gemm_grid1, 256>>>(GArgs{ao, wo, bo, out},
                                          GArgs{ao, wo, bo, out},
                                          GArgs{ao, wo, bo, out});
}

// round 3
// speedup vs baseline: 1.4238x; 1.4238x over previous
#include <cuda_runtime.h>
#include <cuda_bf16.h>
#include <math.h>
#include <stdint.h>

#define BSZ 2
#define SEQ 2048
#define DIMM 1024
#define CCH 1024
#define NHH 16
#define HDD 64
#define MROWS (BSZ*SEQ)   // 4096

// ---------------- scratch (device globals; no runtime allocation) ----------------
__device__ float g_q[MROWS*CCH];
__device__ float g_k[MROWS*CCH];
__device__ float g_v[MROWS*CCH];
__device__ float g_qc[MROWS*CCH];
__device__ float g_kc[MROWS*CCH];
__device__ float g_vc[MROWS*CCH];
__device__ float g_ao[MROWS*CCH];

// ================= mma.sync bf16 helpers =========================================
__device__ __forceinline__ uint32_t packbf(__nv_bfloat16 a, __nv_bfloat16 b) {
    __nv_bfloat162 t = __halves2bfloat162(a, b);
    return *reinterpret_cast<uint32_t*>(&t);
}
__device__ __forceinline__ void split4(float4 v, uint32_t& h0, uint32_t& h1,
                                       uint32_t& l0, uint32_t& l1) {
    __nv_bfloat16 hx = __float2bfloat16_rn(v.x);
    __nv_bfloat16 hy = __float2bfloat16_rn(v.y);
    __nv_bfloat16 hz = __float2bfloat16_rn(v.z);
    __nv_bfloat16 hw = __float2bfloat16_rn(v.w);
    __nv_bfloat16 lx = __float2bfloat16_rn(v.x - __bfloat162float(hx));
    __nv_bfloat16 ly = __float2bfloat16_rn(v.y - __bfloat162float(hy));
    __nv_bfloat16 lz = __float2bfloat16_rn(v.z - __bfloat162float(hz));
    __nv_bfloat16 lw = __float2bfloat16_rn(v.w - __bfloat162float(hw));
    h0 = packbf(hx, hy); h1 = packbf(hz, hw);
    l0 = packbf(lx, ly); l1 = packbf(lz, lw);
}
__device__ __forceinline__ void mma_bf16(float* d, const uint32_t* a, const uint32_t* b) {
    asm volatile(
        "mma.sync.aligned.m16n8k16.row.col.f32.bf16.bf16.f32 "
        "{%0,%1,%2,%3}, {%4,%5,%6,%7}, {%8,%9}, {%0,%1,%2,%3};"
        : "+f"(d[0]), "+f"(d[1]), "+f"(d[2]), "+f"(d[3])
        : "r"(a[0]), "r"(a[1]), "r"(a[2]), "r"(a[3]), "r"(b[0]), "r"(b[1]));
}

// ================= bf16 split-2 (3-product) GEMM via mma.sync ====================
// C[m,n] = sum_k A[m,k]*W[n,k] + bias[n]; M=4096, N=1024, K=1024.
// CTA 128x128, KC=32, 512 threads (16 warps, 4x4 grid, warp tile 32x32).
struct GArgs { const float* A; const float* W; const float* bias; float* C; };

#define GSTRIDE 20                 // u32 words per plane row (16 data + 4 pad)
#define PLANE_W (128*GSTRIDE)      // 2560 words
#define STAGE_W (4*PLANE_W)        // Ahi,Alo,Bhi,Blo
#define G_SMEM_BYTES (2*STAGE_W*4) // 81920 B

template<bool SILU>
__global__ void __launch_bounds__(512) gemm_bf16_k(GArgs ga0, GArgs ga1, GArgs ga2)
{
    GArgs ga = (blockIdx.z == 0) ? ga0 : ((blockIdx.z == 1) ? ga1 : ga2);
    extern __shared__ uint32_t smw[];

    const int tid = threadIdx.x;
    const int lane = tid & 31, wid = tid >> 5;
    const int wm = wid & 3, wn = wid >> 2;       // 4x4 warp grid
    const int gr = lane >> 2, gc = lane & 3;
    const int m0 = blockIdx.y * 128, n0 = blockIdx.x * 128;

    const float* A = ga.A + (size_t)m0 * DIMM;
    const float* B = ga.W + (size_t)n0 * DIMM;

    const int row0 = tid >> 3;    // 0..63 ; second chunk uses row0+64
    const int f4 = tid & 7;       // float4 index within 32-float row

    float4 av0, av1, bv0, bv1;

    // ---- pipeline helpers ----
    #define GLOAD(kk)  do { \
        av0 = *(const float4*)(A + (size_t)row0 * DIMM + (kk) + f4 * 4); \
        av1 = *(const float4*)(A + (size_t)(row0 + 64) * DIMM + (kk) + f4 * 4); \
        bv0 = *(const float4*)(B + (size_t)row0 * DIMM + (kk) + f4 * 4); \
        bv1 = *(const float4*)(B + (size_t)(row0 + 64) * DIMM + (kk) + f4 * 4); \
    } while (0)

    #define SSTORE(buf) do { \
        uint32_t* st = smw + (buf) * STAGE_W; \
        uint32_t h0, h1, l0, l1; \
        int w0 = row0 * GSTRIDE + f4 * 2; \
        int w1 = (row0 + 64) * GSTRIDE + f4 * 2; \
        split4(av0, h0, h1, l0, l1); \
        st[w0] = h0; st[w0 + 1] = h1; st[PLANE_W + w0] = l0; st[PLANE_W + w0 + 1] = l1; \
        split4(av1, h0, h1, l0, l1); \
        st[w1] = h0; st[w1 + 1] = h1; st[PLANE_W + w1] = l0; st[PLANE_W + w1 + 1] = l1; \
        split4(bv0, h0, h1, l0, l1); \
        st[2 * PLANE_W + w0] = h0; st[2 * PLANE_W + w0 + 1] = h1; \
        st[3 * PLANE_W + w0] = l0; st[3 * PLANE_W + w0 + 1] = l1; \
        split4(bv1, h0, h1, l0, l1); \
        st[2 * PLANE_W + w1] = h0; st[2 * PLANE_W + w1 + 1] = h1; \
        st[3 * PLANE_W + w1] = l0; st[3 * PLANE_W + w1 + 1] = l1; \
    } while (0)

    float acc[2][4][4];
    #pragma unroll
    for (int mi = 0; mi < 2; mi++)
        #pragma unroll
        for (int ni = 0; ni < 4; ni++)
            #pragma unroll
            for (int e = 0; e < 4; e++) acc[mi][ni][e] = 0.f;

    GLOAD(0);
    SSTORE(0);
    GLOAD(32);

    #pragma unroll 1
    for (int i = 0; i < 32; i++) {
        int b = i & 1;
        __syncthreads();
        if (i + 1 < 32) SSTORE(1 ^ b);
        if (i + 2 < 32) GLOAD((i + 2) * 32);

        const uint32_t* st = smw + b * STAGE_W;
        const uint32_t* Ah = st;
        const uint32_t* Al = st + PLANE_W;
        const uint32_t* Bh = st + 2 * PLANE_W;
        const uint32_t* Bl = st + 3 * PLANE_W;

        #pragma unroll
        for (int ki = 0; ki < 2; ki++) {
            int kw = ki * 8 + gc;
            uint32_t ah[2][4], al[2][4], bh[4][2], bl[4][2];
            #pragma unroll
            for (int mi = 0; mi < 2; mi++) {
                int r = wm * 32 + mi * 16 + gr;
                ah[mi][0] = Ah[r * GSTRIDE + kw];
                ah[mi][1] = Ah[(r + 8) * GSTRIDE + kw];
                ah[mi][2] = Ah[r * GSTRIDE + kw + 4];
                ah[mi][3] = Ah[(r + 8) * GSTRIDE + kw + 4];
                al[mi][0] = Al[r * GSTRIDE + kw];
                al[mi][1] = Al[(r + 8) * GSTRIDE + kw];
                al[mi][2] = Al[r * GSTRIDE + kw + 4];
                al[mi][3] = Al[(r + 8) * GSTRIDE + kw + 4];
            }
            #pragma unroll
            for (int ni = 0; ni < 4; ni++) {
                int n = wn * 32 + ni * 8 + gr;
                bh[ni][0] = Bh[n * GSTRIDE + kw];
                bh[ni][1] = Bh[n * GSTRIDE + kw + 4];
                bl[ni][0] = Bl[n * GSTRIDE + kw];
                bl[ni][1] = Bl[n * GSTRIDE + kw + 4];
            }
            #pragma unroll
            for (int ni = 0; ni < 4; ni++)
                #pragma unroll
                for (int mi = 0; mi < 2; mi++) {
                    mma_bf16(acc[mi][ni], ah[mi], bh[ni]);
                    mma_bf16(acc[mi][ni], ah[mi], bl[ni]);
                    mma_bf16(acc[mi][ni], al[mi], bh[ni]);
                }
        }
    }

    // ---- epilogue ----
    #pragma unroll
    for (int ni = 0; ni < 4; ni++) {
        int cg = n0 + wn * 32 + ni * 8 + 2 * gc;
        float b0 = ga.bias[cg], b1 = ga.bias[cg + 1];
        #pragma unroll
        for (int mi = 0; mi < 2; mi++) {
            int r = m0 + wm * 32 + mi * 16 + gr;
            float v0 = acc[mi][ni][0] + b0;
            float v1 = acc[mi][ni][1] + b1;
            float v2 = acc[mi][ni][2] + b0;
            float v3 = acc[mi][ni][3] + b1;
            if (SILU) {
                v0 = v0 / (1.f + __expf(-v0));
                v1 = v1 / (1.f + __expf(-v1));
                v2 = v2 / (1.f + __expf(-v2));
                v3 = v3 / (1.f + __expf(-v3));
            }
            *(float2*)(ga.C + (size_t)r * CCH + cg)       = make_float2(v0, v1);
            *(float2*)(ga.C + (size_t)(r + 8) * CCH + cg) = make_float2(v2, v3);
        }
    }
    #undef GLOAD
    #undef SSTORE
}

// ---------------- depthwise conv k=3 pad=1 over sequence (per batch) -------------
__global__ void dwconv_k(const float* iq, const float* ik, const float* iv,
                         const float* wqd, const float* wkd, const float* wvd,
                         const float* bqd, const float* bkd, const float* bvd,
                         float* oq, float* ok, float* ov)
{
    int z = blockIdx.y;
    const float* in = (z == 0) ? iq : ((z == 1) ? ik : iv);
    const float* w  = (z == 0) ? wqd : ((z == 1) ? wkd : wvd);
    const float* bb = (z == 0) ? bqd : ((z == 1) ? bkd : bvd);
    float* out      = (z == 0) ? oq : ((z == 1) ? ok : ov);

    int idx = blockIdx.x * blockDim.x + threadIdx.x;
    if (idx >= MROWS * CCH) return;
    int c = idx & (CCH - 1);
    int m = idx >> 10;
    int s = m & (SEQ - 1);

    float w0 = w[c * 3 + 0], w1 = w[c * 3 + 1], w2 = w[c * 3 + 2];
    float val = in[idx] * w1 + bb[c];
    if (s > 0)        val += in[idx - CCH] * w0;
    if (s < SEQ - 1)  val += in[idx + CCH] * w2;
    out[idx] = val;
}

// ---------------- per-head L2 normalize (in place) for q and k -------------------
__global__ void l2norm_k(float* q, float* k)
{
    float* p = (blockIdx.y == 0) ? q : k;
    int warp = threadIdx.x >> 5;
    int lane = threadIdx.x & 31;
    int g = blockIdx.x * 8 + warp;
    float* row = p + (size_t)g * HDD;
    float x0 = row[lane], x1 = row[lane + 32];
    float ss = x0 * x0 + x1 * x1;
    #pragma unroll
    for (int o = 16; o; o >>= 1) ss += __shfl_xor_sync(0xffffffffu, ss, o);
    float inv = 1.f / fmaxf(sqrtf(ss), 1e-12f);
    row[lane]      = x0 * inv;
    row[lane + 32] = x1 * inv;
}

// ---------------- flash attention (fp32, cosine attn, softmax over K) ------------
#define APAD 68
#define ASMEM (4 * 64 * APAD * 4)

__global__ void __launch_bounds__(256) attn_k(const float* __restrict__ Q,
                                              const float* __restrict__ K,
                                              const float* __restrict__ V,
                                              const int* __restrict__ mask,
                                              float* __restrict__ O)
{
    int qt = blockIdx.x, h = blockIdx.y, b = blockIdx.z;
    extern __shared__ float sm[];
    float* Qs = sm;
    float* Ks = Qs + 64 * APAD;
    float* Vs = Ks + 64 * APAD;
    float* Ps = Vs + 64 * APAD;
    __shared__ int s_mask[64];

    int tid = threadIdx.x;
    int tx = tid & 15;
    int ty = tid >> 4;

    {
        size_t base = ((size_t)(b * SEQ + qt * 64)) * CCH + h * HDD;
        for (int idx = tid; idx < 64 * 64; idx += 256) {
            int r = idx >> 6, d = idx & 63;
            Qs[d * APAD + r] = Q[base + (size_t)r * CCH + d];
        }
    }

    float m_i[4], l_i[4], o[4][4];
    #pragma unroll
    for (int i = 0; i < 4; i++) {
        m_i[i] = -1e30f; l_i[i] = 0.f;
        #pragma unroll
        for (int j = 0; j < 4; j++) o[i][j] = 0.f;
    }

    for (int jt = 0; jt < SEQ / 64; jt++) {
        __syncthreads();
        size_t base = ((size_t)(b * SEQ + jt * 64)) * CCH + h * HDD;
        for (int idx = tid; idx < 64 * 64; idx += 256) {
            int c = idx >> 6, d = idx & 63;
            Ks[d * APAD + c] = K[base + (size_t)c * CCH + d];
            Vs[c * APAD + d] = V[base + (size_t)c * CCH + d];
        }
        if (tid < 64) s_mask[tid] = mask[b * SEQ + jt * 64 + tid];
        __syncthreads();

        float s[4][4];
        #pragma unroll
        for (int i = 0; i < 4; i++)
            #pragma unroll
            for (int j = 0; j < 4; j++) s[i][j] = 0.f;

        #pragma unroll 4
        for (int k = 0; k < 64; k++) {
            float4 aq = *(const float4*)&Qs[k * APAD + ty * 4];
            float4 bk = *(const float4*)&Ks[k * APAD + tx * 4];
            float av[4] = {aq.x, aq.y, aq.z, aq.w};
            float bv[4] = {bk.x, bk.y, bk.z, bk.w};
            #pragma unroll
            for (int i = 0; i < 4; i++)
                #pragma unroll
                for (int j = 0; j < 4; j++)
                    s[i][j] = fmaf(av[i], bv[j], s[i][j]);
        }

        #pragma unroll
        for (int j = 0; j < 4; j++) {
            bool ok = s_mask[tx * 4 + j] != 0;
            #pragma unroll
            for (int i = 0; i < 4; i++)
                s[i][j] = ok ? s[i][j] * 0.125f : -1e30f;
        }

        #pragma unroll
        for (int i = 0; i < 4; i++) {
            float mx = fmaxf(fmaxf(s[i][0], s[i][1]), fmaxf(s[i][2], s[i][3]));
            #pragma unroll
            for (int off = 8; off; off >>= 1)
                mx = fmaxf(mx, __shfl_xor_sync(0xffffffffu, mx, off));
            float m_new = fmaxf(m_i[i], mx);
            float alpha = __expf(m_i[i] - m_new);
            float rs = 0.f;
            #pragma unroll
            for (int j = 0; j < 4; j++) {
                float p = __expf(s[i][j] - m_new);
                s[i][j] = p;
                rs += p;
            }
            #pragma unroll
            for (int off = 8; off; off >>= 1)
                rs += __shfl_xor_sync(0xffffffffu, rs, off);
            l_i[i] = l_i[i] * alpha + rs;
            m_i[i] = m_new;
            #pragma unroll
            for (int j = 0; j < 4; j++) o[i][j] *= alpha;
            #pragma unroll
            for (int j = 0; j < 4; j++)
                Ps[(tx * 4 + j) * APAD + ty * 4 + i] = s[i][j];
        }
        __syncthreads();

        #pragma unroll 4
        for (int c = 0; c < 64; c++) {
            float4 pv = *(const float4*)&Ps[c * APAD + ty * 4];
            float4 vv = *(const float4*)&Vs[c * APAD + tx * 4];
            float pa[4] = {pv.x, pv.y, pv.z, pv.w};
            float vb[4] = {vv.x, vv.y, vv.z, vv.w};
            #pragma unroll
            for (int i = 0; i < 4; i++)
                #pragma unroll
                for (int j = 0; j < 4; j++)
                    o[i][j] = fmaf(pa[i], vb[j], o[i][j]);
        }
    }

    #pragma unroll
    for (int i = 0; i < 4; i++) {
        float inv = 1.f / l_i[i];
        int r = qt * 64 + ty * 4 + i;
        float vb[4];
        #pragma unroll
        for (int j = 0; j < 4; j++) vb[j] = o[i][j] * inv;
        float* dst = O + ((size_t)(b * SEQ + r)) * CCH + h * HDD + tx * 4;
        *(float4*)dst = *(float4*)&vb[0];
    }
}

// ---------------- host launcher ---------------------------------------------------
extern "C" void kernel_launch(void* const* d_in, const int* in_sizes, int n_in,
                              void* d_out, int out_size)
{
    const float* x    = (const float*)d_in[0];
    const int*   mask = (const int*)d_in[1];
    const float* wq   = (const float*)d_in[2];
    const float* bq   = (const float*)d_in[3];
    const float* wk   = (const float*)d_in[4];
    const float* bk   = (const float*)d_in[5];
    const float* wv   = (const float*)d_in[6];
    const float* bv   = (const float*)d_in[7];
    const float* qdww = (const float*)d_in[8];
    const float* qdwb = (const float*)d_in[9];
    const float* qpww = (const float*)d_in[10];
    const float* qpwb = (const float*)d_in[11];
    const float* kdww = (const float*)d_in[12];
    const float* kdwb = (const float*)d_in[13];
    const float* kpww = (const float*)d_in[14];
    const float* kpwb = (const float*)d_in[15];
    const float* vdww = (const float*)d_in[16];
    const float* vdwb = (const float*)d_in[17];
    const float* vpww = (const float*)d_in[18];
    const float* vpwb = (const float*)d_in[19];
    const float* wo   = (const float*)d_in[20];
    const float* bo   = (const float*)d_in[21];
    float* out = (float*)d_out;

    float *q, *k, *v, *qc, *kc, *vc, *ao;
    cudaGetSymbolAddress((void**)&q,  g_q);
    cudaGetSymbolAddress((void**)&k,  g_k);
    cudaGetSymbolAddress((void**)&v,  g_v);
    cudaGetSymbolAddress((void**)&qc, g_qc);
    cudaGetSymbolAddress((void**)&kc, g_kc);
    cudaGetSymbolAddress((void**)&vc, g_vc);
    cudaGetSymbolAddress((void**)&ao, g_ao);

    cudaFuncSetAttribute(attn_k, cudaFuncAttributeMaxDynamicSharedMemorySize, ASMEM);
    cudaFuncSetAttribute(gemm_bf16_k<true>,  cudaFuncAttributeMaxDynamicSharedMemorySize, G_SMEM_BYTES);
    cudaFuncSetAttribute(gemm_bf16_k<false>, cudaFuncAttributeMaxDynamicSharedMemorySize, G_SMEM_BYTES);

    dim3 gemm_grid3(8, 32, 3);
    dim3 gemm_grid1(8, 32, 1);

    // 1) QKV projection + SiLU
    gemm_bf16_k<true><<<gemm_grid3, 512, G_SMEM_BYTES>>>(GArgs{x, wq, bq, q},
                                                         GArgs{x, wk, bk, k},
                                                         GArgs{x, wv, bv, v});

    // 2) depthwise conv k=3 over sequence
    dwconv_k<<<dim3((MROWS * CCH) / 256, 3), 256>>>(q, k, v,
                                                    qdww, kdww, vdww,
                                                    qdwb, kdwb, vdwb,
                                                    qc, kc, vc);

    // 3) pointwise 1x1 conv (GEMM, no activation)
    gemm_bf16_k<false><<<gemm_grid3, 512, G_SMEM_BYTES>>>(GArgs{qc, qpww, qpwb, q},
                                                          GArgs{kc, kpww, kpwb, k},
                                                          GArgs{vc, vpww, vpwb, v});

    // 4) per-head L2 normalize q, k
    l2norm_k<<<dim3((MROWS * NHH) / 8, 2), 256>>>(q, k);

    // 5) flash attention
    attn_k<<<dim3(SEQ / 64, NHH, BSZ), 256, ASMEM>>>(q, k, v, mask, ao);

    // 6) output projection -> d_out
    gemm_bf16_k<false><<<gemm_grid1, 512, G_SMEM_BYTES>>>(GArgs{ao, wo, bo, out},
                                                          GArgs{ao, wo, bo, out},
                                                          GArgs{ao, wo, bo, out});
}

// round 4
// speedup vs baseline: 2.4178x; 1.6981x over previous
#include <cuda_runtime.h>
#include <cuda_bf16.h>
#include <math.h>
#include <stdint.h>

#define BSZ 2
#define SEQ 2048
#define DIMM 1024
#define CCH 1024
#define NHH 16
#define HDD 64
#define MROWS (BSZ*SEQ)   // 4096

// ---------------- scratch (device globals; no runtime allocation) ----------------
__device__ float g_q[MROWS*CCH];
__device__ float g_k[MROWS*CCH];
__device__ float g_v[MROWS*CCH];
__device__ float g_qc[MROWS*CCH];
__device__ float g_kc[MROWS*CCH];
__device__ float g_vc[MROWS*CCH];
__device__ float g_ao[MROWS*CCH];

// ================= mma.sync bf16 helpers =========================================
__device__ __forceinline__ uint32_t packbf(__nv_bfloat16 a, __nv_bfloat16 b) {
    __nv_bfloat162 t = __halves2bfloat162(a, b);
    return *reinterpret_cast<uint32_t*>(&t);
}
__device__ __forceinline__ uint32_t pack2h(float x, float y) {
    return packbf(__float2bfloat16_rn(x), __float2bfloat16_rn(y));
}
__device__ __forceinline__ void split2(float x, float y, uint32_t& h, uint32_t& l) {
    __nv_bfloat16 hx = __float2bfloat16_rn(x);
    __nv_bfloat16 hy = __float2bfloat16_rn(y);
    h = packbf(hx, hy);
    l = pack2h(x - __bfloat162float(hx), y - __bfloat162float(hy));
}
__device__ __forceinline__ void split4(float4 v, uint32_t& h0, uint32_t& h1,
                                       uint32_t& l0, uint32_t& l1) {
    split2(v.x, v.y, h0, l0);
    split2(v.z, v.w, h1, l1);
}
__device__ __forceinline__ void mma_bf16(float* d, const uint32_t* a, const uint32_t* b) {
    asm volatile(
        "mma.sync.aligned.m16n8k16.row.col.f32.bf16.bf16.f32 "
        "{%0,%1,%2,%3}, {%4,%5,%6,%7}, {%8,%9}, {%0,%1,%2,%3};"
        : "+f"(d[0]), "+f"(d[1]), "+f"(d[2]), "+f"(d[3])
        : "r"(a[0]), "r"(a[1]), "r"(a[2]), "r"(a[3]), "r"(b[0]), "r"(b[1]));
}
__device__ __forceinline__ void mma_bf16_b(float* d, const uint32_t* a, uint32_t b0, uint32_t b1) {
    asm volatile(
        "mma.sync.aligned.m16n8k16.row.col.f32.bf16.bf16.f32 "
        "{%0,%1,%2,%3}, {%4,%5,%6,%7}, {%8,%9}, {%0,%1,%2,%3};"
        : "+f"(d[0]), "+f"(d[1]), "+f"(d[2]), "+f"(d[3])
        : "r"(a[0]), "r"(a[1]), "r"(a[2]), "r"(a[3]), "r"(b0), "r"(b1));
}

// ================= bf16 split-2 (3-product) GEMM via mma.sync ====================
// C[m,n] = sum_k A[m,k]*W[n,k] + bias[n]; M=4096, N=1024, K=1024.
// CTA 128x128, KC=32, 512 threads (16 warps, 4x4 grid, warp tile 32x32).
struct GArgs { const float* A; const float* W; const float* bias; float* C; };

#define GSTRIDE 20                 // u32 words per plane row (16 data + 4 pad)
#define PLANE_W (128*GSTRIDE)      // 2560 words
#define STAGE_W (4*PLANE_W)        // Ahi,Alo,Bhi,Blo
#define G_SMEM_BYTES (2*STAGE_W*4) // 81920 B

template<bool SILU>
__global__ void __launch_bounds__(512) gemm_bf16_k(GArgs ga0, GArgs ga1, GArgs ga2)
{
    GArgs ga = (blockIdx.z == 0) ? ga0 : ((blockIdx.z == 1) ? ga1 : ga2);
    extern __shared__ uint32_t smw[];

    const int tid = threadIdx.x;
    const int lane = tid & 31, wid = tid >> 5;
    const int wm = wid & 3, wn = wid >> 2;       // 4x4 warp grid
    const int gr = lane >> 2, gc = lane & 3;
    const int m0 = blockIdx.y * 128, n0 = blockIdx.x * 128;

    const float* A = ga.A + (size_t)m0 * DIMM;
    const float* B = ga.W + (size_t)n0 * DIMM;

    const int row0 = tid >> 3;    // 0..63 ; second chunk uses row0+64
    const int f4 = tid & 7;       // float4 index within 32-float row

    float4 av0, av1, bv0, bv1;

    #define GLOAD(kk)  do { \
        av0 = *(const float4*)(A + (size_t)row0 * DIMM + (kk) + f4 * 4); \
        av1 = *(const float4*)(A + (size_t)(row0 + 64) * DIMM + (kk) + f4 * 4); \
        bv0 = *(const float4*)(B + (size_t)row0 * DIMM + (kk) + f4 * 4); \
        bv1 = *(const float4*)(B + (size_t)(row0 + 64) * DIMM + (kk) + f4 * 4); \
    } while (0)

    #define SSTORE(buf) do { \
        uint32_t* st = smw + (buf) * STAGE_W; \
        uint32_t h0, h1, l0, l1; \
        int w0 = row0 * GSTRIDE + f4 * 2; \
        int w1 = (row0 + 64) * GSTRIDE + f4 * 2; \
        split4(av0, h0, h1, l0, l1); \
        st[w0] = h0; st[w0 + 1] = h1; st[PLANE_W + w0] = l0; st[PLANE_W + w0 + 1] = l1; \
        split4(av1, h0, h1, l0, l1); \
        st[w1] = h0; st[w1 + 1] = h1; st[PLANE_W + w1] = l0; st[PLANE_W + w1 + 1] = l1; \
        split4(bv0, h0, h1, l0, l1); \
        st[2 * PLANE_W + w0] = h0; st[2 * PLANE_W + w0 + 1] = h1; \
        st[3 * PLANE_W + w0] = l0; st[3 * PLANE_W + w0 + 1] = l1; \
        split4(bv1, h0, h1, l0, l1); \
        st[2 * PLANE_W + w1] = h0; st[2 * PLANE_W + w1 + 1] = h1; \
        st[3 * PLANE_W + w1] = l0; st[3 * PLANE_W + w1 + 1] = l1; \
    } while (0)

    float acc[2][4][4];
    #pragma unroll
    for (int mi = 0; mi < 2; mi++)
        #pragma unroll
        for (int ni = 0; ni < 4; ni++)
            #pragma unroll
            for (int e = 0; e < 4; e++) acc[mi][ni][e] = 0.f;

    GLOAD(0);
    SSTORE(0);
    GLOAD(32);

    #pragma unroll 1
    for (int i = 0; i < 32; i++) {
        int b = i & 1;
        __syncthreads();
        if (i + 1 < 32) SSTORE(1 ^ b);
        if (i + 2 < 32) GLOAD((i + 2) * 32);

        const uint32_t* st = smw + b * STAGE_W;
        const uint32_t* Ah = st;
        const uint32_t* Al = st + PLANE_W;
        const uint32_t* Bh = st + 2 * PLANE_W;
        const uint32_t* Bl = st + 3 * PLANE_W;

        #pragma unroll
        for (int ki = 0; ki < 2; ki++) {
            int kw = ki * 8 + gc;
            uint32_t ah[2][4], al[2][4], bh[4][2], bl[4][2];
            #pragma unroll
            for (int mi = 0; mi < 2; mi++) {
                int r = wm * 32 + mi * 16 + gr;
                ah[mi][0] = Ah[r * GSTRIDE + kw];
                ah[mi][1] = Ah[(r + 8) * GSTRIDE + kw];
                ah[mi][2] = Ah[r * GSTRIDE + kw + 4];
                ah[mi][3] = Ah[(r + 8) * GSTRIDE + kw + 4];
                al[mi][0] = Al[r * GSTRIDE + kw];
                al[mi][1] = Al[(r + 8) * GSTRIDE + kw];
                al[mi][2] = Al[r * GSTRIDE + kw + 4];
                al[mi][3] = Al[(r + 8) * GSTRIDE + kw + 4];
            }
            #pragma unroll
            for (int ni = 0; ni < 4; ni++) {
                int n = wn * 32 + ni * 8 + gr;
                bh[ni][0] = Bh[n * GSTRIDE + kw];
                bh[ni][1] = Bh[n * GSTRIDE + kw + 4];
                bl[ni][0] = Bl[n * GSTRIDE + kw];
                bl[ni][1] = Bl[n * GSTRIDE + kw + 4];
            }
            #pragma unroll
            for (int ni = 0; ni < 4; ni++)
                #pragma unroll
                for (int mi = 0; mi < 2; mi++) {
                    mma_bf16(acc[mi][ni], ah[mi], bh[ni]);
                    mma_bf16(acc[mi][ni], ah[mi], bl[ni]);
                    mma_bf16(acc[mi][ni], al[mi], bh[ni]);
                }
        }
    }

    #pragma unroll
    for (int ni = 0; ni < 4; ni++) {
        int cg = n0 + wn * 32 + ni * 8 + 2 * gc;
        float b0 = ga.bias[cg], b1 = ga.bias[cg + 1];
        #pragma unroll
        for (int mi = 0; mi < 2; mi++) {
            int r = m0 + wm * 32 + mi * 16 + gr;
            float v0 = acc[mi][ni][0] + b0;
            float v1 = acc[mi][ni][1] + b1;
            float v2 = acc[mi][ni][2] + b0;
            float v3 = acc[mi][ni][3] + b1;
            if (SILU) {
                v0 = v0 / (1.f + __expf(-v0));
                v1 = v1 / (1.f + __expf(-v1));
                v2 = v2 / (1.f + __expf(-v2));
                v3 = v3 / (1.f + __expf(-v3));
            }
            *(float2*)(ga.C + (size_t)r * CCH + cg)       = make_float2(v0, v1);
            *(float2*)(ga.C + (size_t)(r + 8) * CCH + cg) = make_float2(v2, v3);
        }
    }
    #undef GLOAD
    #undef SSTORE
}

// ---------------- depthwise conv k=3 pad=1 over sequence (per batch) -------------
__global__ void dwconv_k(const float* iq, const float* ik, const float* iv,
                         const float* wqd, const float* wkd, const float* wvd,
                         const float* bqd, const float* bkd, const float* bvd,
                         float* oq, float* ok, float* ov)
{
    int z = blockIdx.y;
    const float* in = (z == 0) ? iq : ((z == 1) ? ik : iv);
    const float* w  = (z == 0) ? wqd : ((z == 1) ? wkd : wvd);
    const float* bb = (z == 0) ? bqd : ((z == 1) ? bkd : bvd);
    float* out      = (z == 0) ? oq : ((z == 1) ? ok : ov);

    int idx = blockIdx.x * blockDim.x + threadIdx.x;
    if (idx >= MROWS * CCH) return;
    int c = idx & (CCH - 1);
    int m = idx >> 10;
    int s = m & (SEQ - 1);

    float w0 = w[c * 3 + 0], w1 = w[c * 3 + 1], w2 = w[c * 3 + 2];
    float val = in[idx] * w1 + bb[c];
    if (s > 0)        val += in[idx - CCH] * w0;
    if (s < SEQ - 1)  val += in[idx + CCH] * w2;
    out[idx] = val;
}

// ---------------- per-head L2 normalize (in place) for q and k -------------------
__global__ void l2norm_k(float* q, float* k)
{
    float* p = (blockIdx.y == 0) ? q : k;
    int warp = threadIdx.x >> 5;
    int lane = threadIdx.x & 31;
    int g = blockIdx.x * 8 + warp;
    float* row = p + (size_t)g * HDD;
    float x0 = row[lane], x1 = row[lane + 32];
    float ss = x0 * x0 + x1 * x1;
    #pragma unroll
    for (int o = 16; o; o >>= 1) ss += __shfl_xor_sync(0xffffffffu, ss, o);
    float inv = 1.f / fmaxf(sqrtf(ss), 1e-12f);
    row[lane]      = x0 * inv;
    row[lane + 32] = x1 * inv;
}

// ================= flash attention via mma.sync (bf16 QK, split P/V) =============
// CTA: (qtile of 128 rows, head, batch). 256 threads = 8 warps, warp = 16 q rows.
// KV tiles of 64, double-buffered smem. K bf16 [kv][hd] pairs-in-hd (stride 36 words).
// V transposed hi/lo [hd][kv] pairs-in-kv (stride 36 words).
#define AT_BUFW 6912                  // u32 per buffer (3 planes x 64*36)
#define AT_SMEM (2*AT_BUFW*4)         // 55296 B

__global__ void __launch_bounds__(256) attn_mma_k(const float* __restrict__ Q,
                                                  const float* __restrict__ K,
                                                  const float* __restrict__ V,
                                                  const int* __restrict__ mask,
                                                  float* __restrict__ O)
{
    const int qt = blockIdx.x, h = blockIdx.y, bb = blockIdx.z;
    extern __shared__ uint32_t asw[];
    __shared__ int s_mask[2][64];

    const int tid = threadIdx.x, lane = tid & 31, w = tid >> 5;
    const int gr = lane >> 2, gc = lane & 3;

    const float* Qg = Q + ((size_t)(bb * SEQ + qt * 128)) * CCH + h * HDD;
    const float* Kg = K + ((size_t)bb * SEQ) * CCH + h * HDD;
    const float* Vg = V + ((size_t)bb * SEQ) * CCH + h * HDD;

    // ---- stage Q in smem (fp32), extract bf16 A-fragments ----
    uint32_t qa[4][4];
    {
        float* qs = (float*)asw;   // [128][64]
        #pragma unroll
        for (int j = 0; j < 8; j++) {
            int idx4 = tid + 256 * j;          // 2048 float4
            int r = idx4 >> 4, c4 = idx4 & 15;
            *(float4*)(qs + r * 64 + c4 * 4) =
                *(const float4*)(Qg + (size_t)r * CCH + c4 * 4);
        }
        __syncthreads();
        int r0 = w * 16 + gr, r1 = r0 + 8;
        #pragma unroll
        for (int ks = 0; ks < 4; ks++) {
            int c = ks * 16 + 2 * gc;
            qa[ks][0] = pack2h(qs[r0 * 64 + c],     qs[r0 * 64 + c + 1]);
            qa[ks][1] = pack2h(qs[r1 * 64 + c],     qs[r1 * 64 + c + 1]);
            qa[ks][2] = pack2h(qs[r0 * 64 + c + 8], qs[r0 * 64 + c + 9]);
            qa[ks][3] = pack2h(qs[r1 * 64 + c + 8], qs[r1 * 64 + c + 9]);
        }
        __syncthreads();  // all reads done before buffers overwrite
    }

    // per-thread tile-load geometry
    const int kvr = tid >> 5, hd2 = tid & 31;        // K: base slot (stride 8 in kvr)
    const int vhd = tid & 63, vkv2 = tid >> 6;       // V: base slot (stride 4 in vkv2)

    float2 kf[8];
    float va[8], vb[8];
    int mreg = 0;

    #define AT_GLOAD(jt) do { \
        const float* kb = Kg + (size_t)((jt) * 64) * CCH; \
        const float* vbp = Vg + (size_t)((jt) * 64) * CCH; \
        _Pragma("unroll") \
        for (int j = 0; j < 8; j++) \
            kf[j] = *(const float2*)(kb + (size_t)(kvr + 8 * j) * CCH + hd2 * 2); \
        _Pragma("unroll") \
        for (int j = 0; j < 8; j++) { \
            va[j] = vbp[(size_t)(2 * (vkv2 + 4 * j)) * CCH + vhd]; \
            vb[j] = vbp[(size_t)(2 * (vkv2 + 4 * j) + 1) * CCH + vhd]; \
        } \
        if (tid < 64) mreg = mask[bb * SEQ + (jt) * 64 + tid]; \
    } while (0)

    #define AT_SSTORE(buf) do { \
        uint32_t* Kw = asw + (buf) * AT_BUFW; \
        uint32_t* Vh = Kw + 2304; \
        uint32_t* Vl = Kw + 4608; \
        _Pragma("unroll") \
        for (int j = 0; j < 8; j++) \
            Kw[(kvr + 8 * j) * 36 + hd2] = pack2h(kf[j].x, kf[j].y); \
        _Pragma("unroll") \
        for (int j = 0; j < 8; j++) { \
            uint32_t hh, ll; \
            split2(va[j], vb[j], hh, ll); \
            Vh[vhd * 36 + vkv2 + 4 * j] = hh; \
            Vl[vhd * 36 + vkv2 + 4 * j] = ll; \
        } \
        if (tid < 64) s_mask[buf][tid] = mreg; \
    } while (0)

    float o[8][4];
    #pragma unroll
    for (int ht = 0; ht < 8; ht++)
        #pragma unroll
        for (int e = 0; e < 4; e++) o[ht][e] = 0.f;
    float m0p = -1e30f, m1p = -1e30f, l0 = 0.f, l1 = 0.f;

    AT_GLOAD(0);
    AT_SSTORE(0);

    #pragma unroll 1
    for (int jt = 0; jt < 32; jt++) {
        const int b = jt & 1;
        __syncthreads();
        if (jt + 1 < 32) AT_GLOAD(jt + 1);

        const uint32_t* Kw = asw + b * AT_BUFW;
        const uint32_t* Vh = Kw + 2304;
        const uint32_t* Vl = Kw + 4608;

        // ---- S = Q K^T ----
        float s[8][4];
        #pragma unroll
        for (int nt = 0; nt < 8; nt++) {
            #pragma unroll
            for (int e = 0; e < 4; e++) s[nt][e] = 0.f;
            #pragma unroll
            for (int ks = 0; ks < 4; ks++) {
                uint32_t b0 = Kw[(nt * 8 + gr) * 36 + ks * 8 + gc];
                uint32_t b1 = Kw[(nt * 8 + gr) * 36 + ks * 8 + gc + 4];
                mma_bf16_b(s[nt], qa[ks], b0, b1);
            }
        }

        // ---- mask + scale ----
        #pragma unroll
        for (int nt = 0; nt < 8; nt++) {
            int c0 = nt * 8 + 2 * gc;
            bool ok0 = s_mask[b][c0] != 0;
            bool ok1 = s_mask[b][c0 + 1] != 0;
            s[nt][0] = ok0 ? s[nt][0] * 0.125f : -1e30f;
            s[nt][1] = ok1 ? s[nt][1] * 0.125f : -1e30f;
            s[nt][2] = ok0 ? s[nt][2] * 0.125f : -1e30f;
            s[nt][3] = ok1 ? s[nt][3] * 0.125f : -1e30f;
        }

        // ---- streaming softmax ----
        float mx0 = -1e30f, mx1 = -1e30f;
        #pragma unroll
        for (int nt = 0; nt < 8; nt++) {
            mx0 = fmaxf(mx0, fmaxf(s[nt][0], s[nt][1]));
            mx1 = fmaxf(mx1, fmaxf(s[nt][2], s[nt][3]));
        }
        mx0 = fmaxf(mx0, __shfl_xor_sync(0xffffffffu, mx0, 1));
        mx0 = fmaxf(mx0, __shfl_xor_sync(0xffffffffu, mx0, 2));
        mx1 = fmaxf(mx1, __shfl_xor_sync(0xffffffffu, mx1, 1));
        mx1 = fmaxf(mx1, __shfl_xor_sync(0xffffffffu, mx1, 2));

        float mn0 = fmaxf(m0p, mx0), mn1 = fmaxf(m1p, mx1);
        float al0 = __expf(m0p - mn0), al1 = __expf(m1p - mn1);
        #pragma unroll
        for (int ht = 0; ht < 8; ht++) {
            o[ht][0] *= al0; o[ht][1] *= al0;
            o[ht][2] *= al1; o[ht][3] *= al1;
        }
        float rs0 = 0.f, rs1 = 0.f;
        #pragma unroll
        for (int nt = 0; nt < 8; nt++) {
            s[nt][0] = __expf(s[nt][0] - mn0); rs0 += s[nt][0];
            s[nt][1] = __expf(s[nt][1] - mn0); rs0 += s[nt][1];
            s[nt][2] = __expf(s[nt][2] - mn1); rs1 += s[nt][2];
            s[nt][3] = __expf(s[nt][3] - mn1); rs1 += s[nt][3];
        }
        rs0 += __shfl_xor_sync(0xffffffffu, rs0, 1);
        rs0 += __shfl_xor_sync(0xffffffffu, rs0, 2);
        rs1 += __shfl_xor_sync(0xffffffffu, rs1, 1);
        rs1 += __shfl_xor_sync(0xffffffffu, rs1, 2);
        l0 = l0 * al0 + rs0; l1 = l1 * al1 + rs1;
        m0p = mn0; m1p = mn1;

        // ---- O += P V  (split-2 on both P and V; 3 products) ----
        #pragma unroll
        for (int ks = 0; ks < 4; ks++) {
            uint32_t aHi[4], aLo[4];
            split2(s[2 * ks][0],     s[2 * ks][1],     aHi[0], aLo[0]);
            split2(s[2 * ks][2],     s[2 * ks][3],     aHi[1], aLo[1]);
            split2(s[2 * ks + 1][0], s[2 * ks + 1][1], aHi[2], aLo[2]);
            split2(s[2 * ks + 1][2], s[2 * ks + 1][3], aHi[3], aLo[3]);
            #pragma unroll
            for (int ht = 0; ht < 8; ht++) {
                int rw = (ht * 8 + gr) * 36 + ks * 8 + gc;
                uint32_t bh0 = Vh[rw], bh1 = Vh[rw + 4];
                uint32_t bl0 = Vl[rw], bl1 = Vl[rw + 4];
                mma_bf16_b(o[ht], aHi, bh0, bh1);
                mma_bf16_b(o[ht], aHi, bl0, bl1);
                mma_bf16_b(o[ht], aLo, bh0, bh1);
            }
        }

        if (jt + 1 < 32) AT_SSTORE(1 - b);
    }

    // ---- epilogue ----
    {
        float inv0 = 1.f / l0, inv1 = 1.f / l1;
        int r0 = w * 16 + gr, r1 = r0 + 8;
        float* Og = O + ((size_t)(bb * SEQ + qt * 128)) * CCH + h * HDD;
        #pragma unroll
        for (int ht = 0; ht < 8; ht++) {
            int c = ht * 8 + 2 * gc;
            *(float2*)(Og + (size_t)r0 * CCH + c) = make_float2(o[ht][0] * inv0, o[ht][1] * inv0);
            *(float2*)(Og + (size_t)r1 * CCH + c) = make_float2(o[ht][2] * inv1, o[ht][3] * inv1);
        }
    }
    #undef AT_GLOAD
    #undef AT_SSTORE
}

// ---------------- host launcher ---------------------------------------------------
extern "C" void kernel_launch(void* const* d_in, const int* in_sizes, int n_in,
                              void* d_out, int out_size)
{
    const float* x    = (const float*)d_in[0];
    const int*   mask = (const int*)d_in[1];
    const float* wq   = (const float*)d_in[2];
    const float* bq   = (const float*)d_in[3];
    const float* wk   = (const float*)d_in[4];
    const float* bk   = (const float*)d_in[5];
    const float* wv   = (const float*)d_in[6];
    const float* bv   = (const float*)d_in[7];
    const float* qdww = (const float*)d_in[8];
    const float* qdwb = (const float*)d_in[9];
    const float* qpww = (const float*)d_in[10];
    const float* qpwb = (const float*)d_in[11];
    const float* kdww = (const float*)d_in[12];
    const float* kdwb = (const float*)d_in[13];
    const float* kpww = (const float*)d_in[14];
    const float* kpwb = (const float*)d_in[15];
    const float* vdww = (const float*)d_in[16];
    const float* vdwb = (const float*)d_in[17];
    const float* vpww = (const float*)d_in[18];
    const float* vpwb = (const float*)d_in[19];
    const float* wo   = (const float*)d_in[20];
    const float* bo   = (const float*)d_in[21];
    float* out = (float*)d_out;

    float *q, *k, *v, *qc, *kc, *vc, *ao;
    cudaGetSymbolAddress((void**)&q,  g_q);
    cudaGetSymbolAddress((void**)&k,  g_k);
    cudaGetSymbolAddress((void**)&v,  g_v);
    cudaGetSymbolAddress((void**)&qc, g_qc);
    cudaGetSymbolAddress((void**)&kc, g_kc);
    cudaGetSymbolAddress((void**)&vc, g_vc);
    cudaGetSymbolAddress((void**)&ao, g_ao);

    cudaFuncSetAttribute(gemm_bf16_k<true>,  cudaFuncAttributeMaxDynamicSharedMemorySize, G_SMEM_BYTES);
    cudaFuncSetAttribute(gemm_bf16_k<false>, cudaFuncAttributeMaxDynamicSharedMemorySize, G_SMEM_BYTES);
    cudaFuncSetAttribute(attn_mma_k, cudaFuncAttributeMaxDynamicSharedMemorySize, AT_SMEM);

    dim3 gemm_grid3(8, 32, 3);
    dim3 gemm_grid1(8, 32, 1);

    // 1) QKV projection + SiLU
    gemm_bf16_k<true><<<gemm_grid3, 512, G_SMEM_BYTES>>>(GArgs{x, wq, bq, q},
                                                         GArgs{x, wk, bk, k},
                                                         GArgs{x, wv, bv, v});

    // 2) depthwise conv k=3 over sequence
    dwconv_k<<<dim3((MROWS * CCH) / 256, 3), 256>>>(q, k, v,
                                                    qdww, kdww, vdww,
                                                    qdwb, kdwb, vdwb,
                                                    qc, kc, vc);

    // 3) pointwise 1x1 conv (GEMM, no activation)
    gemm_bf16_k<false><<<gemm_grid3, 512, G_SMEM_BYTES>>>(GArgs{qc, qpww, qpwb, q},
                                                          GArgs{kc, kpww, kpwb, k},
                                                          GArgs{vc, vpww, vpwb, v});

    // 4) per-head L2 normalize q, k
    l2norm_k<<<dim3((MROWS * NHH) / 8, 2), 256>>>(q, k);

    // 5) flash attention (tensor cores)
    attn_mma_k<<<dim3(SEQ / 128, NHH, BSZ), 256, AT_SMEM>>>(q, k, v, mask, ao);

    // 6) output projection -> d_out
    gemm_bf16_k<false><<<gemm_grid1, 512, G_SMEM_BYTES>>>(GArgs{ao, wo, bo, out},
                                                          GArgs{ao, wo, bo, out},
                                                          GArgs{ao, wo, bo, out});
}

// round 5
// speedup vs baseline: 3.3713x; 1.3944x over previous
#include <cuda_runtime.h>
#include <cuda_fp16.h>
#include <math.h>
#include <stdint.h>

#define BSZ 2
#define SEQ 2048
#define DIMM 1024
#define CCH 1024
#define NHH 16
#define HDD 64
#define MROWS (BSZ*SEQ)   // 4096

// ---------------- scratch (device globals; no runtime allocation) ----------------
__device__ float g_q[MROWS*CCH];
__device__ float g_k[MROWS*CCH];
__device__ float g_v[MROWS*CCH];
__device__ float g_qc[MROWS*CCH];
__device__ float g_kc[MROWS*CCH];
__device__ float g_vc[MROWS*CCH];
__device__ float g_ao[MROWS*CCH];

// ================= mma.sync fp16 helpers =========================================
__device__ __forceinline__ uint32_t pack2f16(float x, float y) {
    __half2 t = __floats2half2_rn(x, y);
    return *reinterpret_cast<uint32_t*>(&t);
}
__device__ __forceinline__ void split2h(float x, float y, uint32_t& h, uint32_t& l) {
    __half hx = __float2half_rn(x);
    __half hy = __float2half_rn(y);
    __half2 hp = __halves2half2(hx, hy);
    h = *reinterpret_cast<uint32_t*>(&hp);
    l = pack2f16(x - __half2float(hx), y - __half2float(hy));
}
__device__ __forceinline__ void mma_f16(float* d, const uint32_t* a, const uint32_t* b) {
    asm volatile(
        "mma.sync.aligned.m16n8k16.row.col.f32.f16.f16.f32 "
        "{%0,%1,%2,%3}, {%4,%5,%6,%7}, {%8,%9}, {%0,%1,%2,%3};"
        : "+f"(d[0]), "+f"(d[1]), "+f"(d[2]), "+f"(d[3])
        : "r"(a[0]), "r"(a[1]), "r"(a[2]), "r"(a[3]), "r"(b[0]), "r"(b[1]));
}
__device__ __forceinline__ void mma_f16_b(float* d, const uint32_t* a, uint32_t b0, uint32_t b1) {
    asm volatile(
        "mma.sync.aligned.m16n8k16.row.col.f32.f16.f16.f32 "
        "{%0,%1,%2,%3}, {%4,%5,%6,%7}, {%8,%9}, {%0,%1,%2,%3};"
        : "+f"(d[0]), "+f"(d[1]), "+f"(d[2]), "+f"(d[3])
        : "r"(a[0]), "r"(a[1]), "r"(a[2]), "r"(a[3]), "r"(b0), "r"(b1));
}

// ================= fp16 2-product GEMM via mma.sync ==============================
// C[m,n] = sum_k A[m,k]*W[n,k] + bias[n]; M=4096, N=1024, K=1024.
// A split hi/lo fp16 (2 products); W single fp16.
// CTA 128x128, KC=32, 512 threads (16 warps, 4x4 grid, warp tile 32x32).
struct GArgs { const float* A; const float* W; const float* bias; float* C; };

#define GSTRIDE 20                 // u32 words per plane row (16 data + 4 pad)
#define PLANE_W (128*GSTRIDE)      // 2560 words
#define STAGE_W (3*PLANE_W)        // Ahi, Alo, B
#define G_SMEM_BYTES (2*STAGE_W*4) // 61440 B

template<bool SILU>
__global__ void __launch_bounds__(512) gemm_f16_k(GArgs ga0, GArgs ga1, GArgs ga2)
{
    GArgs ga = (blockIdx.z == 0) ? ga0 : ((blockIdx.z == 1) ? ga1 : ga2);
    extern __shared__ uint32_t smw[];

    const int tid = threadIdx.x;
    const int lane = tid & 31, wid = tid >> 5;
    const int wm = wid & 3, wn = wid >> 2;       // 4x4 warp grid
    const int gr = lane >> 2, gc = lane & 3;
    const int m0 = blockIdx.y * 128, n0 = blockIdx.x * 128;

    const float* A = ga.A + (size_t)m0 * DIMM;
    const float* B = ga.W + (size_t)n0 * DIMM;

    const int row0 = tid >> 3;    // 0..63 ; second chunk uses row0+64
    const int f4 = tid & 7;       // float4 index within 32-float row

    float4 av0, av1, bv0, bv1;

    #define GLOAD(kk)  do { \
        av0 = *(const float4*)(A + (size_t)row0 * DIMM + (kk) + f4 * 4); \
        av1 = *(const float4*)(A + (size_t)(row0 + 64) * DIMM + (kk) + f4 * 4); \
        bv0 = *(const float4*)(B + (size_t)row0 * DIMM + (kk) + f4 * 4); \
        bv1 = *(const float4*)(B + (size_t)(row0 + 64) * DIMM + (kk) + f4 * 4); \
    } while (0)

    #define SSTORE(buf) do { \
        uint32_t* st = smw + (buf) * STAGE_W; \
        uint32_t h0, h1, l0, l1; \
        int w0 = row0 * GSTRIDE + f4 * 2; \
        int w1 = (row0 + 64) * GSTRIDE + f4 * 2; \
        split2h(av0.x, av0.y, h0, l0); split2h(av0.z, av0.w, h1, l1); \
        st[w0] = h0; st[w0 + 1] = h1; st[PLANE_W + w0] = l0; st[PLANE_W + w0 + 1] = l1; \
        split2h(av1.x, av1.y, h0, l0); split2h(av1.z, av1.w, h1, l1); \
        st[w1] = h0; st[w1 + 1] = h1; st[PLANE_W + w1] = l0; st[PLANE_W + w1 + 1] = l1; \
        st[2 * PLANE_W + w0]     = pack2f16(bv0.x, bv0.y); \
        st[2 * PLANE_W + w0 + 1] = pack2f16(bv0.z, bv0.w); \
        st[2 * PLANE_W + w1]     = pack2f16(bv1.x, bv1.y); \
        st[2 * PLANE_W + w1 + 1] = pack2f16(bv1.z, bv1.w); \
    } while (0)

    float acc[2][4][4];
    #pragma unroll
    for (int mi = 0; mi < 2; mi++)
        #pragma unroll
        for (int ni = 0; ni < 4; ni++)
            #pragma unroll
            for (int e = 0; e < 4; e++) acc[mi][ni][e] = 0.f;

    GLOAD(0);
    SSTORE(0);
    GLOAD(32);

    #pragma unroll 1
    for (int i = 0; i < 32; i++) {
        int b = i & 1;
        __syncthreads();
        if (i + 1 < 32) SSTORE(1 ^ b);
        if (i + 2 < 32) GLOAD((i + 2) * 32);

        const uint32_t* st = smw + b * STAGE_W;
        const uint32_t* Ah = st;
        const uint32_t* Al = st + PLANE_W;
        const uint32_t* Bh = st + 2 * PLANE_W;

        #pragma unroll
        for (int ki = 0; ki < 2; ki++) {
            int kw = ki * 8 + gc;
            uint32_t ah[2][4], al[2][4], bh[4][2];
            #pragma unroll
            for (int mi = 0; mi < 2; mi++) {
                int r = wm * 32 + mi * 16 + gr;
                ah[mi][0] = Ah[r * GSTRIDE + kw];
                ah[mi][1] = Ah[(r + 8) * GSTRIDE + kw];
                ah[mi][2] = Ah[r * GSTRIDE + kw + 4];
                ah[mi][3] = Ah[(r + 8) * GSTRIDE + kw + 4];
                al[mi][0] = Al[r * GSTRIDE + kw];
                al[mi][1] = Al[(r + 8) * GSTRIDE + kw];
                al[mi][2] = Al[r * GSTRIDE + kw + 4];
                al[mi][3] = Al[(r + 8) * GSTRIDE + kw + 4];
            }
            #pragma unroll
            for (int ni = 0; ni < 4; ni++) {
                int n = wn * 32 + ni * 8 + gr;
                bh[ni][0] = Bh[n * GSTRIDE + kw];
                bh[ni][1] = Bh[n * GSTRIDE + kw + 4];
            }
            #pragma unroll
            for (int ni = 0; ni < 4; ni++)
                #pragma unroll
                for (int mi = 0; mi < 2; mi++) {
                    mma_f16(acc[mi][ni], ah[mi], bh[ni]);
                    mma_f16(acc[mi][ni], al[mi], bh[ni]);
                }
        }
    }

    #pragma unroll
    for (int ni = 0; ni < 4; ni++) {
        int cg = n0 + wn * 32 + ni * 8 + 2 * gc;
        float b0 = ga.bias[cg], b1 = ga.bias[cg + 1];
        #pragma unroll
        for (int mi = 0; mi < 2; mi++) {
            int r = m0 + wm * 32 + mi * 16 + gr;
            float v0 = acc[mi][ni][0] + b0;
            float v1 = acc[mi][ni][1] + b1;
            float v2 = acc[mi][ni][2] + b0;
            float v3 = acc[mi][ni][3] + b1;
            if (SILU) {
                v0 = v0 / (1.f + __expf(-v0));
                v1 = v1 / (1.f + __expf(-v1));
                v2 = v2 / (1.f + __expf(-v2));
                v3 = v3 / (1.f + __expf(-v3));
            }
            *(float2*)(ga.C + (size_t)r * CCH + cg)       = make_float2(v0, v1);
            *(float2*)(ga.C + (size_t)(r + 8) * CCH + cg) = make_float2(v2, v3);
        }
    }
    #undef GLOAD
    #undef SSTORE
}

// ---------------- depthwise conv k=3 pad=1 over sequence (per batch) -------------
__global__ void dwconv_k(const float* iq, const float* ik, const float* iv,
                         const float* wqd, const float* wkd, const float* wvd,
                         const float* bqd, const float* bkd, const float* bvd,
                         float* oq, float* ok, float* ov)
{
    int z = blockIdx.y;
    const float* in = (z == 0) ? iq : ((z == 1) ? ik : iv);
    const float* w  = (z == 0) ? wqd : ((z == 1) ? wkd : wvd);
    const float* bb = (z == 0) ? bqd : ((z == 1) ? bkd : bvd);
    float* out      = (z == 0) ? oq : ((z == 1) ? ok : ov);

    int idx = blockIdx.x * blockDim.x + threadIdx.x;
    if (idx >= MROWS * CCH) return;
    int c = idx & (CCH - 1);
    int m = idx >> 10;
    int s = m & (SEQ - 1);

    float w0 = w[c * 3 + 0], w1 = w[c * 3 + 1], w2 = w[c * 3 + 2];
    float val = in[idx] * w1 + bb[c];
    if (s > 0)        val += in[idx - CCH] * w0;
    if (s < SEQ - 1)  val += in[idx + CCH] * w2;
    out[idx] = val;
}

// ---------------- per-head L2 normalize (in place) for q and k -------------------
__global__ void l2norm_k(float* q, float* k)
{
    float* p = (blockIdx.y == 0) ? q : k;
    int warp = threadIdx.x >> 5;
    int lane = threadIdx.x & 31;
    int g = blockIdx.x * 8 + warp;
    float* row = p + (size_t)g * HDD;
    float x0 = row[lane], x1 = row[lane + 32];
    float ss = x0 * x0 + x1 * x1;
    #pragma unroll
    for (int o = 16; o; o >>= 1) ss += __shfl_xor_sync(0xffffffffu, ss, o);
    float inv = 1.f / fmaxf(sqrtf(ss), 1e-12f);
    row[lane]      = x0 * inv;
    row[lane + 32] = x1 * inv;
}

// ================= flash attention via mma.sync (fp16, bounded-score softmax) ====
// CTA: (qtile of 128 rows, head, batch). 256 threads = 8 warps, warp = 16 q rows.
// KV tiles of 64, double-buffered smem. K fp16 [kv][hd] pairs-in-hd (stride 36 words).
// V fp16 transposed [hd][kv] pairs-in-kv (stride 36 words).
// Cosine attention: |score*scale| <= ~0.125 -> no running max needed.
#define AT_BUFW 4608                  // u32 per buffer (2 planes x 64*36)
#define AT_SMEM (2*AT_BUFW*4)         // 36864 B (>= 32KB Q staging)

__global__ void __launch_bounds__(256) attn_mma_k(const float* __restrict__ Q,
                                                  const float* __restrict__ K,
                                                  const float* __restrict__ V,
                                                  const int* __restrict__ mask,
                                                  float* __restrict__ O)
{
    const int qt = blockIdx.x, h = blockIdx.y, bb = blockIdx.z;
    extern __shared__ uint32_t asw[];
    __shared__ int s_mask[2][64];

    const int tid = threadIdx.x, lane = tid & 31, w = tid >> 5;
    const int gr = lane >> 2, gc = lane & 3;

    const float* Qg = Q + ((size_t)(bb * SEQ + qt * 128)) * CCH + h * HDD;
    const float* Kg = K + ((size_t)bb * SEQ) * CCH + h * HDD;
    const float* Vg = V + ((size_t)bb * SEQ) * CCH + h * HDD;

    // ---- stage Q in smem (fp32), extract fp16 A-fragments ----
    uint32_t qa[4][4];
    {
        float* qs = (float*)asw;   // [128][64]
        #pragma unroll
        for (int j = 0; j < 8; j++) {
            int idx4 = tid + 256 * j;          // 2048 float4
            int r = idx4 >> 4, c4 = idx4 & 15;
            *(float4*)(qs + r * 64 + c4 * 4) =
                *(const float4*)(Qg + (size_t)r * CCH + c4 * 4);
        }
        __syncthreads();
        int r0 = w * 16 + gr, r1 = r0 + 8;
        #pragma unroll
        for (int ks = 0; ks < 4; ks++) {
            int c = ks * 16 + 2 * gc;
            qa[ks][0] = pack2f16(qs[r0 * 64 + c],     qs[r0 * 64 + c + 1]);
            qa[ks][1] = pack2f16(qs[r1 * 64 + c],     qs[r1 * 64 + c + 1]);
            qa[ks][2] = pack2f16(qs[r0 * 64 + c + 8], qs[r0 * 64 + c + 9]);
            qa[ks][3] = pack2f16(qs[r1 * 64 + c + 8], qs[r1 * 64 + c + 9]);
        }
        __syncthreads();  // all reads done before buffers overwrite
    }

    // per-thread tile-load geometry
    const int kvr = tid >> 5, hd2 = tid & 31;        // K: base slot (stride 8 in kvr)
    const int vhd = tid & 63, vkv2 = tid >> 6;       // V: base slot (stride 4 in vkv2)

    float2 kf[8];
    float va[8], vb[8];
    int mreg = 0;

    #define AT_GLOAD(jt) do { \
        const float* kb = Kg + (size_t)((jt) * 64) * CCH; \
        const float* vbp = Vg + (size_t)((jt) * 64) * CCH; \
        _Pragma("unroll") \
        for (int j = 0; j < 8; j++) \
            kf[j] = *(const float2*)(kb + (size_t)(kvr + 8 * j) * CCH + hd2 * 2); \
        _Pragma("unroll") \
        for (int j = 0; j < 8; j++) { \
            va[j] = vbp[(size_t)(2 * (vkv2 + 4 * j)) * CCH + vhd]; \
            vb[j] = vbp[(size_t)(2 * (vkv2 + 4 * j) + 1) * CCH + vhd]; \
        } \
        if (tid < 64) mreg = mask[bb * SEQ + (jt) * 64 + tid]; \
    } while (0)

    #define AT_SSTORE(buf) do { \
        uint32_t* Kw = asw + (buf) * AT_BUFW; \
        uint32_t* Vh = Kw + 2304; \
        _Pragma("unroll") \
        for (int j = 0; j < 8; j++) \
            Kw[(kvr + 8 * j) * 36 + hd2] = pack2f16(kf[j].x, kf[j].y); \
        _Pragma("unroll") \
        for (int j = 0; j < 8; j++) \
            Vh[vhd * 36 + vkv2 + 4 * j] = pack2f16(va[j], vb[j]); \
        if (tid < 64) s_mask[buf][tid] = mreg; \
    } while (0)

    float o[8][4];
    #pragma unroll
    for (int ht = 0; ht < 8; ht++)
        #pragma unroll
        for (int e = 0; e < 4; e++) o[ht][e] = 0.f;
    float l0 = 0.f, l1 = 0.f;   // per-thread partial row sums (reduced at end)

    AT_GLOAD(0);
    AT_SSTORE(0);

    #pragma unroll 1
    for (int jt = 0; jt < 32; jt++) {
        const int b = jt & 1;
        __syncthreads();
        if (jt + 1 < 32) AT_GLOAD(jt + 1);

        const uint32_t* Kw = asw + b * AT_BUFW;
        const uint32_t* Vh = Kw + 2304;

        // ---- S = Q K^T ----
        float s[8][4];
        #pragma unroll
        for (int nt = 0; nt < 8; nt++) {
            #pragma unroll
            for (int e = 0; e < 4; e++) s[nt][e] = 0.f;
            #pragma unroll
            for (int ks = 0; ks < 4; ks++) {
                uint32_t b0 = Kw[(nt * 8 + gr) * 36 + ks * 8 + gc];
                uint32_t b1 = Kw[(nt * 8 + gr) * 36 + ks * 8 + gc + 4];
                mma_f16_b(s[nt], qa[ks], b0, b1);
            }
        }

        // ---- p = exp(s*scale) (bounded; no max), masked -> 0 ----
        #pragma unroll
        for (int nt = 0; nt < 8; nt++) {
            int c0 = nt * 8 + 2 * gc;
            bool ok0 = s_mask[b][c0] != 0;
            bool ok1 = s_mask[b][c0 + 1] != 0;
            s[nt][0] = ok0 ? __expf(s[nt][0] * 0.125f) : 0.f;
            s[nt][1] = ok1 ? __expf(s[nt][1] * 0.125f) : 0.f;
            s[nt][2] = ok0 ? __expf(s[nt][2] * 0.125f) : 0.f;
            s[nt][3] = ok1 ? __expf(s[nt][3] * 0.125f) : 0.f;
            l0 += s[nt][0] + s[nt][1];
            l1 += s[nt][2] + s[nt][3];
        }

        // ---- O += P V  (plain fp16) ----
        #pragma unroll
        for (int ks = 0; ks < 4; ks++) {
            uint32_t aF[4];
            aF[0] = pack2f16(s[2 * ks][0],     s[2 * ks][1]);
            aF[1] = pack2f16(s[2 * ks][2],     s[2 * ks][3]);
            aF[2] = pack2f16(s[2 * ks + 1][0], s[2 * ks + 1][1]);
            aF[3] = pack2f16(s[2 * ks + 1][2], s[2 * ks + 1][3]);
            #pragma unroll
            for (int ht = 0; ht < 8; ht++) {
                int rw = (ht * 8 + gr) * 36 + ks * 8 + gc;
                mma_f16_b(o[ht], aF, Vh[rw], Vh[rw + 4]);
            }
        }

        if (jt + 1 < 32) AT_SSTORE(1 - b);
    }

    // ---- reduce l across the 4 gc lanes, epilogue ----
    l0 += __shfl_xor_sync(0xffffffffu, l0, 1);
    l0 += __shfl_xor_sync(0xffffffffu, l0, 2);
    l1 += __shfl_xor_sync(0xffffffffu, l1, 1);
    l1 += __shfl_xor_sync(0xffffffffu, l1, 2);
    {
        float inv0 = 1.f / l0, inv1 = 1.f / l1;
        int r0 = w * 16 + gr, r1 = r0 + 8;
        float* Og = O + ((size_t)(bb * SEQ + qt * 128)) * CCH + h * HDD;
        #pragma unroll
        for (int ht = 0; ht < 8; ht++) {
            int c = ht * 8 + 2 * gc;
            *(float2*)(Og + (size_t)r0 * CCH + c) = make_float2(o[ht][0] * inv0, o[ht][1] * inv0);
            *(float2*)(Og + (size_t)r1 * CCH + c) = make_float2(o[ht][2] * inv1, o[ht][3] * inv1);
        }
    }
    #undef AT_GLOAD
    #undef AT_SSTORE
}

// ---------------- host launcher ---------------------------------------------------
extern "C" void kernel_launch(void* const* d_in, const int* in_sizes, int n_in,
                              void* d_out, int out_size)
{
    const float* x    = (const float*)d_in[0];
    const int*   mask = (const int*)d_in[1];
    const float* wq   = (const float*)d_in[2];
    const float* bq   = (const float*)d_in[3];
    const float* wk   = (const float*)d_in[4];
    const float* bk   = (const float*)d_in[5];
    const float* wv   = (const float*)d_in[6];
    const float* bv   = (const float*)d_in[7];
    const float* qdww = (const float*)d_in[8];
    const float* qdwb = (const float*)d_in[9];
    const float* qpww = (const float*)d_in[10];
    const float* qpwb = (const float*)d_in[11];
    const float* kdww = (const float*)d_in[12];
    const float* kdwb = (const float*)d_in[13];
    const float* kpww = (const float*)d_in[14];
    const float* kpwb = (const float*)d_in[15];
    const float* vdww = (const float*)d_in[16];
    const float* vdwb = (const float*)d_in[17];
    const float* vpww = (const float*)d_in[18];
    const float* vpwb = (const float*)d_in[19];
    const float* wo   = (const float*)d_in[20];
    const float* bo   = (const float*)d_in[21];
    float* out = (float*)d_out;

    float *q, *k, *v, *qc, *kc, *vc, *ao;
    cudaGetSymbolAddress((void**)&q,  g_q);
    cudaGetSymbolAddress((void**)&k,  g_k);
    cudaGetSymbolAddress((void**)&v,  g_v);
    cudaGetSymbolAddress((void**)&qc, g_qc);
    cudaGetSymbolAddress((void**)&kc, g_kc);
    cudaGetSymbolAddress((void**)&vc, g_vc);
    cudaGetSymbolAddress((void**)&ao, g_ao);

    cudaFuncSetAttribute(gemm_f16_k<true>,  cudaFuncAttributeMaxDynamicSharedMemorySize, G_SMEM_BYTES);
    cudaFuncSetAttribute(gemm_f16_k<false>, cudaFuncAttributeMaxDynamicSharedMemorySize, G_SMEM_BYTES);
    cudaFuncSetAttribute(attn_mma_k, cudaFuncAttributeMaxDynamicSharedMemorySize, AT_SMEM);

    dim3 gemm_grid3(8, 32, 3);
    dim3 gemm_grid1(8, 32, 1);

    // 1) QKV projection + SiLU
    gemm_f16_k<true><<<gemm_grid3, 512, G_SMEM_BYTES>>>(GArgs{x, wq, bq, q},
                                                        GArgs{x, wk, bk, k},
                                                        GArgs{x, wv, bv, v});

    // 2) depthwise conv k=3 over sequence
    dwconv_k<<<dim3((MROWS * CCH) / 256, 3), 256>>>(q, k, v,
                                                    qdww, kdww, vdww,
                                                    qdwb, kdwb, vdwb,
                                                    qc, kc, vc);

    // 3) pointwise 1x1 conv (GEMM, no activation)
    gemm_f16_k<false><<<gemm_grid3, 512, G_SMEM_BYTES>>>(GArgs{qc, qpww, qpwb, q},
                                                         GArgs{kc, kpww, kpwb, k},
                                                         GArgs{vc, vpww, vpwb, v});

    // 4) per-head L2 normalize q, k
    l2norm_k<<<dim3((MROWS * NHH) / 8, 2), 256>>>(q, k);

    // 5) flash attention (tensor cores, fp16)
    attn_mma_k<<<dim3(SEQ / 128, NHH, BSZ), 256, AT_SMEM>>>(q, k, v, mask, ao);

    // 6) output projection -> d_out
    gemm_f16_k<false><<<gemm_grid1, 512, G_SMEM_BYTES>>>(GArgs{ao, wo, bo, out},
                                                         GArgs{ao, wo, bo, out},
                                                         GArgs{ao, wo, bo, out});
}

// round 6
// speedup vs baseline: 3.8519x; 1.1426x over previous
#include <cuda_runtime.h>
#include <cuda_fp16.h>
#include <math.h>
#include <stdint.h>

#define BSZ 2
#define SEQ 2048
#define DIMM 1024
#define CCH 1024
#define NHH 16
#define HDD 64
#define MROWS (BSZ*SEQ)   // 4096

// ---------------- scratch (device globals; no runtime allocation) ----------------
__device__ float g_q[MROWS*CCH];
__device__ float g_k[MROWS*CCH];
__device__ float g_v[MROWS*CCH];
__device__ float g_qc[MROWS*CCH];
__device__ float g_kc[MROWS*CCH];
__device__ float g_vc[MROWS*CCH];
__device__ float g_ao[MROWS*CCH];
__device__ __half g_qh[MROWS*CCH];
__device__ __half g_kh[MROWS*CCH];
__device__ __half g_vt[MROWS*CCH];   // [b][ch][s] transposed fp16 V

// ================= helpers =======================================================
__device__ __forceinline__ uint32_t smem_u32(const void* p) {
    uint32_t a;
    asm("{ .reg .u64 t; cvta.to.shared.u64 t, %1; cvt.u32.u64 %0, t; }" : "=r"(a) : "l"(p));
    return a;
}
__device__ __forceinline__ uint32_t pack2f16(float x, float y) {
    __half2 t = __floats2half2_rn(x, y);
    return *reinterpret_cast<uint32_t*>(&t);
}
__device__ __forceinline__ void split2h(float x, float y, uint32_t& h, uint32_t& l) {
    __half hx = __float2half_rn(x);
    __half hy = __float2half_rn(y);
    __half2 hp = __halves2half2(hx, hy);
    h = *reinterpret_cast<uint32_t*>(&hp);
    l = pack2f16(x - __half2float(hx), y - __half2float(hy));
}
__device__ __forceinline__ void mma_f16(float* d, const uint32_t* a, const uint32_t* b) {
    asm volatile(
        "mma.sync.aligned.m16n8k16.row.col.f32.f16.f16.f32 "
        "{%0,%1,%2,%3}, {%4,%5,%6,%7}, {%8,%9}, {%0,%1,%2,%3};"
        : "+f"(d[0]), "+f"(d[1]), "+f"(d[2]), "+f"(d[3])
        : "r"(a[0]), "r"(a[1]), "r"(a[2]), "r"(a[3]), "r"(b[0]), "r"(b[1]));
}
__device__ __forceinline__ void mma_f16_b(float* d, const uint32_t* a, uint32_t b0, uint32_t b1) {
    asm volatile(
        "mma.sync.aligned.m16n8k16.row.col.f32.f16.f16.f32 "
        "{%0,%1,%2,%3}, {%4,%5,%6,%7}, {%8,%9}, {%0,%1,%2,%3};"
        : "+f"(d[0]), "+f"(d[1]), "+f"(d[2]), "+f"(d[3])
        : "r"(a[0]), "r"(a[1]), "r"(a[2]), "r"(a[3]), "r"(b0), "r"(b1));
}

// ================= fp16 GEMM via mma.sync (PROD = # of A planes) =================
// C[m,n] = sum_k A[m,k]*W[n,k] + bias[n]; M=4096, N=1024, K=1024.
// PROD=2: A split hi/lo (2 mma products). PROD=1: plain fp16 A.
// CTA 128x128, KC=32, 512 threads (16 warps, 4x4 grid, warp tile 32x32).
struct GArgs { const float* A; const float* W; const float* bias; float* C; };

#define GSTRIDE 20                 // u32 words per plane row (16 data + 4 pad)
#define PLANE_W (128*GSTRIDE)      // 2560 words

template<bool SILU, int PROD>
__global__ void __launch_bounds__(512) gemm_f16_k(GArgs ga0, GArgs ga1, GArgs ga2)
{
    constexpr int STW = (PROD + 1) * PLANE_W;   // planes: Ahi[,Alo],B
    GArgs ga = (blockIdx.z == 0) ? ga0 : ((blockIdx.z == 1) ? ga1 : ga2);
    extern __shared__ uint32_t smw[];

    const int tid = threadIdx.x;
    const int lane = tid & 31, wid = tid >> 5;
    const int wm = wid & 3, wn = wid >> 2;
    const int gr = lane >> 2, gc = lane & 3;
    const int m0 = blockIdx.y * 128, n0 = blockIdx.x * 128;

    const float* A = ga.A + (size_t)m0 * DIMM;
    const float* B = ga.W + (size_t)n0 * DIMM;

    const int row0 = tid >> 3;
    const int f4 = tid & 7;

    float4 av0, av1, bv0, bv1;

    auto gload = [&](int kk) {
        av0 = *(const float4*)(A + (size_t)row0 * DIMM + kk + f4 * 4);
        av1 = *(const float4*)(A + (size_t)(row0 + 64) * DIMM + kk + f4 * 4);
        bv0 = *(const float4*)(B + (size_t)row0 * DIMM + kk + f4 * 4);
        bv1 = *(const float4*)(B + (size_t)(row0 + 64) * DIMM + kk + f4 * 4);
    };
    auto sstore = [&](int buf) {
        uint32_t* st = smw + buf * STW;
        int w0 = row0 * GSTRIDE + f4 * 2;
        int w1 = (row0 + 64) * GSTRIDE + f4 * 2;
        if (PROD == 2) {
            uint32_t h0, h1, l0, l1;
            split2h(av0.x, av0.y, h0, l0); split2h(av0.z, av0.w, h1, l1);
            st[w0] = h0; st[w0 + 1] = h1; st[PLANE_W + w0] = l0; st[PLANE_W + w0 + 1] = l1;
            split2h(av1.x, av1.y, h0, l0); split2h(av1.z, av1.w, h1, l1);
            st[w1] = h0; st[w1 + 1] = h1; st[PLANE_W + w1] = l0; st[PLANE_W + w1 + 1] = l1;
        } else {
            st[w0]     = pack2f16(av0.x, av0.y);
            st[w0 + 1] = pack2f16(av0.z, av0.w);
            st[w1]     = pack2f16(av1.x, av1.y);
            st[w1 + 1] = pack2f16(av1.z, av1.w);
        }
        uint32_t* bp = st + PROD * PLANE_W;
        bp[w0]     = pack2f16(bv0.x, bv0.y);
        bp[w0 + 1] = pack2f16(bv0.z, bv0.w);
        bp[w1]     = pack2f16(bv1.x, bv1.y);
        bp[w1 + 1] = pack2f16(bv1.z, bv1.w);
    };

    float acc[2][4][4];
    #pragma unroll
    for (int mi = 0; mi < 2; mi++)
        #pragma unroll
        for (int ni = 0; ni < 4; ni++)
            #pragma unroll
            for (int e = 0; e < 4; e++) acc[mi][ni][e] = 0.f;

    gload(0);
    sstore(0);
    gload(32);

    #pragma unroll 1
    for (int i = 0; i < 32; i++) {
        int b = i & 1;
        __syncthreads();
        if (i + 1 < 32) sstore(1 ^ b);
        if (i + 2 < 32) gload((i + 2) * 32);

        const uint32_t* st = smw + b * STW;
        const uint32_t* Ah = st;
        const uint32_t* Al = st + PLANE_W;
        const uint32_t* Bh = st + PROD * PLANE_W;

        #pragma unroll
        for (int ki = 0; ki < 2; ki++) {
            int kw = ki * 8 + gc;
            uint32_t ah[2][4], al[2][4], bh[4][2];
            #pragma unroll
            for (int mi = 0; mi < 2; mi++) {
                int r = wm * 32 + mi * 16 + gr;
                ah[mi][0] = Ah[r * GSTRIDE + kw];
                ah[mi][1] = Ah[(r + 8) * GSTRIDE + kw];
                ah[mi][2] = Ah[r * GSTRIDE + kw + 4];
                ah[mi][3] = Ah[(r + 8) * GSTRIDE + kw + 4];
                if (PROD == 2) {
                    al[mi][0] = Al[r * GSTRIDE + kw];
                    al[mi][1] = Al[(r + 8) * GSTRIDE + kw];
                    al[mi][2] = Al[r * GSTRIDE + kw + 4];
                    al[mi][3] = Al[(r + 8) * GSTRIDE + kw + 4];
                }
            }
            #pragma unroll
            for (int ni = 0; ni < 4; ni++) {
                int n = wn * 32 + ni * 8 + gr;
                bh[ni][0] = Bh[n * GSTRIDE + kw];
                bh[ni][1] = Bh[n * GSTRIDE + kw + 4];
            }
            #pragma unroll
            for (int ni = 0; ni < 4; ni++)
                #pragma unroll
                for (int mi = 0; mi < 2; mi++) {
                    mma_f16(acc[mi][ni], ah[mi], bh[ni]);
                    if (PROD == 2) mma_f16(acc[mi][ni], al[mi], bh[ni]);
                }
        }
    }

    #pragma unroll
    for (int ni = 0; ni < 4; ni++) {
        int cg = n0 + wn * 32 + ni * 8 + 2 * gc;
        float b0 = ga.bias[cg], b1 = ga.bias[cg + 1];
        #pragma unroll
        for (int mi = 0; mi < 2; mi++) {
            int r = m0 + wm * 32 + mi * 16 + gr;
            float v0 = acc[mi][ni][0] + b0;
            float v1 = acc[mi][ni][1] + b1;
            float v2 = acc[mi][ni][2] + b0;
            float v3 = acc[mi][ni][3] + b1;
            if (SILU) {
                v0 = v0 / (1.f + __expf(-v0));
                v1 = v1 / (1.f + __expf(-v1));
                v2 = v2 / (1.f + __expf(-v2));
                v3 = v3 / (1.f + __expf(-v3));
            }
            *(float2*)(ga.C + (size_t)r * CCH + cg)       = make_float2(v0, v1);
            *(float2*)(ga.C + (size_t)(r + 8) * CCH + cg) = make_float2(v2, v3);
        }
    }
}

// ---------------- depthwise conv k=3 pad=1 over sequence (per batch) -------------
__global__ void dwconv_k(const float* iq, const float* ik, const float* iv,
                         const float* wqd, const float* wkd, const float* wvd,
                         const float* bqd, const float* bkd, const float* bvd,
                         float* oq, float* ok, float* ov)
{
    int z = blockIdx.y;
    const float* in = (z == 0) ? iq : ((z == 1) ? ik : iv);
    const float* w  = (z == 0) ? wqd : ((z == 1) ? wkd : wvd);
    const float* bb = (z == 0) ? bqd : ((z == 1) ? bkd : bvd);
    float* out      = (z == 0) ? oq : ((z == 1) ? ok : ov);

    int idx = blockIdx.x * blockDim.x + threadIdx.x;
    if (idx >= MROWS * CCH) return;
    int c = idx & (CCH - 1);
    int m = idx >> 10;
    int s = m & (SEQ - 1);

    float w0 = w[c * 3 + 0], w1 = w[c * 3 + 1], w2 = w[c * 3 + 2];
    float val = in[idx] * w1 + bb[c];
    if (s > 0)        val += in[idx - CCH] * w0;
    if (s < SEQ - 1)  val += in[idx + CCH] * w2;
    out[idx] = val;
}

// ---------------- per-head L2 normalize -> fp16 (q, k) ---------------------------
__global__ void l2norm_f16_k(const float* q, const float* k, __half* qh, __half* kh)
{
    const float* src = (blockIdx.y == 0) ? q : k;
    __half* dst = (blockIdx.y == 0) ? qh : kh;
    int warp = threadIdx.x >> 5;
    int lane = threadIdx.x & 31;
    size_t g = (size_t)blockIdx.x * 8 + warp;
    const float* row = src + g * HDD;
    float2 x = *(const float2*)(row + lane * 2);
    float ss = x.x * x.x + x.y * x.y;
    #pragma unroll
    for (int o = 16; o; o >>= 1) ss += __shfl_xor_sync(0xffffffffu, ss, o);
    float inv = 1.f / fmaxf(sqrtf(ss), 1e-12f);
    __half2* d = (__half2*)(dst + g * HDD);
    d[lane] = __floats2half2_rn(x.x * inv, x.y * inv);
}

// ---------------- V transpose -> fp16 [b][ch][s] ---------------------------------
__global__ void vtrans_k(const float* v, __half* vt)
{
    __shared__ float t[32][33];
    int b = blockIdx.z;
    int s0 = blockIdx.y * 32, c0 = blockIdx.x * 32;
    int tx = threadIdx.x, ty = threadIdx.y;   // 32x8
    #pragma unroll
    for (int j = 0; j < 4; j++)
        t[ty + 8 * j][tx] = v[(size_t)(b * SEQ + s0 + ty + 8 * j) * CCH + c0 + tx];
    __syncthreads();
    #pragma unroll
    for (int j = 0; j < 4; j++)
        vt[(size_t)(b * CCH + c0 + ty + 8 * j) * SEQ + s0 + tx] = __float2half(t[tx][ty + 8 * j]);
}

// ================= flash attention: cp.async fp16 pipeline =======================
// CTA: (qtile of 128 rows, head, batch). 256 threads = 8 warps, warp = 16 q rows.
// 3-stage cp.async pipeline; KV tiles 64. Stage = K[64 kv][36w] + V[64 hd][36w] fp16.
// Cosine attention: |score*scale| <= ~0.125 -> no running max needed.
#define AT_STW 4608                  // words per stage
#define AT_NST 3
#define AT_SMEM (AT_NST*AT_STW*4)    // 55296 B

__global__ void __launch_bounds__(256) attn_mma_k(const __half* __restrict__ Qh,
                                                  const __half* __restrict__ Kh,
                                                  const __half* __restrict__ Vt,
                                                  const int* __restrict__ mask,
                                                  float* __restrict__ O)
{
    const int qt = blockIdx.x, h = blockIdx.y, bb = blockIdx.z;
    extern __shared__ uint32_t asw[];
    __shared__ int s_mask[AT_NST][64];

    const int tid = threadIdx.x, lane = tid & 31, w = tid >> 5;
    const int gr = lane >> 2, gc = lane & 3;
    const uint32_t sbase = smem_u32(asw);

    const __half* kb = Kh + ((size_t)bb * SEQ) * CCH + h * HDD;
    const __half* vb = Vt + ((size_t)(bb * NHH + h)) * HDD * SEQ;   // rows = hd, len SEQ

    auto issue = [&](int jt) {
        int slot = jt % AT_NST;
        uint32_t kdst = sbase + slot * AT_STW * 4;
        uint32_t vdst = kdst + 2304 * 4;
        #pragma unroll
        for (int j = 0; j < 2; j++) {
            int c = tid + 256 * j;              // 0..511
            int row = c >> 3, ch = c & 7;
            uint32_t d = kdst + (row * 36 + ch * 4) * 4;
            const __half* s = kb + (size_t)(jt * 64 + row) * CCH + ch * 8;
            asm volatile("cp.async.cg.shared.global [%0], [%1], 16;" :: "r"(d), "l"(s));
        }
        #pragma unroll
        for (int j = 0; j < 2; j++) {
            int c = tid + 256 * j;
            int row = c >> 3, ch = c & 7;
            uint32_t d = vdst + (row * 36 + ch * 4) * 4;
            const __half* s = vb + (size_t)row * SEQ + jt * 64 + ch * 8;
            asm volatile("cp.async.cg.shared.global [%0], [%1], 16;" :: "r"(d), "l"(s));
        }
        if (tid < 16) {
            uint32_t d = smem_u32(&s_mask[slot][0]) + tid * 16;
            const int* s = mask + bb * SEQ + jt * 64 + tid * 4;
            asm volatile("cp.async.cg.shared.global [%0], [%1], 16;" :: "r"(d), "l"(s));
        }
        asm volatile("cp.async.commit_group;");
    };

    issue(0);
    issue(1);

    // ---- Q fragments direct from fp16 gmem ----
    uint32_t qa[4][4];
    {
        const __half* qb = Qh + ((size_t)(bb * SEQ + qt * 128)) * CCH + h * HDD;
        int r0 = w * 16 + gr, r1 = r0 + 8;
        #pragma unroll
        for (int ks = 0; ks < 4; ks++) {
            int c = ks * 16 + 2 * gc;
            qa[ks][0] = *(const uint32_t*)(qb + (size_t)r0 * CCH + c);
            qa[ks][1] = *(const uint32_t*)(qb + (size_t)r1 * CCH + c);
            qa[ks][2] = *(const uint32_t*)(qb + (size_t)r0 * CCH + c + 8);
            qa[ks][3] = *(const uint32_t*)(qb + (size_t)r1 * CCH + c + 8);
        }
    }

    float o[8][4];
    #pragma unroll
    for (int ht = 0; ht < 8; ht++)
        #pragma unroll
        for (int e = 0; e < 4; e++) o[ht][e] = 0.f;
    float l0 = 0.f, l1 = 0.f;

    #pragma unroll 1
    for (int jt = 0; jt < 32; jt++) {
        const int slot = jt % AT_NST;
        if (jt < 31) asm volatile("cp.async.wait_group 1;");
        else         asm volatile("cp.async.wait_group 0;");
        __syncthreads();
        if (jt + 2 < 32) issue(jt + 2);

        const uint32_t* Kw = asw + slot * AT_STW;
        const uint32_t* Vh = Kw + 2304;

        // ---- S = Q K^T ----
        float s[8][4];
        #pragma unroll
        for (int nt = 0; nt < 8; nt++) {
            #pragma unroll
            for (int e = 0; e < 4; e++) s[nt][e] = 0.f;
            #pragma unroll
            for (int ks = 0; ks < 4; ks++) {
                uint32_t b0 = Kw[(nt * 8 + gr) * 36 + ks * 8 + gc];
                uint32_t b1 = Kw[(nt * 8 + gr) * 36 + ks * 8 + gc + 4];
                mma_f16_b(s[nt], qa[ks], b0, b1);
            }
        }

        // ---- p = exp(s*scale) (bounded; no max), masked -> 0 ----
        #pragma unroll
        for (int nt = 0; nt < 8; nt++) {
            int c0 = nt * 8 + 2 * gc;
            bool ok0 = s_mask[slot][c0] != 0;
            bool ok1 = s_mask[slot][c0 + 1] != 0;
            s[nt][0] = ok0 ? __expf(s[nt][0] * 0.125f) : 0.f;
            s[nt][1] = ok1 ? __expf(s[nt][1] * 0.125f) : 0.f;
            s[nt][2] = ok0 ? __expf(s[nt][2] * 0.125f) : 0.f;
            s[nt][3] = ok1 ? __expf(s[nt][3] * 0.125f) : 0.f;
            l0 += s[nt][0] + s[nt][1];
            l1 += s[nt][2] + s[nt][3];
        }

        // ---- O += P V ----
        #pragma unroll
        for (int ks = 0; ks < 4; ks++) {
            uint32_t aF[4];
            aF[0] = pack2f16(s[2 * ks][0],     s[2 * ks][1]);
            aF[1] = pack2f16(s[2 * ks][2],     s[2 * ks][3]);
            aF[2] = pack2f16(s[2 * ks + 1][0], s[2 * ks + 1][1]);
            aF[3] = pack2f16(s[2 * ks + 1][2], s[2 * ks + 1][3]);
            #pragma unroll
            for (int ht = 0; ht < 8; ht++) {
                int rw = (ht * 8 + gr) * 36 + ks * 8 + gc;
                mma_f16_b(o[ht], aF, Vh[rw], Vh[rw + 4]);
            }
        }
    }

    // ---- reduce l across the 4 gc lanes, epilogue ----
    l0 += __shfl_xor_sync(0xffffffffu, l0, 1);
    l0 += __shfl_xor_sync(0xffffffffu, l0, 2);
    l1 += __shfl_xor_sync(0xffffffffu, l1, 1);
    l1 += __shfl_xor_sync(0xffffffffu, l1, 2);
    {
        float inv0 = 1.f / l0, inv1 = 1.f / l1;
        int r0 = w * 16 + gr, r1 = r0 + 8;
        float* Og = O + ((size_t)(bb * SEQ + qt * 128)) * CCH + h * HDD;
        #pragma unroll
        for (int ht = 0; ht < 8; ht++) {
            int c = ht * 8 + 2 * gc;
            *(float2*)(Og + (size_t)r0 * CCH + c) = make_float2(o[ht][0] * inv0, o[ht][1] * inv0);
            *(float2*)(Og + (size_t)r1 * CCH + c) = make_float2(o[ht][2] * inv1, o[ht][3] * inv1);
        }
    }
}

// ---------------- host launcher ---------------------------------------------------
extern "C" void kernel_launch(void* const* d_in, const int* in_sizes, int n_in,
                              void* d_out, int out_size)
{
    const float* x    = (const float*)d_in[0];
    const int*   mask = (const int*)d_in[1];
    const float* wq   = (const float*)d_in[2];
    const float* bq   = (const float*)d_in[3];
    const float* wk   = (const float*)d_in[4];
    const float* bk   = (const float*)d_in[5];
    const float* wv   = (const float*)d_in[6];
    const float* bv   = (const float*)d_in[7];
    const float* qdww = (const float*)d_in[8];
    const float* qdwb = (const float*)d_in[9];
    const float* qpww = (const float*)d_in[10];
    const float* qpwb = (const float*)d_in[11];
    const float* kdww = (const float*)d_in[12];
    const float* kdwb = (const float*)d_in[13];
    const float* kpww = (const float*)d_in[14];
    const float* kpwb = (const float*)d_in[15];
    const float* vdww = (const float*)d_in[16];
    const float* vdwb = (const float*)d_in[17];
    const float* vpww = (const float*)d_in[18];
    const float* vpwb = (const float*)d_in[19];
    const float* wo   = (const float*)d_in[20];
    const float* bo   = (const float*)d_in[21];
    float* out = (float*)d_out;

    float *q, *k, *v, *qc, *kc, *vc, *ao;
    __half *qh, *kh, *vt;
    cudaGetSymbolAddress((void**)&q,  g_q);
    cudaGetSymbolAddress((void**)&k,  g_k);
    cudaGetSymbolAddress((void**)&v,  g_v);
    cudaGetSymbolAddress((void**)&qc, g_qc);
    cudaGetSymbolAddress((void**)&kc, g_kc);
    cudaGetSymbolAddress((void**)&vc, g_vc);
    cudaGetSymbolAddress((void**)&ao, g_ao);
    cudaGetSymbolAddress((void**)&qh, g_qh);
    cudaGetSymbolAddress((void**)&kh, g_kh);
    cudaGetSymbolAddress((void**)&vt, g_vt);

    const int SM1 = 2 * 2 * PLANE_W * 4;   // PROD=1: 40960 B
    const int SM2 = 2 * 3 * PLANE_W * 4;   // PROD=2: 61440 B
    cudaFuncSetAttribute(gemm_f16_k<true, 1>,  cudaFuncAttributeMaxDynamicSharedMemorySize, SM1);
    cudaFuncSetAttribute(gemm_f16_k<true, 2>,  cudaFuncAttributeMaxDynamicSharedMemorySize, SM2);
    cudaFuncSetAttribute(gemm_f16_k<false, 1>, cudaFuncAttributeMaxDynamicSharedMemorySize, SM1);
    cudaFuncSetAttribute(gemm_f16_k<false, 2>, cudaFuncAttributeMaxDynamicSharedMemorySize, SM2);
    cudaFuncSetAttribute(attn_mma_k, cudaFuncAttributeMaxDynamicSharedMemorySize, AT_SMEM);

    dim3 grid_qk(8, 32, 2), grid_v(8, 32, 1);

    // 1) QKV projection + SiLU  (q,k single-product; v split-2)
    gemm_f16_k<true, 1><<<grid_qk, 512, SM1>>>(GArgs{x, wq, bq, q},
                                               GArgs{x, wk, bk, k},
                                               GArgs{x, wk, bk, k});
    gemm_f16_k<true, 2><<<grid_v, 512, SM2>>>(GArgs{x, wv, bv, v},
                                              GArgs{x, wv, bv, v},
                                              GArgs{x, wv, bv, v});

    // 2) depthwise conv k=3 over sequence
    dwconv_k<<<dim3((MROWS * CCH) / 256, 3), 256>>>(q, k, v,
                                                    qdww, kdww, vdww,
                                                    qdwb, kdwb, vdwb,
                                                    qc, kc, vc);

    // 3) pointwise 1x1 conv (q,k single-product; v split-2)
    gemm_f16_k<false, 1><<<grid_qk, 512, SM1>>>(GArgs{qc, qpww, qpwb, q},
                                                GArgs{kc, kpww, kpwb, k},
                                                GArgs{kc, kpww, kpwb, k});
    gemm_f16_k<false, 2><<<grid_v, 512, SM2>>>(GArgs{vc, vpww, vpwb, v},
                                               GArgs{vc, vpww, vpwb, v},
                                               GArgs{vc, vpww, vpwb, v});

    // 4) prep: l2norm q,k -> fp16; transpose v -> fp16
    l2norm_f16_k<<<dim3((MROWS * NHH) / 8, 2), 256>>>(q, k, qh, kh);
    vtrans_k<<<dim3(32, 64, 2), dim3(32, 8)>>>(v, vt);

    // 5) flash attention (cp.async fp16 pipeline)
    attn_mma_k<<<dim3(SEQ / 128, NHH, BSZ), 256, AT_SMEM>>>(qh, kh, vt, mask, ao);

    // 6) output projection -> d_out (split-2)
    gemm_f16_k<false, 2><<<grid_v, 512, SM2>>>(GArgs{ao, wo, bo, out},
                                               GArgs{ao, wo, bo, out},
                                               GArgs{ao, wo, bo, out});
}

// round 7
// speedup vs baseline: 3.9984x; 1.0380x over previous
#include <cuda_runtime.h>
#include <cuda_fp16.h>
#include <math.h>
#include <stdint.h>

#define BSZ 2
#define SEQ 2048
#define DIMM 1024
#define CCH 1024
#define NHH 16
#define HDD 64
#define MROWS (BSZ*SEQ)   // 4096

// ---------------- scratch (device globals; no runtime allocation) ----------------
__device__ float g_q[MROWS*CCH];
__device__ float g_k[MROWS*CCH];
__device__ float g_v[MROWS*CCH];
__device__ float g_qc[MROWS*CCH];
__device__ float g_kc[MROWS*CCH];
__device__ float g_vc[MROWS*CCH];
__device__ float g_ao[MROWS*CCH];
__device__ __half g_qh[MROWS*CCH];
__device__ __half g_kh[MROWS*CCH];
__device__ __half g_vt[MROWS*CCH];   // [b][ch][s] transposed fp16 V

// ================= helpers =======================================================
__device__ __forceinline__ uint32_t smem_u32(const void* p) {
    uint32_t a;
    asm("{ .reg .u64 t; cvta.to.shared.u64 t, %1; cvt.u32.u64 %0, t; }" : "=r"(a) : "l"(p));
    return a;
}
__device__ __forceinline__ uint32_t pack2f16(float x, float y) {
    __half2 t = __floats2half2_rn(x, y);
    return *reinterpret_cast<uint32_t*>(&t);
}
__device__ __forceinline__ void split2h(float x, float y, uint32_t& h, uint32_t& l) {
    __half hx = __float2half_rn(x);
    __half hy = __float2half_rn(y);
    __half2 hp = __halves2half2(hx, hy);
    h = *reinterpret_cast<uint32_t*>(&hp);
    l = pack2f16(x - __half2float(hx), y - __half2float(hy));
}
__device__ __forceinline__ void mma_f16(float* d, const uint32_t* a, const uint32_t* b) {
    asm volatile(
        "mma.sync.aligned.m16n8k16.row.col.f32.f16.f16.f32 "
        "{%0,%1,%2,%3}, {%4,%5,%6,%7}, {%8,%9}, {%0,%1,%2,%3};"
        : "+f"(d[0]), "+f"(d[1]), "+f"(d[2]), "+f"(d[3])
        : "r"(a[0]), "r"(a[1]), "r"(a[2]), "r"(a[3]), "r"(b[0]), "r"(b[1]));
}
__device__ __forceinline__ void mma_f16_b(float* d, const uint32_t* a, uint32_t b0, uint32_t b1) {
    asm volatile(
        "mma.sync.aligned.m16n8k16.row.col.f32.f16.f16.f32 "
        "{%0,%1,%2,%3}, {%4,%5,%6,%7}, {%8,%9}, {%0,%1,%2,%3};"
        : "+f"(d[0]), "+f"(d[1]), "+f"(d[2]), "+f"(d[3])
        : "r"(a[0]), "r"(a[1]), "r"(a[2]), "r"(a[3]), "r"(b0), "r"(b1));
}
__device__ __forceinline__ void ldm_x4(uint32_t& r0, uint32_t& r1, uint32_t& r2, uint32_t& r3,
                                       uint32_t addr) {
    asm volatile("ldmatrix.sync.aligned.m8n8.x4.shared.b16 {%0,%1,%2,%3}, [%4];"
                 : "=r"(r0), "=r"(r1), "=r"(r2), "=r"(r3) : "r"(addr));
}
// exp(x) for |x| <= 0.125 via 4th-order Taylor (rel err ~3e-8); runs on FMA pipe.
__device__ __forceinline__ float exp_small(float x) {
    return 1.f + x * (1.f + x * (0.5f + x * (0.166666667f + x * 0.0416666667f)));
}

// ================= fp16 GEMM via mma.sync + ldmatrix (PROD = # of A planes) ======
// C[m,n] = sum_k A[m,k]*W[n,k] + bias[n]; M=4096, N=1024, K=1024.
// PROD=2: A split hi/lo (2 mma products). PROD=1: plain fp16 A.
// CTA 128x128, KC=32, 512 threads (16 warps, 4x4 grid, warp tile 32x32).
struct GArgs { const float* A; const float* W; const float* bias; float* C; };

#define GSTRIDE 20                 // u32 words per plane row (16 data + 4 pad)
#define PLANE_W (128*GSTRIDE)      // 2560 words
#define PLANE_B (PLANE_W*4)        // 10240 bytes

template<bool SILU, int PROD>
__global__ void __launch_bounds__(512) gemm_f16_k(GArgs ga0, GArgs ga1, GArgs ga2)
{
    constexpr int STW = (PROD + 1) * PLANE_W;   // words per stage
    constexpr int STB = STW * 4;
    GArgs ga = (blockIdx.z == 0) ? ga0 : ((blockIdx.z == 1) ? ga1 : ga2);
    extern __shared__ uint32_t smw[];

    const int tid = threadIdx.x;
    const int lane = tid & 31, wid = tid >> 5;
    const int wm = wid & 3, wn = wid >> 2;
    const int gr = lane >> 2, gc = lane & 3;
    const int m0 = blockIdx.y * 128, n0 = blockIdx.x * 128;
    const uint32_t sb = smem_u32(smw);

    const float* A = ga.A + (size_t)m0 * DIMM;
    const float* B = ga.W + (size_t)n0 * DIMM;

    const int row0 = tid >> 3;
    const int f4 = tid & 7;

    // ldmatrix lane-address bases (bytes, relative to stage start)
    const uint32_t aoff = (uint32_t)(wm * 32 + (lane & 15)) * 80 + ((lane >> 4) << 4);
    const uint32_t boff = PROD * PLANE_B +
        (uint32_t)(wn * 32 + ((lane >> 4) << 3) + (lane & 7)) * 80 + (((lane >> 3) & 1) << 4);

    float4 av0, av1, bv0, bv1;

    auto gload = [&](int kk) {
        av0 = *(const float4*)(A + (size_t)row0 * DIMM + kk + f4 * 4);
        av1 = *(const float4*)(A + (size_t)(row0 + 64) * DIMM + kk + f4 * 4);
        bv0 = *(const float4*)(B + (size_t)row0 * DIMM + kk + f4 * 4);
        bv1 = *(const float4*)(B + (size_t)(row0 + 64) * DIMM + kk + f4 * 4);
    };
    auto sstore = [&](int buf) {
        uint32_t* st = smw + buf * STW;
        int w0 = row0 * GSTRIDE + f4 * 2;
        int w1 = (row0 + 64) * GSTRIDE + f4 * 2;
        if (PROD == 2) {
            uint32_t h0, h1, l0, l1;
            split2h(av0.x, av0.y, h0, l0); split2h(av0.z, av0.w, h1, l1);
            st[w0] = h0; st[w0 + 1] = h1; st[PLANE_W + w0] = l0; st[PLANE_W + w0 + 1] = l1;
            split2h(av1.x, av1.y, h0, l0); split2h(av1.z, av1.w, h1, l1);
            st[w1] = h0; st[w1 + 1] = h1; st[PLANE_W + w1] = l0; st[PLANE_W + w1 + 1] = l1;
        } else {
            st[w0]     = pack2f16(av0.x, av0.y);
            st[w0 + 1] = pack2f16(av0.z, av0.w);
            st[w1]     = pack2f16(av1.x, av1.y);
            st[w1 + 1] = pack2f16(av1.z, av1.w);
        }
        uint32_t* bp = st + PROD * PLANE_W;
        bp[w0]     = pack2f16(bv0.x, bv0.y);
        bp[w0 + 1] = pack2f16(bv0.z, bv0.w);
        bp[w1]     = pack2f16(bv1.x, bv1.y);
        bp[w1 + 1] = pack2f16(bv1.z, bv1.w);
    };

    float acc[2][4][4];
    #pragma unroll
    for (int mi = 0; mi < 2; mi++)
        #pragma unroll
        for (int ni = 0; ni < 4; ni++)
            #pragma unroll
            for (int e = 0; e < 4; e++) acc[mi][ni][e] = 0.f;

    gload(0);
    sstore(0);
    gload(32);

    #pragma unroll 1
    for (int i = 0; i < 32; i++) {
        int b = i & 1;
        __syncthreads();
        if (i + 1 < 32) sstore(1 ^ b);
        if (i + 2 < 32) gload((i + 2) * 32);

        uint32_t stbase = sb + b * STB;

        #pragma unroll
        for (int ki = 0; ki < 2; ki++) {
            uint32_t koff = ki * 32;
            uint32_t ah[2][4], al[2][4], bf[4][2];
            ldm_x4(ah[0][0], ah[0][1], ah[0][2], ah[0][3], stbase + aoff + koff);
            ldm_x4(ah[1][0], ah[1][1], ah[1][2], ah[1][3], stbase + aoff + 16 * 80 + koff);
            if (PROD == 2) {
                ldm_x4(al[0][0], al[0][1], al[0][2], al[0][3], stbase + aoff + PLANE_B + koff);
                ldm_x4(al[1][0], al[1][1], al[1][2], al[1][3], stbase + aoff + PLANE_B + 16 * 80 + koff);
            }
            ldm_x4(bf[0][0], bf[0][1], bf[1][0], bf[1][1], stbase + boff + koff);
            ldm_x4(bf[2][0], bf[2][1], bf[3][0], bf[3][1], stbase + boff + 16 * 80 + koff);

            #pragma unroll
            for (int ni = 0; ni < 4; ni++)
                #pragma unroll
                for (int mi = 0; mi < 2; mi++) {
                    mma_f16(acc[mi][ni], ah[mi], bf[ni]);
                    if (PROD == 2) mma_f16(acc[mi][ni], al[mi], bf[ni]);
                }
        }
    }

    #pragma unroll
    for (int ni = 0; ni < 4; ni++) {
        int cg = n0 + wn * 32 + ni * 8 + 2 * gc;
        float b0 = ga.bias[cg], b1 = ga.bias[cg + 1];
        #pragma unroll
        for (int mi = 0; mi < 2; mi++) {
            int r = m0 + wm * 32 + mi * 16 + gr;
            float v0 = acc[mi][ni][0] + b0;
            float v1 = acc[mi][ni][1] + b1;
            float v2 = acc[mi][ni][2] + b0;
            float v3 = acc[mi][ni][3] + b1;
            if (SILU) {
                v0 = v0 / (1.f + __expf(-v0));
                v1 = v1 / (1.f + __expf(-v1));
                v2 = v2 / (1.f + __expf(-v2));
                v3 = v3 / (1.f + __expf(-v3));
            }
            *(float2*)(ga.C + (size_t)r * CCH + cg)       = make_float2(v0, v1);
            *(float2*)(ga.C + (size_t)(r + 8) * CCH + cg) = make_float2(v2, v3);
        }
    }
}

// ---------------- depthwise conv k=3 pad=1 over sequence (per batch) -------------
__global__ void dwconv_k(const float* iq, const float* ik, const float* iv,
                         const float* wqd, const float* wkd, const float* wvd,
                         const float* bqd, const float* bkd, const float* bvd,
                         float* oq, float* ok, float* ov)
{
    int z = blockIdx.y;
    const float* in = (z == 0) ? iq : ((z == 1) ? ik : iv);
    const float* w  = (z == 0) ? wqd : ((z == 1) ? wkd : wvd);
    const float* bb = (z == 0) ? bqd : ((z == 1) ? bkd : bvd);
    float* out      = (z == 0) ? oq : ((z == 1) ? ok : ov);

    int idx = blockIdx.x * blockDim.x + threadIdx.x;
    if (idx >= MROWS * CCH) return;
    int c = idx & (CCH - 1);
    int m = idx >> 10;
    int s = m & (SEQ - 1);

    float w0 = w[c * 3 + 0], w1 = w[c * 3 + 1], w2 = w[c * 3 + 2];
    float val = in[idx] * w1 + bb[c];
    if (s > 0)        val += in[idx - CCH] * w0;
    if (s < SEQ - 1)  val += in[idx + CCH] * w2;
    out[idx] = val;
}

// ---------------- per-head L2 normalize -> fp16 (q gets 0.125 scale folded) ------
__global__ void l2norm_f16_k(const float* q, const float* k, __half* qh, __half* kh)
{
    const float* src = (blockIdx.y == 0) ? q : k;
    __half* dst = (blockIdx.y == 0) ? qh : kh;
    float sc = (blockIdx.y == 0) ? 0.125f : 1.0f;
    int warp = threadIdx.x >> 5;
    int lane = threadIdx.x & 31;
    size_t g = (size_t)blockIdx.x * 8 + warp;
    const float* row = src + g * HDD;
    float2 x = *(const float2*)(row + lane * 2);
    float ss = x.x * x.x + x.y * x.y;
    #pragma unroll
    for (int o = 16; o; o >>= 1) ss += __shfl_xor_sync(0xffffffffu, ss, o);
    float inv = sc / fmaxf(sqrtf(ss), 1e-12f);
    __half2* d = (__half2*)(dst + g * HDD);
    d[lane] = __floats2half2_rn(x.x * inv, x.y * inv);
}

// ---------------- V transpose -> fp16 [b][ch][s] ---------------------------------
__global__ void vtrans_k(const float* v, __half* vt)
{
    __shared__ float t[32][33];
    int b = blockIdx.z;
    int s0 = blockIdx.y * 32, c0 = blockIdx.x * 32;
    int tx = threadIdx.x, ty = threadIdx.y;   // 32x8
    #pragma unroll
    for (int j = 0; j < 4; j++)
        t[ty + 8 * j][tx] = v[(size_t)(b * SEQ + s0 + ty + 8 * j) * CCH + c0 + tx];
    __syncthreads();
    #pragma unroll
    for (int j = 0; j < 4; j++)
        vt[(size_t)(b * CCH + c0 + ty + 8 * j) * SEQ + s0 + tx] = __float2half(t[tx][ty + 8 * j]);
}

// ================= flash attention: cp.async + ldmatrix fp16 pipeline ============
// CTA: (qtile of 128 rows, head, batch). 256 threads = 8 warps, warp = 16 q rows.
// 3-stage cp.async pipeline; KV tiles 64. Stage = K[64 kv][36w] + V[64 hd][36w] fp16.
// Cosine attention: scale folded into q; |score| <= 0.125 -> poly exp, no max.
#define AT_STW 4608                  // words per stage
#define AT_NST 3
#define AT_SMEM (AT_NST*AT_STW*4)    // 55296 B

__global__ void __launch_bounds__(256) attn_mma_k(const __half* __restrict__ Qh,
                                                  const __half* __restrict__ Kh,
                                                  const __half* __restrict__ Vt,
                                                  const int* __restrict__ mask,
                                                  float* __restrict__ O)
{
    const int qt = blockIdx.x, h = blockIdx.y, bb = blockIdx.z;
    extern __shared__ uint32_t asw[];
    __shared__ int s_mask[AT_NST][64];

    const int tid = threadIdx.x, lane = tid & 31, w = tid >> 5;
    const int gr = lane >> 2, gc = lane & 3;
    const uint32_t sbase = smem_u32(asw);

    const __half* kb = Kh + ((size_t)bb * SEQ) * CCH + h * HDD;
    const __half* vb = Vt + ((size_t)(bb * NHH + h)) * HDD * SEQ;

    // ldmatrix lane-address base (bytes, relative to stage start); stride 144B/row
    const uint32_t ldmoff =
        (uint32_t)(((lane >> 4) << 3) + (lane & 7)) * 144 + (((lane >> 3) & 1) << 4);

    auto issue = [&](int jt) {
        int slot = jt % AT_NST;
        uint32_t kdst = sbase + slot * AT_STW * 4;
        uint32_t vdst = kdst + 2304 * 4;
        #pragma unroll
        for (int j = 0; j < 2; j++) {
            int c = tid + 256 * j;
            int row = c >> 3, ch = c & 7;
            uint32_t d = kdst + (row * 36 + ch * 4) * 4;
            const __half* s = kb + (size_t)(jt * 64 + row) * CCH + ch * 8;
            asm volatile("cp.async.cg.shared.global [%0], [%1], 16;" :: "r"(d), "l"(s));
        }
        #pragma unroll
        for (int j = 0; j < 2; j++) {
            int c = tid + 256 * j;
            int row = c >> 3, ch = c & 7;
            uint32_t d = vdst + (row * 36 + ch * 4) * 4;
            const __half* s = vb + (size_t)row * SEQ + jt * 64 + ch * 8;
            asm volatile("cp.async.cg.shared.global [%0], [%1], 16;" :: "r"(d), "l"(s));
        }
        if (tid < 16) {
            uint32_t d = smem_u32(&s_mask[slot][0]) + tid * 16;
            const int* s = mask + bb * SEQ + jt * 64 + tid * 4;
            asm volatile("cp.async.cg.shared.global [%0], [%1], 16;" :: "r"(d), "l"(s));
        }
        asm volatile("cp.async.commit_group;");
    };

    issue(0);
    issue(1);

    // ---- Q fragments direct from fp16 gmem (pre-scaled by 0.125) ----
    uint32_t qa[4][4];
    {
        const __half* qb = Qh + ((size_t)(bb * SEQ + qt * 128)) * CCH + h * HDD;
        int r0 = w * 16 + gr, r1 = r0 + 8;
        #pragma unroll
        for (int ks = 0; ks < 4; ks++) {
            int c = ks * 16 + 2 * gc;
            qa[ks][0] = *(const uint32_t*)(qb + (size_t)r0 * CCH + c);
            qa[ks][1] = *(const uint32_t*)(qb + (size_t)r1 * CCH + c);
            qa[ks][2] = *(const uint32_t*)(qb + (size_t)r0 * CCH + c + 8);
            qa[ks][3] = *(const uint32_t*)(qb + (size_t)r1 * CCH + c + 8);
        }
    }

    float o[8][4];
    #pragma unroll
    for (int ht = 0; ht < 8; ht++)
        #pragma unroll
        for (int e = 0; e < 4; e++) o[ht][e] = 0.f;
    float l0 = 0.f, l1 = 0.f;

    #pragma unroll 1
    for (int jt = 0; jt < 32; jt++) {
        const int slot = jt % AT_NST;
        if (jt < 31) asm volatile("cp.async.wait_group 1;");
        else         asm volatile("cp.async.wait_group 0;");
        __syncthreads();
        if (jt + 2 < 32) issue(jt + 2);

        uint32_t kaddr = sbase + slot * AT_STW * 4 + ldmoff;
        uint32_t vaddr = kaddr + 2304 * 4;

        // ---- S = Q K^T (scores pre-scaled via q) ----
        float s[8][4];
        #pragma unroll
        for (int nt = 0; nt < 8; nt++)
            #pragma unroll
            for (int e = 0; e < 4; e++) s[nt][e] = 0.f;
        #pragma unroll
        for (int ks = 0; ks < 4; ks++) {
            uint32_t bf[8][2];
            #pragma unroll
            for (int p = 0; p < 4; p++)
                ldm_x4(bf[2 * p][0], bf[2 * p][1], bf[2 * p + 1][0], bf[2 * p + 1][1],
                       kaddr + p * (16 * 144) + ks * 32);
            #pragma unroll
            for (int nt = 0; nt < 8; nt++)
                mma_f16_b(s[nt], qa[ks], bf[nt][0], bf[nt][1]);
        }

        // ---- p = exp(s) via poly (|s|<=0.125), masked -> 0 ----
        #pragma unroll
        for (int nt = 0; nt < 8; nt++) {
            int c0 = nt * 8 + 2 * gc;
            bool ok0 = s_mask[slot][c0] != 0;
            bool ok1 = s_mask[slot][c0 + 1] != 0;
            s[nt][0] = ok0 ? exp_small(s[nt][0]) : 0.f;
            s[nt][1] = ok1 ? exp_small(s[nt][1]) : 0.f;
            s[nt][2] = ok0 ? exp_small(s[nt][2]) : 0.f;
            s[nt][3] = ok1 ? exp_small(s[nt][3]) : 0.f;
            l0 += s[nt][0] + s[nt][1];
            l1 += s[nt][2] + s[nt][3];
        }

        // ---- O += P V ----
        #pragma unroll
        for (int ks = 0; ks < 4; ks++) {
            uint32_t aF[4];
            aF[0] = pack2f16(s[2 * ks][0],     s[2 * ks][1]);
            aF[1] = pack2f16(s[2 * ks][2],     s[2 * ks][3]);
            aF[2] = pack2f16(s[2 * ks + 1][0], s[2 * ks + 1][1]);
            aF[3] = pack2f16(s[2 * ks + 1][2], s[2 * ks + 1][3]);
            uint32_t vf[8][2];
            #pragma unroll
            for (int p = 0; p < 4; p++)
                ldm_x4(vf[2 * p][0], vf[2 * p][1], vf[2 * p + 1][0], vf[2 * p + 1][1],
                       vaddr + p * (16 * 144) + ks * 32);
            #pragma unroll
            for (int ht = 0; ht < 8; ht++)
                mma_f16_b(o[ht], aF, vf[ht][0], vf[ht][1]);
        }
    }

    // ---- reduce l across the 4 gc lanes, epilogue ----
    l0 += __shfl_xor_sync(0xffffffffu, l0, 1);
    l0 += __shfl_xor_sync(0xffffffffu, l0, 2);
    l1 += __shfl_xor_sync(0xffffffffu, l1, 1);
    l1 += __shfl_xor_sync(0xffffffffu, l1, 2);
    {
        float inv0 = 1.f / l0, inv1 = 1.f / l1;
        int r0 = w * 16 + gr, r1 = r0 + 8;
        float* Og = O + ((size_t)(bb * SEQ + qt * 128)) * CCH + h * HDD;
        #pragma unroll
        for (int ht = 0; ht < 8; ht++) {
            int c = ht * 8 + 2 * gc;
            *(float2*)(Og + (size_t)r0 * CCH + c) = make_float2(o[ht][0] * inv0, o[ht][1] * inv0);
            *(float2*)(Og + (size_t)r1 * CCH + c) = make_float2(o[ht][2] * inv1, o[ht][3] * inv1);
        }
    }
}

// ---------------- host launcher ---------------------------------------------------
extern "C" void kernel_launch(void* const* d_in, const int* in_sizes, int n_in,
                              void* d_out, int out_size)
{
    const float* x    = (const float*)d_in[0];
    const int*   mask = (const int*)d_in[1];
    const float* wq   = (const float*)d_in[2];
    const float* bq   = (const float*)d_in[3];
    const float* wk   = (const float*)d_in[4];
    const float* bk   = (const float*)d_in[5];
    const float* wv   = (const float*)d_in[6];
    const float* bv   = (const float*)d_in[7];
    const float* qdww = (const float*)d_in[8];
    const float* qdwb = (const float*)d_in[9];
    const float* qpww = (const float*)d_in[10];
    const float* qpwb = (const float*)d_in[11];
    const float* kdww = (const float*)d_in[12];
    const float* kdwb = (const float*)d_in[13];
    const float* kpww = (const float*)d_in[14];
    const float* kpwb = (const float*)d_in[15];
    const float* vdww = (const float*)d_in[16];
    const float* vdwb = (const float*)d_in[17];
    const float* vpww = (const float*)d_in[18];
    const float* vpwb = (const float*)d_in[19];
    const float* wo   = (const float*)d_in[20];
    const float* bo   = (const float*)d_in[21];
    float* out = (float*)d_out;

    float *q, *k, *v, *qc, *kc, *vc, *ao;
    __half *qh, *kh, *vt;
    cudaGetSymbolAddress((void**)&q,  g_q);
    cudaGetSymbolAddress((void**)&k,  g_k);
    cudaGetSymbolAddress((void**)&v,  g_v);
    cudaGetSymbolAddress((void**)&qc, g_qc);
    cudaGetSymbolAddress((void**)&kc, g_kc);
    cudaGetSymbolAddress((void**)&vc, g_vc);
    cudaGetSymbolAddress((void**)&ao, g_ao);
    cudaGetSymbolAddress((void**)&qh, g_qh);
    cudaGetSymbolAddress((void**)&kh, g_kh);
    cudaGetSymbolAddress((void**)&vt, g_vt);

    const int SM1 = 2 * 2 * PLANE_W * 4;   // PROD=1: 40960 B
    const int SM2 = 2 * 3 * PLANE_W * 4;   // PROD=2: 61440 B
    cudaFuncSetAttribute(gemm_f16_k<true, 1>,  cudaFuncAttributeMaxDynamicSharedMemorySize, SM1);
    cudaFuncSetAttribute(gemm_f16_k<true, 2>,  cudaFuncAttributeMaxDynamicSharedMemorySize, SM2);
    cudaFuncSetAttribute(gemm_f16_k<false, 1>, cudaFuncAttributeMaxDynamicSharedMemorySize, SM1);
    cudaFuncSetAttribute(gemm_f16_k<false, 2>, cudaFuncAttributeMaxDynamicSharedMemorySize, SM2);
    cudaFuncSetAttribute(attn_mma_k, cudaFuncAttributeMaxDynamicSharedMemorySize, AT_SMEM);

    dim3 grid_qk(8, 32, 2), grid_v(8, 32, 1);

    // 1) QKV projection + SiLU  (q,k single-product; v split-2)
    gemm_f16_k<true, 1><<<grid_qk, 512, SM1>>>(GArgs{x, wq, bq, q},
                                               GArgs{x, wk, bk, k},
                                               GArgs{x, wk, bk, k});
    gemm_f16_k<true, 2><<<grid_v, 512, SM2>>>(GArgs{x, wv, bv, v},
                                              GArgs{x, wv, bv, v},
                                              GArgs{x, wv, bv, v});

    // 2) depthwise conv k=3 over sequence
    dwconv_k<<<dim3((MROWS * CCH) / 256, 3), 256>>>(q, k, v,
                                                    qdww, kdww, vdww,
                                                    qdwb, kdwb, vdwb,
                                                    qc, kc, vc);

    // 3) pointwise 1x1 conv (q,k single-product; v split-2)
    gemm_f16_k<false, 1><<<grid_qk, 512, SM1>>>(GArgs{qc, qpww, qpwb, q},
                                                GArgs{kc, kpww, kpwb, k},
                                                GArgs{kc, kpww, kpwb, k});
    gemm_f16_k<false, 2><<<grid_v, 512, SM2>>>(GArgs{vc, vpww, vpwb, v},
                                               GArgs{vc, vpww, vpwb, v},
                                               GArgs{vc, vpww, vpwb, v});

    // 4) prep: l2norm q,k -> fp16 (q scaled); transpose v -> fp16
    l2norm_f16_k<<<dim3((MROWS * NHH) / 8, 2), 256>>>(q, k, qh, kh);
    vtrans_k<<<dim3(32, 64, 2), dim3(32, 8)>>>(v, vt);

    // 5) flash attention (cp.async + ldmatrix fp16 pipeline)
    attn_mma_k<<<dim3(SEQ / 128, NHH, BSZ), 256, AT_SMEM>>>(qh, kh, vt, mask, ao);

    // 6) output projection -> d_out (split-2)
    gemm_f16_k<false, 2><<<grid_v, 512, SM2>>>(GArgs{ao, wo, bo, out},
                                               GArgs{ao, wo, bo, out},
                                               GArgs{ao, wo, bo, out});
}

// round 8
// speedup vs baseline: 4.4506x; 1.1131x over previous
#include <cuda_runtime.h>
#include <cuda_fp16.h>
#include <stdint.h>

#define BSZ 2
#define SEQ 2048
#define DIMM 1024
#define CCH 1024
#define NHH 16
#define HDD 64
#define MROWS (BSZ*SEQ)   // 4096

// ---------------- fp16 scratch (device globals) ----------------------------------
__device__ __half g_xh [MROWS*DIMM];
__device__ __half g_xlo[MROWS*DIMM];
__device__ __half g_w16[7][DIMM*CCH];          // wq,wk,wv,qpw,kpw,vpw,wo
__device__ __half g_q16[MROWS*CCH],  g_k16[MROWS*CCH];
__device__ __half g_vhi[MROWS*CCH],  g_vlo[MROWS*CCH];
__device__ __half g_qc16[MROWS*CCH], g_kc16[MROWS*CCH];
__device__ __half g_vchi[MROWS*CCH], g_vclo[MROWS*CCH];
__device__ __half g_qpw[MROWS*CCH],  g_kpw[MROWS*CCH], g_vpw[MROWS*CCH];
__device__ __half g_qn[MROWS*CCH],   g_kn[MROWS*CCH],  g_vt[MROWS*CCH];
__device__ __half g_aoh[MROWS*CCH],  g_aol[MROWS*CCH];

// ================= helpers =======================================================
__device__ __forceinline__ uint32_t smem_u32(const void* p) {
    uint32_t a;
    asm("{ .reg .u64 t; cvta.to.shared.u64 t, %1; cvt.u32.u64 %0, t; }" : "=r"(a) : "l"(p));
    return a;
}
__device__ __forceinline__ uint32_t pack2f16(float x, float y) {
    __half2 t = __floats2half2_rn(x, y);
    return *reinterpret_cast<uint32_t*>(&t);
}
__device__ __forceinline__ void split2h(float x, float y, uint32_t& h, uint32_t& l) {
    __half hx = __float2half_rn(x);
    __half hy = __float2half_rn(y);
    __half2 hp = __halves2half2(hx, hy);
    h = *reinterpret_cast<uint32_t*>(&hp);
    l = pack2f16(x - __half2float(hx), y - __half2float(hy));
}
__device__ __forceinline__ void mma_f16(float* d, const uint32_t* a, const uint32_t* b) {
    asm volatile(
        "mma.sync.aligned.m16n8k16.row.col.f32.f16.f16.f32 "
        "{%0,%1,%2,%3}, {%4,%5,%6,%7}, {%8,%9}, {%0,%1,%2,%3};"
        : "+f"(d[0]), "+f"(d[1]), "+f"(d[2]), "+f"(d[3])
        : "r"(a[0]), "r"(a[1]), "r"(a[2]), "r"(a[3]), "r"(b[0]), "r"(b[1]));
}
__device__ __forceinline__ void mma_f16_b(float* d, const uint32_t* a, uint32_t b0, uint32_t b1) {
    asm volatile(
        "mma.sync.aligned.m16n8k16.row.col.f32.f16.f16.f32 "
        "{%0,%1,%2,%3}, {%4,%5,%6,%7}, {%8,%9}, {%0,%1,%2,%3};"
        : "+f"(d[0]), "+f"(d[1]), "+f"(d[2]), "+f"(d[3])
        : "r"(a[0]), "r"(a[1]), "r"(a[2]), "r"(a[3]), "r"(b0), "r"(b1));
}
__device__ __forceinline__ void ldm_x4(uint32_t& r0, uint32_t& r1, uint32_t& r2, uint32_t& r3,
                                       uint32_t addr) {
    asm volatile("ldmatrix.sync.aligned.m8n8.x4.shared.b16 {%0,%1,%2,%3}, [%4];"
                 : "=r"(r0), "=r"(r1), "=r"(r2), "=r"(r3) : "r"(addr));
}
__device__ __forceinline__ float exp_small(float x) {   // |x| <= 0.125, rel err ~3e-8
    return 1.f + x * (1.f + x * (0.5f + x * (0.166666667f + x * 0.0416666667f)));
}

// ================= prep kernels ==================================================
struct WC { const float* s[7]; __half* d[7]; };
__global__ void wconv_k(WC wc)
{
    const float2* s = (const float2*)wc.s[blockIdx.y];
    __half2* d = (__half2*)wc.d[blockIdx.y];
    int i = blockIdx.x * 256 + threadIdx.x;    // < 512K
    float2 v = s[i];
    d[i] = __floats2half2_rn(v.x, v.y);
}
__global__ void xconv_k(const float2* x, uint32_t* xh, uint32_t* xl)
{
    int i = blockIdx.x * 256 + threadIdx.x;    // < 2M
    float2 v = x[i];
    uint32_t h, l;
    split2h(v.x, v.y, h, l);
    xh[i] = h; xl[i] = l;
}

// ================= fp16 GEMM: cp.async + ldmatrix + mma ==========================
// C[m,n] = sum_k A[m,k]*W[n,k] + bias[n]; M=4096, N=K=1024. fp16 inputs.
// PROD=2: A has hi+lo planes. OMODE: 0=f32 out, 1=f16 out, 2=f16 hi/lo out.
// CTA 128x128, KC=32, 512 threads, plane row = 64B data + 16B pad (80B).
struct GH { const __half* A; const __half* Al; const __half* W; const float* bias;
            void* C; void* Cl; };

template<bool SILU, int PROD, int OMODE>
__global__ void __launch_bounds__(512, (PROD == 1) ? 2 : 1)
gemm_h_k(GH g0, GH g1, GH g2)
{
    constexpr int NST = (PROD == 1) ? 4 : 3;
    constexpr int PL  = 10240;                  // plane bytes (128 rows x 80B)
    constexpr int STB = (PROD + 1) * PL;
    GH g = (blockIdx.z == 0) ? g0 : ((blockIdx.z == 1) ? g1 : g2);
    extern __shared__ uint32_t smw[];
    const uint32_t sb = smem_u32(smw);

    const int tid = threadIdx.x, lane = tid & 31, wid = tid >> 5;
    const int wm = wid & 3, wn = wid >> 2;
    const int gr = lane >> 2, gc = lane & 3;
    const int m0 = blockIdx.y * 128, n0 = blockIdx.x * 128;

    const int rr = tid >> 2, ch = tid & 3;      // cp.async geometry
    const __half* pa = g.A + (size_t)(m0 + rr) * DIMM + ch * 8;
    const __half* pl = (PROD == 2) ? (g.Al + (size_t)(m0 + rr) * DIMM + ch * 8) : (const __half*)0;
    const __half* pw = g.W + (size_t)(n0 + rr) * DIMM + ch * 8;
    const uint32_t dbase = sb + rr * 80 + ch * 16;

    const uint32_t aoff = (uint32_t)(wm * 32 + (lane & 15)) * 80 + ((lane >> 4) << 4);
    const uint32_t boff = PROD * PL +
        (uint32_t)(wn * 32 + ((lane >> 4) << 3) + (lane & 7)) * 80 + (((lane >> 3) & 1) << 4);

    auto issue = [&](int i) {
        int kk = i * 32;
        uint32_t d = dbase + (i % NST) * STB;
        asm volatile("cp.async.cg.shared.global [%0], [%1], 16;" :: "r"(d), "l"(pa + kk));
        if (PROD == 2)
            asm volatile("cp.async.cg.shared.global [%0], [%1], 16;" :: "r"(d + PL), "l"(pl + kk));
        asm volatile("cp.async.cg.shared.global [%0], [%1], 16;" :: "r"(d + PROD * PL), "l"(pw + kk));
        asm volatile("cp.async.commit_group;");
    };

    float acc[2][4][4];
    #pragma unroll
    for (int mi = 0; mi < 2; mi++)
        #pragma unroll
        for (int ni = 0; ni < 4; ni++)
            #pragma unroll
            for (int e = 0; e < 4; e++) acc[mi][ni][e] = 0.f;

    #pragma unroll
    for (int s = 0; s < NST - 1; s++) issue(s);

    #pragma unroll 1
    for (int i = 0; i < 32; i++) {
        if (31 - i >= NST - 2)           asm volatile("cp.async.wait_group %0;" :: "n"(NST - 2));
        else if (NST >= 4 && 31 - i >= 1) asm volatile("cp.async.wait_group 1;");
        else                              asm volatile("cp.async.wait_group 0;");
        __syncthreads();
        if (i + NST - 1 < 32) issue(i + NST - 1);

        uint32_t stb = sb + (i % NST) * STB;
        #pragma unroll
        for (int ki = 0; ki < 2; ki++) {
            uint32_t koff = ki * 32;
            uint32_t ah[2][4], al[2][4], bf[4][2];
            ldm_x4(ah[0][0], ah[0][1], ah[0][2], ah[0][3], stb + aoff + koff);
            ldm_x4(ah[1][0], ah[1][1], ah[1][2], ah[1][3], stb + aoff + 16 * 80 + koff);
            if (PROD == 2) {
                ldm_x4(al[0][0], al[0][1], al[0][2], al[0][3], stb + aoff + PL + koff);
                ldm_x4(al[1][0], al[1][1], al[1][2], al[1][3], stb + aoff + PL + 16 * 80 + koff);
            }
            ldm_x4(bf[0][0], bf[0][1], bf[1][0], bf[1][1], stb + boff + koff);
            ldm_x4(bf[2][0], bf[2][1], bf[3][0], bf[3][1], stb + boff + 16 * 80 + koff);
            #pragma unroll
            for (int ni = 0; ni < 4; ni++)
                #pragma unroll
                for (int mi = 0; mi < 2; mi++) {
                    mma_f16(acc[mi][ni], ah[mi], bf[ni]);
                    if (PROD == 2) mma_f16(acc[mi][ni], al[mi], bf[ni]);
                }
        }
    }

    #pragma unroll
    for (int ni = 0; ni < 4; ni++) {
        int cg = n0 + wn * 32 + ni * 8 + 2 * gc;
        float b0 = g.bias[cg], b1 = g.bias[cg + 1];
        #pragma unroll
        for (int mi = 0; mi < 2; mi++) {
            int r = m0 + wm * 32 + mi * 16 + gr;
            float v0 = acc[mi][ni][0] + b0;
            float v1 = acc[mi][ni][1] + b1;
            float v2 = acc[mi][ni][2] + b0;
            float v3 = acc[mi][ni][3] + b1;
            if (SILU) {
                v0 = v0 / (1.f + __expf(-v0));
                v1 = v1 / (1.f + __expf(-v1));
                v2 = v2 / (1.f + __expf(-v2));
                v3 = v3 / (1.f + __expf(-v3));
            }
            if (OMODE == 0) {
                float* C = (float*)g.C;
                *(float2*)(C + (size_t)r * CCH + cg)       = make_float2(v0, v1);
                *(float2*)(C + (size_t)(r + 8) * CCH + cg) = make_float2(v2, v3);
            } else if (OMODE == 1) {
                __half* C = (__half*)g.C;
                *(uint32_t*)(C + (size_t)r * CCH + cg)       = pack2f16(v0, v1);
                *(uint32_t*)(C + (size_t)(r + 8) * CCH + cg) = pack2f16(v2, v3);
            } else {
                __half* C  = (__half*)g.C;
                __half* Cl = (__half*)g.Cl;
                uint32_t h, l;
                split2h(v0, v1, h, l);
                *(uint32_t*)(C  + (size_t)r * CCH + cg) = h;
                *(uint32_t*)(Cl + (size_t)r * CCH + cg) = l;
                split2h(v2, v3, h, l);
                *(uint32_t*)(C  + (size_t)(r + 8) * CCH + cg) = h;
                *(uint32_t*)(Cl + (size_t)(r + 8) * CCH + cg) = l;
            }
        }
    }
}

// ---------------- depthwise conv k=3 (fp16 single; q,k) --------------------------
__global__ void dwconv_h_k(const __half2* i0, const __half2* i1,
                           const float* w0, const float* w1,
                           const float* bq, const float* bk,
                           __half2* o0, __half2* o1)
{
    const __half2* in = blockIdx.y ? i1 : i0;
    const float* w    = blockIdx.y ? w1 : w0;
    const float* bb   = blockIdx.y ? bk : bq;
    __half2* out      = blockIdx.y ? o1 : o0;
    int i2 = blockIdx.x * 256 + threadIdx.x;     // < 2M
    int c2 = i2 & 511, m = i2 >> 9, s = m & (SEQ - 1);
    int c0 = c2 * 2;
    float wa0 = w[c0*3], wa1 = w[c0*3+1], wa2 = w[c0*3+2];
    float wb0 = w[c0*3+3], wb1 = w[c0*3+4], wb2 = w[c0*3+5];
    float2 x  = __half22float2(in[i2]);
    float2 xm = make_float2(0.f, 0.f), xp = make_float2(0.f, 0.f);
    if (s > 0)       xm = __half22float2(in[i2 - 512]);
    if (s < SEQ - 1) xp = __half22float2(in[i2 + 512]);
    float va = xm.x*wa0 + x.x*wa1 + xp.x*wa2 + bb[c0];
    float vb = xm.y*wb0 + x.y*wb1 + xp.y*wb2 + bb[c0+1];
    out[i2] = __floats2half2_rn(va, vb);
}

// ---------------- depthwise conv k=3 (fp16 hi/lo; v) -----------------------------
__global__ void dwconv_hl_k(const __half2* ih, const __half2* il,
                            const float* w, const float* bb,
                            uint32_t* oh, uint32_t* ol)
{
    int i2 = blockIdx.x * 256 + threadIdx.x;
    int c2 = i2 & 511, m = i2 >> 9, s = m & (SEQ - 1);
    int c0 = c2 * 2;
    float wa0 = w[c0*3], wa1 = w[c0*3+1], wa2 = w[c0*3+2];
    float wb0 = w[c0*3+3], wb1 = w[c0*3+4], wb2 = w[c0*3+5];
    float2 xh = __half22float2(ih[i2]), xl = __half22float2(il[i2]);
    float2 x  = make_float2(xh.x + xl.x, xh.y + xl.y);
    float2 xm = make_float2(0.f, 0.f), xp = make_float2(0.f, 0.f);
    if (s > 0) {
        float2 a = __half22float2(ih[i2 - 512]), b = __half22float2(il[i2 - 512]);
        xm = make_float2(a.x + b.x, a.y + b.y);
    }
    if (s < SEQ - 1) {
        float2 a = __half22float2(ih[i2 + 512]), b = __half22float2(il[i2 + 512]);
        xp = make_float2(a.x + b.x, a.y + b.y);
    }
    float va = xm.x*wa0 + x.x*wa1 + xp.x*wa2 + bb[c0];
    float vb = xm.y*wb0 + x.y*wb1 + xp.y*wb2 + bb[c0+1];
    uint32_t h, l;
    split2h(va, vb, h, l);
    oh[i2] = h; ol[i2] = l;
}

// ---------------- per-head L2 normalize (fp16 in/out; q gets 0.125 folded) -------
__global__ void l2norm_f16_k(const __half2* q, const __half2* k, __half2* qn, __half2* kn)
{
    const __half2* src = blockIdx.y ? k : q;
    __half2* dst = blockIdx.y ? kn : qn;
    float sc = blockIdx.y ? 1.0f : 0.125f;
    int warp = threadIdx.x >> 5, lane = threadIdx.x & 31;
    size_t g = (size_t)blockIdx.x * 8 + warp;
    float2 x = __half22float2(src[g * 32 + lane]);
    float ss = x.x * x.x + x.y * x.y;
    #pragma unroll
    for (int o = 16; o; o >>= 1) ss += __shfl_xor_sync(0xffffffffu, ss, o);
    float inv = sc / fmaxf(sqrtf(ss), 1e-12f);
    dst[g * 32 + lane] = __floats2half2_rn(x.x * inv, x.y * inv);
}

// ---------------- V transpose fp16 [b][ch][s] ------------------------------------
__global__ void vtrans_k(const __half* v, __half* vt)
{
    __shared__ float t[32][33];
    int b = blockIdx.z;
    int s0 = blockIdx.y * 32, c0 = blockIdx.x * 32;
    int tx = threadIdx.x, ty = threadIdx.y;   // 32x8
    #pragma unroll
    for (int j = 0; j < 4; j++)
        t[ty + 8 * j][tx] = __half2float(v[(size_t)(b * SEQ + s0 + ty + 8 * j) * CCH + c0 + tx]);
    __syncthreads();
    #pragma unroll
    for (int j = 0; j < 4; j++)
        vt[(size_t)(b * CCH + c0 + ty + 8 * j) * SEQ + s0 + tx] = __float2half(t[tx][ty + 8 * j]);
}

// ================= flash attention: cp.async + ldmatrix fp16 pipeline ============
#define AT_STW 4608
#define AT_NST 3
#define AT_SMEM (AT_NST*AT_STW*4)    // 55296 B

__global__ void __launch_bounds__(256) attn_mma_k(const __half* __restrict__ Qh,
                                                  const __half* __restrict__ Kh,
                                                  const __half* __restrict__ Vt,
                                                  const int* __restrict__ mask,
                                                  __half* __restrict__ AOh,
                                                  __half* __restrict__ AOl)
{
    const int qt = blockIdx.x, h = blockIdx.y, bb = blockIdx.z;
    extern __shared__ uint32_t asw[];
    __shared__ int s_mask[AT_NST][64];

    const int tid = threadIdx.x, lane = tid & 31, w = tid >> 5;
    const int gr = lane >> 2, gc = lane & 3;
    const uint32_t sbase = smem_u32(asw);

    const __half* kb = Kh + ((size_t)bb * SEQ) * CCH + h * HDD;
    const __half* vb = Vt + ((size_t)(bb * NHH + h)) * HDD * SEQ;

    const uint32_t ldmoff =
        (uint32_t)(((lane >> 4) << 3) + (lane & 7)) * 144 + (((lane >> 3) & 1) << 4);

    auto issue = [&](int jt) {
        int slot = jt % AT_NST;
        uint32_t kdst = sbase + slot * AT_STW * 4;
        uint32_t vdst = kdst + 2304 * 4;
        #pragma unroll
        for (int j = 0; j < 2; j++) {
            int c = tid + 256 * j;
            int row = c >> 3, ch = c & 7;
            uint32_t d = kdst + (row * 36 + ch * 4) * 4;
            const __half* s = kb + (size_t)(jt * 64 + row) * CCH + ch * 8;
            asm volatile("cp.async.cg.shared.global [%0], [%1], 16;" :: "r"(d), "l"(s));
        }
        #pragma unroll
        for (int j = 0; j < 2; j++) {
            int c = tid + 256 * j;
            int row = c >> 3, ch = c & 7;
            uint32_t d = vdst + (row * 36 + ch * 4) * 4;
            const __half* s = vb + (size_t)row * SEQ + jt * 64 + ch * 8;
            asm volatile("cp.async.cg.shared.global [%0], [%1], 16;" :: "r"(d), "l"(s));
        }
        if (tid < 16) {
            uint32_t d = smem_u32(&s_mask[slot][0]) + tid * 16;
            const int* s = mask + bb * SEQ + jt * 64 + tid * 4;
            asm volatile("cp.async.cg.shared.global [%0], [%1], 16;" :: "r"(d), "l"(s));
        }
        asm volatile("cp.async.commit_group;");
    };

    issue(0);
    issue(1);

    uint32_t qa[4][4];
    {
        const __half* qb = Qh + ((size_t)(bb * SEQ + qt * 128)) * CCH + h * HDD;
        int r0 = w * 16 + gr, r1 = r0 + 8;
        #pragma unroll
        for (int ks = 0; ks < 4; ks++) {
            int c = ks * 16 + 2 * gc;
            qa[ks][0] = *(const uint32_t*)(qb + (size_t)r0 * CCH + c);
            qa[ks][1] = *(const uint32_t*)(qb + (size_t)r1 * CCH + c);
            qa[ks][2] = *(const uint32_t*)(qb + (size_t)r0 * CCH + c + 8);
            qa[ks][3] = *(const uint32_t*)(qb + (size_t)r1 * CCH + c + 8);
        }
    }

    float o[8][4];
    #pragma unroll
    for (int ht = 0; ht < 8; ht++)
        #pragma unroll
        for (int e = 0; e < 4; e++) o[ht][e] = 0.f;
    float l0 = 0.f, l1 = 0.f;

    #pragma unroll 1
    for (int jt = 0; jt < 32; jt++) {
        const int slot = jt % AT_NST;
        if (jt < 31) asm volatile("cp.async.wait_group 1;");
        else         asm volatile("cp.async.wait_group 0;");
        __syncthreads();
        if (jt + 2 < 32) issue(jt + 2);

        uint32_t kaddr = sbase + slot * AT_STW * 4 + ldmoff;
        uint32_t vaddr = kaddr + 2304 * 4;

        float s[8][4];
        #pragma unroll
        for (int nt = 0; nt < 8; nt++)
            #pragma unroll
            for (int e = 0; e < 4; e++) s[nt][e] = 0.f;
        #pragma unroll
        for (int ks = 0; ks < 4; ks++) {
            uint32_t bf[8][2];
            #pragma unroll
            for (int p = 0; p < 4; p++)
                ldm_x4(bf[2 * p][0], bf[2 * p][1], bf[2 * p + 1][0], bf[2 * p + 1][1],
                       kaddr + p * (16 * 144) + ks * 32);
            #pragma unroll
            for (int nt = 0; nt < 8; nt++)
                mma_f16_b(s[nt], qa[ks], bf[nt][0], bf[nt][1]);
        }

        #pragma unroll
        for (int nt = 0; nt < 8; nt++) {
            int c0 = nt * 8 + 2 * gc;
            bool ok0 = s_mask[slot][c0] != 0;
            bool ok1 = s_mask[slot][c0 + 1] != 0;
            s[nt][0] = ok0 ? exp_small(s[nt][0]) : 0.f;
            s[nt][1] = ok1 ? exp_small(s[nt][1]) : 0.f;
            s[nt][2] = ok0 ? exp_small(s[nt][2]) : 0.f;
            s[nt][3] = ok1 ? exp_small(s[nt][3]) : 0.f;
            l0 += s[nt][0] + s[nt][1];
            l1 += s[nt][2] + s[nt][3];
        }

        #pragma unroll
        for (int ks = 0; ks < 4; ks++) {
            uint32_t aF[4];
            aF[0] = pack2f16(s[2 * ks][0],     s[2 * ks][1]);
            aF[1] = pack2f16(s[2 * ks][2],     s[2 * ks][3]);
            aF[2] = pack2f16(s[2 * ks + 1][0], s[2 * ks + 1][1]);
            aF[3] = pack2f16(s[2 * ks + 1][2], s[2 * ks + 1][3]);
            uint32_t vf[8][2];
            #pragma unroll
            for (int p = 0; p < 4; p++)
                ldm_x4(vf[2 * p][0], vf[2 * p][1], vf[2 * p + 1][0], vf[2 * p + 1][1],
                       vaddr + p * (16 * 144) + ks * 32);
            #pragma unroll
            for (int ht = 0; ht < 8; ht++)
                mma_f16_b(o[ht], aF, vf[ht][0], vf[ht][1]);
        }
    }

    l0 += __shfl_xor_sync(0xffffffffu, l0, 1);
    l0 += __shfl_xor_sync(0xffffffffu, l0, 2);
    l1 += __shfl_xor_sync(0xffffffffu, l1, 1);
    l1 += __shfl_xor_sync(0xffffffffu, l1, 2);
    {
        float inv0 = 1.f / l0, inv1 = 1.f / l1;
        int r0 = w * 16 + gr, r1 = r0 + 8;
        size_t base = ((size_t)(bb * SEQ + qt * 128)) * CCH + h * HDD;
        __half* Oh = AOh + base;
        __half* Ol = AOl + base;
        #pragma unroll
        for (int ht = 0; ht < 8; ht++) {
            int c = ht * 8 + 2 * gc;
            uint32_t hh, ll;
            split2h(o[ht][0] * inv0, o[ht][1] * inv0, hh, ll);
            *(uint32_t*)(Oh + (size_t)r0 * CCH + c) = hh;
            *(uint32_t*)(Ol + (size_t)r0 * CCH + c) = ll;
            split2h(o[ht][2] * inv1, o[ht][3] * inv1, hh, ll);
            *(uint32_t*)(Oh + (size_t)r1 * CCH + c) = hh;
            *(uint32_t*)(Ol + (size_t)r1 * CCH + c) = ll;
        }
    }
}

// ---------------- host launcher ---------------------------------------------------
extern "C" void kernel_launch(void* const* d_in, const int* in_sizes, int n_in,
                              void* d_out, int out_size)
{
    const float* x    = (const float*)d_in[0];
    const int*   mask = (const int*)d_in[1];
    const float* wq   = (const float*)d_in[2];
    const float* bq   = (const float*)d_in[3];
    const float* wk   = (const float*)d_in[4];
    const float* bk   = (const float*)d_in[5];
    const float* wv   = (const float*)d_in[6];
    const float* bv   = (const float*)d_in[7];
    const float* qdww = (const float*)d_in[8];
    const float* qdwb = (const float*)d_in[9];
    const float* qpww = (const float*)d_in[10];
    const float* qpwb = (const float*)d_in[11];
    const float* kdww = (const float*)d_in[12];
    const float* kdwb = (const float*)d_in[13];
    const float* kpww = (const float*)d_in[14];
    const float* kpwb = (const float*)d_in[15];
    const float* vdww = (const float*)d_in[16];
    const float* vdwb = (const float*)d_in[17];
    const float* vpww = (const float*)d_in[18];
    const float* vpwb = (const float*)d_in[19];
    const float* wo   = (const float*)d_in[20];
    const float* bo   = (const float*)d_in[21];
    float* out = (float*)d_out;

    __half *xh, *xlo, *w16, *q16, *k16, *vhi, *vlo, *qc16, *kc16, *vchi, *vclo;
    __half *qpw, *kpw, *vpw, *qn, *kn, *vt, *aoh, *aol;
    cudaGetSymbolAddress((void**)&xh,  g_xh);
    cudaGetSymbolAddress((void**)&xlo, g_xlo);
    cudaGetSymbolAddress((void**)&w16, g_w16);
    cudaGetSymbolAddress((void**)&q16, g_q16);
    cudaGetSymbolAddress((void**)&k16, g_k16);
    cudaGetSymbolAddress((void**)&vhi, g_vhi);
    cudaGetSymbolAddress((void**)&vlo, g_vlo);
    cudaGetSymbolAddress((void**)&qc16, g_qc16);
    cudaGetSymbolAddress((void**)&kc16, g_kc16);
    cudaGetSymbolAddress((void**)&vchi, g_vchi);
    cudaGetSymbolAddress((void**)&vclo, g_vclo);
    cudaGetSymbolAddress((void**)&qpw, g_qpw);
    cudaGetSymbolAddress((void**)&kpw, g_kpw);
    cudaGetSymbolAddress((void**)&vpw, g_vpw);
    cudaGetSymbolAddress((void**)&qn,  g_qn);
    cudaGetSymbolAddress((void**)&kn,  g_kn);
    cudaGetSymbolAddress((void**)&vt,  g_vt);
    cudaGetSymbolAddress((void**)&aoh, g_aoh);
    cudaGetSymbolAddress((void**)&aol, g_aol);

    __half* wqh  = w16 + 0 * (size_t)DIMM * CCH;
    __half* wkh  = w16 + 1 * (size_t)DIMM * CCH;
    __half* wvh  = w16 + 2 * (size_t)DIMM * CCH;
    __half* qpwh = w16 + 3 * (size_t)DIMM * CCH;
    __half* kpwh = w16 + 4 * (size_t)DIMM * CCH;
    __half* vpwh = w16 + 5 * (size_t)DIMM * CCH;
    __half* woh  = w16 + 6 * (size_t)DIMM * CCH;

    const int SMP1 = 4 * 2 * 10240;    // 81920
    const int SMP2 = 3 * 3 * 10240;    // 92160
    cudaFuncSetAttribute(gemm_h_k<true, 1, 1>,  cudaFuncAttributeMaxDynamicSharedMemorySize, SMP1);
    cudaFuncSetAttribute(gemm_h_k<true, 2, 2>,  cudaFuncAttributeMaxDynamicSharedMemorySize, SMP2);
    cudaFuncSetAttribute(gemm_h_k<false, 1, 1>, cudaFuncAttributeMaxDynamicSharedMemorySize, SMP1);
    cudaFuncSetAttribute(gemm_h_k<false, 2, 1>, cudaFuncAttributeMaxDynamicSharedMemorySize, SMP2);
    cudaFuncSetAttribute(gemm_h_k<false, 2, 0>, cudaFuncAttributeMaxDynamicSharedMemorySize, SMP2);
    cudaFuncSetAttribute(attn_mma_k, cudaFuncAttributeMaxDynamicSharedMemorySize, AT_SMEM);

    // 0) prep: weights + x to fp16
    WC wc;
    wc.s[0] = wq;  wc.d[0] = wqh;
    wc.s[1] = wk;  wc.d[1] = wkh;
    wc.s[2] = wv;  wc.d[2] = wvh;
    wc.s[3] = qpww; wc.d[3] = qpwh;
    wc.s[4] = kpww; wc.d[4] = kpwh;
    wc.s[5] = vpww; wc.d[5] = vpwh;
    wc.s[6] = wo;  wc.d[6] = woh;
    wconv_k<<<dim3(2048, 7), 256>>>(wc);
    xconv_k<<<8192, 256>>>((const float2*)x, (uint32_t*)xh, (uint32_t*)xlo);

    dim3 grid_qk(8, 32, 2), grid_1(8, 32, 1);

    // 1) QKV projection + SiLU
    gemm_h_k<true, 1, 1><<<grid_qk, 512, SMP1>>>(
        GH{xh, 0, wqh, bq, q16, 0}, GH{xh, 0, wkh, bk, k16, 0}, GH{xh, 0, wkh, bk, k16, 0});
    gemm_h_k<true, 2, 2><<<grid_1, 512, SMP2>>>(
        GH{xh, xlo, wvh, bv, vhi, vlo}, GH{xh, xlo, wvh, bv, vhi, vlo}, GH{xh, xlo, wvh, bv, vhi, vlo});

    // 2) depthwise conv
    dwconv_h_k<<<dim3(8192, 2), 256>>>((const __half2*)q16, (const __half2*)k16,
                                       qdww, kdww, qdwb, kdwb,
                                       (__half2*)qc16, (__half2*)kc16);
    dwconv_hl_k<<<8192, 256>>>((const __half2*)vhi, (const __half2*)vlo,
                               vdww, vdwb, (uint32_t*)vchi, (uint32_t*)vclo);

    // 3) pointwise conv
    gemm_h_k<false, 1, 1><<<grid_qk, 512, SMP1>>>(
        GH{qc16, 0, qpwh, qpwb, qpw, 0}, GH{kc16, 0, kpwh, kpwb, kpw, 0}, GH{kc16, 0, kpwh, kpwb, kpw, 0});
    gemm_h_k<false, 2, 1><<<grid_1, 512, SMP2>>>(
        GH{vchi, vclo, vpwh, vpwb, vpw, 0}, GH{vchi, vclo, vpwh, vpwb, vpw, 0}, GH{vchi, vclo, vpwh, vpwb, vpw, 0});

    // 4) l2norm (q scaled by 0.125) + v transpose
    l2norm_f16_k<<<dim3((MROWS * NHH) / 8, 2), 256>>>((const __half2*)qpw, (const __half2*)kpw,
                                                      (__half2*)qn, (__half2*)kn);
    vtrans_k<<<dim3(32, 64, 2), dim3(32, 8)>>>(vpw, vt);

    // 5) flash attention -> fp16 hi/lo
    attn_mma_k<<<dim3(SEQ / 128, NHH, BSZ), 256, AT_SMEM>>>(qn, kn, vt, mask, aoh, aol);

    // 6) output projection -> d_out (fp32)
    gemm_h_k<false, 2, 0><<<grid_1, 512, SMP2>>>(
        GH{aoh, aol, woh, bo, out, 0}, GH{aoh, aol, woh, bo, out, 0}, GH{aoh, aol, woh, bo, out, 0});
}

// round 9
// speedup vs baseline: 4.5521x; 1.0228x over previous
#include <cuda_runtime.h>
#include <cuda_fp16.h>
#include <stdint.h>

#define BSZ 2
#define SEQ 2048
#define DIMM 1024
#define CCH 1024
#define NHH 16
#define HDD 64
#define MROWS (BSZ*SEQ)   // 4096

// ---------------- fp16 scratch (device globals) ----------------------------------
__device__ __half g_xh [MROWS*DIMM];
__device__ __half g_xlo[MROWS*DIMM];
__device__ __half g_w16[7][DIMM*CCH];          // wq,wk,wv,qpw,kpw,vpw,wo
__device__ __half g_q16[MROWS*CCH],  g_k16[MROWS*CCH];
__device__ __half g_vhi[MROWS*CCH],  g_vlo[MROWS*CCH];
__device__ __half g_qc16[MROWS*CCH], g_kc16[MROWS*CCH];
__device__ __half g_vchi[MROWS*CCH], g_vclo[MROWS*CCH];
__device__ __half g_qpw[MROWS*CCH],  g_kpw[MROWS*CCH], g_vpw[MROWS*CCH];
__device__ __half g_qn[MROWS*CCH],   g_kn[MROWS*CCH],  g_vt[MROWS*CCH];
__device__ __half g_aoh[MROWS*CCH],  g_aol[MROWS*CCH];

// ================= helpers =======================================================
__device__ __forceinline__ uint32_t smem_u32(const void* p) {
    uint32_t a;
    asm("{ .reg .u64 t; cvta.to.shared.u64 t, %1; cvt.u32.u64 %0, t; }" : "=r"(a) : "l"(p));
    return a;
}
__device__ __forceinline__ uint32_t pack2f16(float x, float y) {
    __half2 t = __floats2half2_rn(x, y);
    return *reinterpret_cast<uint32_t*>(&t);
}
__device__ __forceinline__ void split2h(float x, float y, uint32_t& h, uint32_t& l) {
    __half hx = __float2half_rn(x);
    __half hy = __float2half_rn(y);
    __half2 hp = __halves2half2(hx, hy);
    h = *reinterpret_cast<uint32_t*>(&hp);
    l = pack2f16(x - __half2float(hx), y - __half2float(hy));
}
__device__ __forceinline__ void mma_f16(float* d, const uint32_t* a, const uint32_t* b) {
    asm volatile(
        "mma.sync.aligned.m16n8k16.row.col.f32.f16.f16.f32 "
        "{%0,%1,%2,%3}, {%4,%5,%6,%7}, {%8,%9}, {%0,%1,%2,%3};"
        : "+f"(d[0]), "+f"(d[1]), "+f"(d[2]), "+f"(d[3])
        : "r"(a[0]), "r"(a[1]), "r"(a[2]), "r"(a[3]), "r"(b[0]), "r"(b[1]));
}
__device__ __forceinline__ void mma_f16_b(float* d, const uint32_t* a, uint32_t b0, uint32_t b1) {
    asm volatile(
        "mma.sync.aligned.m16n8k16.row.col.f32.f16.f16.f32 "
        "{%0,%1,%2,%3}, {%4,%5,%6,%7}, {%8,%9}, {%0,%1,%2,%3};"
        : "+f"(d[0]), "+f"(d[1]), "+f"(d[2]), "+f"(d[3])
        : "r"(a[0]), "r"(a[1]), "r"(a[2]), "r"(a[3]), "r"(b0), "r"(b1));
}
__device__ __forceinline__ void ldm_x4(uint32_t& r0, uint32_t& r1, uint32_t& r2, uint32_t& r3,
                                       uint32_t addr) {
    asm volatile("ldmatrix.sync.aligned.m8n8.x4.shared.b16 {%0,%1,%2,%3}, [%4];"
                 : "=r"(r0), "=r"(r1), "=r"(r2), "=r"(r3) : "r"(addr));
}
__device__ __forceinline__ float exp_small(float x) {   // |x| <= 0.125, rel err ~3e-8
    return 1.f + x * (1.f + x * (0.5f + x * (0.166666667f + x * 0.0416666667f)));
}

// ================= prep kernels ==================================================
struct WC { const float* s[7]; __half* d[7]; };
__global__ void wconv_k(WC wc)
{
    const float2* s = (const float2*)wc.s[blockIdx.y];
    __half2* d = (__half2*)wc.d[blockIdx.y];
    int i = blockIdx.x * 256 + threadIdx.x;    // < 512K
    float2 v = s[i];
    d[i] = __floats2half2_rn(v.x, v.y);
}
__global__ void xconv_k(const float2* x, uint32_t* xh, uint32_t* xl)
{
    int i = blockIdx.x * 256 + threadIdx.x;    // < 2M
    float2 v = x[i];
    uint32_t h, l;
    split2h(v.x, v.y, h, l);
    xh[i] = h; xl[i] = l;
}

// ================= fp16 GEMM: cp.async + ldmatrix + mma ==========================
// C[m,n] = sum_k A[m,k]*W[n,k] + bias[n]; M=4096, N=K=1024. fp16 inputs.
// PROD=2: A has hi+lo planes. OMODE: 0=f32 out, 1=f16 out, 2=f16 hi/lo out.
// CTA 64x128, KC=32, 256 threads (8 warps, 2x4), warp tile 32x32, 4-stage cp.async.
struct GH { const __half* A; const __half* Al; const __half* W; const float* bias;
            void* C; void* Cl; };

#define PL_A 5120                    // A plane: 64 rows x 80B
#define PL_B 10240                   // B plane: 128 rows x 80B

template<bool SILU, int PROD, int OMODE>
__global__ void __launch_bounds__(256, (PROD == 1) ? 3 : 2)
gemm_h_k(GH g0, GH g1, GH g2)
{
    constexpr int NST = 4;
    constexpr int STB = PROD * PL_A + PL_B;     // stage bytes
    GH g = (blockIdx.z == 0) ? g0 : ((blockIdx.z == 1) ? g1 : g2);
    extern __shared__ uint32_t smw[];
    const uint32_t sb = smem_u32(smw);

    const int tid = threadIdx.x, lane = tid & 31, wid = tid >> 5;
    const int wm = wid & 1, wn = wid >> 1;       // 2x4 warp grid
    const int gr = lane >> 2, gc = lane & 3;
    const int m0 = blockIdx.y * 64, n0 = blockIdx.x * 128;

    const int rr = tid >> 2, ch = tid & 3;       // cp.async geometry (64 rows x 4 chunks)
    const __half* pa  = g.A + (size_t)(m0 + rr) * DIMM + ch * 8;
    const __half* pl  = (PROD == 2) ? (g.Al + (size_t)(m0 + rr) * DIMM + ch * 8) : (const __half*)0;
    const __half* pw0 = g.W + (size_t)(n0 + rr) * DIMM + ch * 8;
    const __half* pw1 = g.W + (size_t)(n0 + rr + 64) * DIMM + ch * 8;
    const uint32_t dA  = sb + rr * 80 + ch * 16;
    const uint32_t dB0 = sb + PROD * PL_A + rr * 80 + ch * 16;
    const uint32_t dB1 = dB0 + 64 * 80;

    const uint32_t aoff = (uint32_t)(wm * 32 + (lane & 15)) * 80 + ((lane >> 4) << 4);
    const uint32_t boff = PROD * PL_A +
        (uint32_t)(wn * 32 + ((lane >> 4) << 3) + (lane & 7)) * 80 + (((lane >> 3) & 1) << 4);

    auto issue = [&](int i) {
        int kk = i * 32;
        uint32_t st = (i % NST) * STB;
        asm volatile("cp.async.cg.shared.global [%0], [%1], 16;" :: "r"(dA + st), "l"(pa + kk));
        if (PROD == 2)
            asm volatile("cp.async.cg.shared.global [%0], [%1], 16;" :: "r"(dA + PL_A + st), "l"(pl + kk));
        asm volatile("cp.async.cg.shared.global [%0], [%1], 16;" :: "r"(dB0 + st), "l"(pw0 + kk));
        asm volatile("cp.async.cg.shared.global [%0], [%1], 16;" :: "r"(dB1 + st), "l"(pw1 + kk));
        asm volatile("cp.async.commit_group;");
    };

    float acc[2][4][4];
    #pragma unroll
    for (int mi = 0; mi < 2; mi++)
        #pragma unroll
        for (int ni = 0; ni < 4; ni++)
            #pragma unroll
            for (int e = 0; e < 4; e++) acc[mi][ni][e] = 0.f;

    #pragma unroll
    for (int s = 0; s < NST - 1; s++) issue(s);

    #pragma unroll 1
    for (int i = 0; i < 32; i++) {
        if (31 - i >= NST - 2)      asm volatile("cp.async.wait_group %0;" :: "n"(NST - 2));
        else if (31 - i >= 1)       asm volatile("cp.async.wait_group 1;");
        else                        asm volatile("cp.async.wait_group 0;");
        __syncthreads();
        if (i + NST - 1 < 32) issue(i + NST - 1);

        uint32_t stb = sb + (i % NST) * STB;
        #pragma unroll
        for (int ki = 0; ki < 2; ki++) {
            uint32_t koff = ki * 32;
            uint32_t ah[2][4], al[2][4], bf[4][2];
            ldm_x4(ah[0][0], ah[0][1], ah[0][2], ah[0][3], stb + aoff + koff);
            ldm_x4(ah[1][0], ah[1][1], ah[1][2], ah[1][3], stb + aoff + 16 * 80 + koff);
            if (PROD == 2) {
                ldm_x4(al[0][0], al[0][1], al[0][2], al[0][3], stb + aoff + PL_A + koff);
                ldm_x4(al[1][0], al[1][1], al[1][2], al[1][3], stb + aoff + PL_A + 16 * 80 + koff);
            }
            ldm_x4(bf[0][0], bf[0][1], bf[1][0], bf[1][1], stb + boff + koff);
            ldm_x4(bf[2][0], bf[2][1], bf[3][0], bf[3][1], stb + boff + 16 * 80 + koff);
            #pragma unroll
            for (int ni = 0; ni < 4; ni++)
                #pragma unroll
                for (int mi = 0; mi < 2; mi++) {
                    mma_f16(acc[mi][ni], ah[mi], bf[ni]);
                    if (PROD == 2) mma_f16(acc[mi][ni], al[mi], bf[ni]);
                }
        }
    }

    #pragma unroll
    for (int ni = 0; ni < 4; ni++) {
        int cg = n0 + wn * 32 + ni * 8 + 2 * gc;
        float b0 = g.bias[cg], b1 = g.bias[cg + 1];
        #pragma unroll
        for (int mi = 0; mi < 2; mi++) {
            int r = m0 + wm * 32 + mi * 16 + gr;
            float v0 = acc[mi][ni][0] + b0;
            float v1 = acc[mi][ni][1] + b1;
            float v2 = acc[mi][ni][2] + b0;
            float v3 = acc[mi][ni][3] + b1;
            if (SILU) {
                v0 = v0 / (1.f + __expf(-v0));
                v1 = v1 / (1.f + __expf(-v1));
                v2 = v2 / (1.f + __expf(-v2));
                v3 = v3 / (1.f + __expf(-v3));
            }
            if (OMODE == 0) {
                float* C = (float*)g.C;
                *(float2*)(C + (size_t)r * CCH + cg)       = make_float2(v0, v1);
                *(float2*)(C + (size_t)(r + 8) * CCH + cg) = make_float2(v2, v3);
            } else if (OMODE == 1) {
                __half* C = (__half*)g.C;
                *(uint32_t*)(C + (size_t)r * CCH + cg)       = pack2f16(v0, v1);
                *(uint32_t*)(C + (size_t)(r + 8) * CCH + cg) = pack2f16(v2, v3);
            } else {
                __half* C  = (__half*)g.C;
                __half* Cl = (__half*)g.Cl;
                uint32_t h, l;
                split2h(v0, v1, h, l);
                *(uint32_t*)(C  + (size_t)r * CCH + cg) = h;
                *(uint32_t*)(Cl + (size_t)r * CCH + cg) = l;
                split2h(v2, v3, h, l);
                *(uint32_t*)(C  + (size_t)(r + 8) * CCH + cg) = h;
                *(uint32_t*)(Cl + (size_t)(r + 8) * CCH + cg) = l;
            }
        }
    }
}

// ---------------- depthwise conv k=3 (fp16 single; q,k) --------------------------
__global__ void dwconv_h_k(const __half2* i0, const __half2* i1,
                           const float* w0, const float* w1,
                           const float* bq, const float* bk,
                           __half2* o0, __half2* o1)
{
    const __half2* in = blockIdx.y ? i1 : i0;
    const float* w    = blockIdx.y ? w1 : w0;
    const float* bb   = blockIdx.y ? bk : bq;
    __half2* out      = blockIdx.y ? o1 : o0;
    int i2 = blockIdx.x * 256 + threadIdx.x;     // < 2M
    int c2 = i2 & 511, m = i2 >> 9, s = m & (SEQ - 1);
    int c0 = c2 * 2;
    float wa0 = w[c0*3], wa1 = w[c0*3+1], wa2 = w[c0*3+2];
    float wb0 = w[c0*3+3], wb1 = w[c0*3+4], wb2 = w[c0*3+5];
    float2 x  = __half22float2(in[i2]);
    float2 xm = make_float2(0.f, 0.f), xp = make_float2(0.f, 0.f);
    if (s > 0)       xm = __half22float2(in[i2 - 512]);
    if (s < SEQ - 1) xp = __half22float2(in[i2 + 512]);
    float va = xm.x*wa0 + x.x*wa1 + xp.x*wa2 + bb[c0];
    float vb = xm.y*wb0 + x.y*wb1 + xp.y*wb2 + bb[c0+1];
    out[i2] = __floats2half2_rn(va, vb);
}

// ---------------- depthwise conv k=3 (fp16 hi/lo; v) -----------------------------
__global__ void dwconv_hl_k(const __half2* ih, const __half2* il,
                            const float* w, const float* bb,
                            uint32_t* oh, uint32_t* ol)
{
    int i2 = blockIdx.x * 256 + threadIdx.x;
    int c2 = i2 & 511, m = i2 >> 9, s = m & (SEQ - 1);
    int c0 = c2 * 2;
    float wa0 = w[c0*3], wa1 = w[c0*3+1], wa2 = w[c0*3+2];
    float wb0 = w[c0*3+3], wb1 = w[c0*3+4], wb2 = w[c0*3+5];
    float2 xh = __half22float2(ih[i2]), xl = __half22float2(il[i2]);
    float2 x  = make_float2(xh.x + xl.x, xh.y + xl.y);
    float2 xm = make_float2(0.f, 0.f), xp = make_float2(0.f, 0.f);
    if (s > 0) {
        float2 a = __half22float2(ih[i2 - 512]), b = __half22float2(il[i2 - 512]);
        xm = make_float2(a.x + b.x, a.y + b.y);
    }
    if (s < SEQ - 1) {
        float2 a = __half22float2(ih[i2 + 512]), b = __half22float2(il[i2 + 512]);
        xp = make_float2(a.x + b.x, a.y + b.y);
    }
    float va = xm.x*wa0 + x.x*wa1 + xp.x*wa2 + bb[c0];
    float vb = xm.y*wb0 + x.y*wb1 + xp.y*wb2 + bb[c0+1];
    uint32_t h, l;
    split2h(va, vb, h, l);
    oh[i2] = h; ol[i2] = l;
}

// ---------------- per-head L2 normalize (fp16 in/out; q gets 0.125 folded) -------
__global__ void l2norm_f16_k(const __half2* q, const __half2* k, __half2* qn, __half2* kn)
{
    const __half2* src = blockIdx.y ? k : q;
    __half2* dst = blockIdx.y ? kn : qn;
    float sc = blockIdx.y ? 1.0f : 0.125f;
    int warp = threadIdx.x >> 5, lane = threadIdx.x & 31;
    size_t g = (size_t)blockIdx.x * 8 + warp;
    float2 x = __half22float2(src[g * 32 + lane]);
    float ss = x.x * x.x + x.y * x.y;
    #pragma unroll
    for (int o = 16; o; o >>= 1) ss += __shfl_xor_sync(0xffffffffu, ss, o);
    float inv = sc / fmaxf(sqrtf(ss), 1e-12f);
    dst[g * 32 + lane] = __floats2half2_rn(x.x * inv, x.y * inv);
}

// ---------------- V transpose fp16 [b][ch][s] ------------------------------------
__global__ void vtrans_k(const __half* v, __half* vt)
{
    __shared__ float t[32][33];
    int b = blockIdx.z;
    int s0 = blockIdx.y * 32, c0 = blockIdx.x * 32;
    int tx = threadIdx.x, ty = threadIdx.y;   // 32x8
    #pragma unroll
    for (int j = 0; j < 4; j++)
        t[ty + 8 * j][tx] = __half2float(v[(size_t)(b * SEQ + s0 + ty + 8 * j) * CCH + c0 + tx]);
    __syncthreads();
    #pragma unroll
    for (int j = 0; j < 4; j++)
        vt[(size_t)(b * CCH + c0 + ty + 8 * j) * SEQ + s0 + tx] = __float2half(t[tx][ty + 8 * j]);
}

// ================= flash attention: cp.async + ldmatrix fp16 pipeline ============
#define AT_STW 4608
#define AT_NST 3
#define AT_SMEM (AT_NST*AT_STW*4)    // 55296 B

__global__ void __launch_bounds__(256) attn_mma_k(const __half* __restrict__ Qh,
                                                  const __half* __restrict__ Kh,
                                                  const __half* __restrict__ Vt,
                                                  const int* __restrict__ mask,
                                                  __half* __restrict__ AOh,
                                                  __half* __restrict__ AOl)
{
    const int qt = blockIdx.x, h = blockIdx.y, bb = blockIdx.z;
    extern __shared__ uint32_t asw[];
    __shared__ int s_mask[AT_NST][64];

    const int tid = threadIdx.x, lane = tid & 31, w = tid >> 5;
    const int gr = lane >> 2, gc = lane & 3;
    const uint32_t sbase = smem_u32(asw);

    const __half* kb = Kh + ((size_t)bb * SEQ) * CCH + h * HDD;
    const __half* vb = Vt + ((size_t)(bb * NHH + h)) * HDD * SEQ;

    const uint32_t ldmoff =
        (uint32_t)(((lane >> 4) << 3) + (lane & 7)) * 144 + (((lane >> 3) & 1) << 4);

    auto issue = [&](int jt) {
        int slot = jt % AT_NST;
        uint32_t kdst = sbase + slot * AT_STW * 4;
        uint32_t vdst = kdst + 2304 * 4;
        #pragma unroll
        for (int j = 0; j < 2; j++) {
            int c = tid + 256 * j;
            int row = c >> 3, ch = c & 7;
            uint32_t d = kdst + (row * 36 + ch * 4) * 4;
            const __half* s = kb + (size_t)(jt * 64 + row) * CCH + ch * 8;
            asm volatile("cp.async.cg.shared.global [%0], [%1], 16;" :: "r"(d), "l"(s));
        }
        #pragma unroll
        for (int j = 0; j < 2; j++) {
            int c = tid + 256 * j;
            int row = c >> 3, ch = c & 7;
            uint32_t d = vdst + (row * 36 + ch * 4) * 4;
            const __half* s = vb + (size_t)row * SEQ + jt * 64 + ch * 8;
            asm volatile("cp.async.cg.shared.global [%0], [%1], 16;" :: "r"(d), "l"(s));
        }
        if (tid < 16) {
            uint32_t d = smem_u32(&s_mask[slot][0]) + tid * 16;
            const int* s = mask + bb * SEQ + jt * 64 + tid * 4;
            asm volatile("cp.async.cg.shared.global [%0], [%1], 16;" :: "r"(d), "l"(s));
        }
        asm volatile("cp.async.commit_group;");
    };

    issue(0);
    issue(1);

    uint32_t qa[4][4];
    {
        const __half* qb = Qh + ((size_t)(bb * SEQ + qt * 128)) * CCH + h * HDD;
        int r0 = w * 16 + gr, r1 = r0 + 8;
        #pragma unroll
        for (int ks = 0; ks < 4; ks++) {
            int c = ks * 16 + 2 * gc;
            qa[ks][0] = *(const uint32_t*)(qb + (size_t)r0 * CCH + c);
            qa[ks][1] = *(const uint32_t*)(qb + (size_t)r1 * CCH + c);
            qa[ks][2] = *(const uint32_t*)(qb + (size_t)r0 * CCH + c + 8);
            qa[ks][3] = *(const uint32_t*)(qb + (size_t)r1 * CCH + c + 8);
        }
    }

    float o[8][4];
    #pragma unroll
    for (int ht = 0; ht < 8; ht++)
        #pragma unroll
        for (int e = 0; e < 4; e++) o[ht][e] = 0.f;
    float l0 = 0.f, l1 = 0.f;

    #pragma unroll 1
    for (int jt = 0; jt < 32; jt++) {
        const int slot = jt % AT_NST;
        if (jt < 31) asm volatile("cp.async.wait_group 1;");
        else         asm volatile("cp.async.wait_group 0;");
        __syncthreads();
        if (jt + 2 < 32) issue(jt + 2);

        uint32_t kaddr = sbase + slot * AT_STW * 4 + ldmoff;
        uint32_t vaddr = kaddr + 2304 * 4;

        float s[8][4];
        #pragma unroll
        for (int nt = 0; nt < 8; nt++)
            #pragma unroll
            for (int e = 0; e < 4; e++) s[nt][e] = 0.f;
        #pragma unroll
        for (int ks = 0; ks < 4; ks++) {
            uint32_t bf[8][2];
            #pragma unroll
            for (int p = 0; p < 4; p++)
                ldm_x4(bf[2 * p][0], bf[2 * p][1], bf[2 * p + 1][0], bf[2 * p + 1][1],
                       kaddr + p * (16 * 144) + ks * 32);
            #pragma unroll
            for (int nt = 0; nt < 8; nt++)
                mma_f16_b(s[nt], qa[ks], bf[nt][0], bf[nt][1]);
        }

        #pragma unroll
        for (int nt = 0; nt < 8; nt++) {
            int c0 = nt * 8 + 2 * gc;
            bool ok0 = s_mask[slot][c0] != 0;
            bool ok1 = s_mask[slot][c0 + 1] != 0;
            s[nt][0] = ok0 ? exp_small(s[nt][0]) : 0.f;
            s[nt][1] = ok1 ? exp_small(s[nt][1]) : 0.f;
            s[nt][2] = ok0 ? exp_small(s[nt][2]) : 0.f;
            s[nt][3] = ok1 ? exp_small(s[nt][3]) : 0.f;
            l0 += s[nt][0] + s[nt][1];
            l1 += s[nt][2] + s[nt][3];
        }

        #pragma unroll
        for (int ks = 0; ks < 4; ks++) {
            uint32_t aF[4];
            aF[0] = pack2f16(s[2 * ks][0],     s[2 * ks][1]);
            aF[1] = pack2f16(s[2 * ks][2],     s[2 * ks][3]);
            aF[2] = pack2f16(s[2 * ks + 1][0], s[2 * ks + 1][1]);
            aF[3] = pack2f16(s[2 * ks + 1][2], s[2 * ks + 1][3]);
            uint32_t vf[8][2];
            #pragma unroll
            for (int p = 0; p < 4; p++)
                ldm_x4(vf[2 * p][0], vf[2 * p][1], vf[2 * p + 1][0], vf[2 * p + 1][1],
                       vaddr + p * (16 * 144) + ks * 32);
            #pragma unroll
            for (int ht = 0; ht < 8; ht++)
                mma_f16_b(o[ht], aF, vf[ht][0], vf[ht][1]);
        }
    }

    l0 += __shfl_xor_sync(0xffffffffu, l0, 1);
    l0 += __shfl_xor_sync(0xffffffffu, l0, 2);
    l1 += __shfl_xor_sync(0xffffffffu, l1, 1);
    l1 += __shfl_xor_sync(0xffffffffu, l1, 2);
    {
        float inv0 = 1.f / l0, inv1 = 1.f / l1;
        int r0 = w * 16 + gr, r1 = r0 + 8;
        size_t base = ((size_t)(bb * SEQ + qt * 128)) * CCH + h * HDD;
        __half* Oh = AOh + base;
        __half* Ol = AOl + base;
        #pragma unroll
        for (int ht = 0; ht < 8; ht++) {
            int c = ht * 8 + 2 * gc;
            uint32_t hh, ll;
            split2h(o[ht][0] * inv0, o[ht][1] * inv0, hh, ll);
            *(uint32_t*)(Oh + (size_t)r0 * CCH + c) = hh;
            *(uint32_t*)(Ol + (size_t)r0 * CCH + c) = ll;
            split2h(o[ht][2] * inv1, o[ht][3] * inv1, hh, ll);
            *(uint32_t*)(Oh + (size_t)r1 * CCH + c) = hh;
            *(uint32_t*)(Ol + (size_t)r1 * CCH + c) = ll;
        }
    }
}

// ---------------- host launcher ---------------------------------------------------
extern "C" void kernel_launch(void* const* d_in, const int* in_sizes, int n_in,
                              void* d_out, int out_size)
{
    const float* x    = (const float*)d_in[0];
    const int*   mask = (const int*)d_in[1];
    const float* wq   = (const float*)d_in[2];
    const float* bq   = (const float*)d_in[3];
    const float* wk   = (const float*)d_in[4];
    const float* bk   = (const float*)d_in[5];
    const float* wv   = (const float*)d_in[6];
    const float* bv   = (const float*)d_in[7];
    const float* qdww = (const float*)d_in[8];
    const float* qdwb = (const float*)d_in[9];
    const float* qpww = (const float*)d_in[10];
    const float* qpwb = (const float*)d_in[11];
    const float* kdww = (const float*)d_in[12];
    const float* kdwb = (const float*)d_in[13];
    const float* kpww = (const float*)d_in[14];
    const float* kpwb = (const float*)d_in[15];
    const float* vdww = (const float*)d_in[16];
    const float* vdwb = (const float*)d_in[17];
    const float* vpww = (const float*)d_in[18];
    const float* vpwb = (const float*)d_in[19];
    const float* wo   = (const float*)d_in[20];
    const float* bo   = (const float*)d_in[21];
    float* out = (float*)d_out;

    __half *xh, *xlo, *w16, *q16, *k16, *vhi, *vlo, *qc16, *kc16, *vchi, *vclo;
    __half *qpw, *kpw, *vpw, *qn, *kn, *vt, *aoh, *aol;
    cudaGetSymbolAddress((void**)&xh,  g_xh);
    cudaGetSymbolAddress((void**)&xlo, g_xlo);
    cudaGetSymbolAddress((void**)&w16, g_w16);
    cudaGetSymbolAddress((void**)&q16, g_q16);
    cudaGetSymbolAddress((void**)&k16, g_k16);
    cudaGetSymbolAddress((void**)&vhi, g_vhi);
    cudaGetSymbolAddress((void**)&vlo, g_vlo);
    cudaGetSymbolAddress((void**)&qc16, g_qc16);
    cudaGetSymbolAddress((void**)&kc16, g_kc16);
    cudaGetSymbolAddress((void**)&vchi, g_vchi);
    cudaGetSymbolAddress((void**)&vclo, g_vclo);
    cudaGetSymbolAddress((void**)&qpw, g_qpw);
    cudaGetSymbolAddress((void**)&kpw, g_kpw);
    cudaGetSymbolAddress((void**)&vpw, g_vpw);
    cudaGetSymbolAddress((void**)&qn,  g_qn);
    cudaGetSymbolAddress((void**)&kn,  g_kn);
    cudaGetSymbolAddress((void**)&vt,  g_vt);
    cudaGetSymbolAddress((void**)&aoh, g_aoh);
    cudaGetSymbolAddress((void**)&aol, g_aol);

    __half* wqh  = w16 + 0 * (size_t)DIMM * CCH;
    __half* wkh  = w16 + 1 * (size_t)DIMM * CCH;
    __half* wvh  = w16 + 2 * (size_t)DIMM * CCH;
    __half* qpwh = w16 + 3 * (size_t)DIMM * CCH;
    __half* kpwh = w16 + 4 * (size_t)DIMM * CCH;
    __half* vpwh = w16 + 5 * (size_t)DIMM * CCH;
    __half* woh  = w16 + 6 * (size_t)DIMM * CCH;

    const int SMP1 = 4 * (PL_A + PL_B);      // 61440
    const int SMP2 = 4 * (2 * PL_A + PL_B);  // 81920
    cudaFuncSetAttribute(gemm_h_k<true, 1, 1>,  cudaFuncAttributeMaxDynamicSharedMemorySize, SMP1);
    cudaFuncSetAttribute(gemm_h_k<true, 2, 2>,  cudaFuncAttributeMaxDynamicSharedMemorySize, SMP2);
    cudaFuncSetAttribute(gemm_h_k<false, 1, 1>, cudaFuncAttributeMaxDynamicSharedMemorySize, SMP1);
    cudaFuncSetAttribute(gemm_h_k<false, 2, 1>, cudaFuncAttributeMaxDynamicSharedMemorySize, SMP2);
    cudaFuncSetAttribute(gemm_h_k<false, 2, 0>, cudaFuncAttributeMaxDynamicSharedMemorySize, SMP2);
    cudaFuncSetAttribute(attn_mma_k, cudaFuncAttributeMaxDynamicSharedMemorySize, AT_SMEM);

    // 0) prep: weights + x to fp16
    WC wc;
    wc.s[0] = wq;  wc.d[0] = wqh;
    wc.s[1] = wk;  wc.d[1] = wkh;
    wc.s[2] = wv;  wc.d[2] = wvh;
    wc.s[3] = qpww; wc.d[3] = qpwh;
    wc.s[4] = kpww; wc.d[4] = kpwh;
    wc.s[5] = vpww; wc.d[5] = vpwh;
    wc.s[6] = wo;  wc.d[6] = woh;
    wconv_k<<<dim3(2048, 7), 256>>>(wc);
    xconv_k<<<8192, 256>>>((const float2*)x, (uint32_t*)xh, (uint32_t*)xlo);

    dim3 grid_qk(8, 64, 2), grid_1(8, 64, 1);

    // 1) QKV projection + SiLU
    gemm_h_k<true, 1, 1><<<grid_qk, 256, SMP1>>>(
        GH{xh, 0, wqh, bq, q16, 0}, GH{xh, 0, wkh, bk, k16, 0}, GH{xh, 0, wkh, bk, k16, 0});
    gemm_h_k<true, 2, 2><<<grid_1, 256, SMP2>>>(
        GH{xh, xlo, wvh, bv, vhi, vlo}, GH{xh, xlo, wvh, bv, vhi, vlo}, GH{xh, xlo, wvh, bv, vhi, vlo});

    // 2) depthwise conv
    dwconv_h_k<<<dim3(8192, 2), 256>>>((const __half2*)q16, (const __half2*)k16,
                                       qdww, kdww, qdwb, kdwb,
                                       (__half2*)qc16, (__half2*)kc16);
    dwconv_hl_k<<<8192, 256>>>((const __half2*)vhi, (const __half2*)vlo,
                               vdww, vdwb, (uint32_t*)vchi, (uint32_t*)vclo);

    // 3) pointwise conv
    gemm_h_k<false, 1, 1><<<grid_qk, 256, SMP1>>>(
        GH{qc16, 0, qpwh, qpwb, qpw, 0}, GH{kc16, 0, kpwh, kpwb, kpw, 0}, GH{kc16, 0, kpwh, kpwb, kpw, 0});
    gemm_h_k<false, 2, 1><<<grid_1, 256, SMP2>>>(
        GH{vchi, vclo, vpwh, vpwb, vpw, 0}, GH{vchi, vclo, vpwh, vpwb, vpw, 0}, GH{vchi, vclo, vpwh, vpwb, vpw, 0});

    // 4) l2norm (q scaled by 0.125) + v transpose
    l2norm_f16_k<<<dim3((MROWS * NHH) / 8, 2), 256>>>((const __half2*)qpw, (const __half2*)kpw,
                                                      (__half2*)qn, (__half2*)kn);
    vtrans_k<<<dim3(32, 64, 2), dim3(32, 8)>>>(vpw, vt);

    // 5) flash attention -> fp16 hi/lo
    attn_mma_k<<<dim3(SEQ / 128, NHH, BSZ), 256, AT_SMEM>>>(qn, kn, vt, mask, aoh, aol);

    // 6) output projection -> d_out (fp32)
    gemm_h_k<false, 2, 0><<<grid_1, 256, SMP2>>>(
        GH{aoh, aol, woh, bo, out, 0}, GH{aoh, aol, woh, bo, out, 0}, GH{aoh, aol, woh, bo, out, 0});
}

// round 10
// speedup vs baseline: 4.7421x; 1.0417x over previous
#include <cuda_runtime.h>
#include <cuda_fp16.h>
#include <stdint.h>

#define BSZ 2
#define SEQ 2048
#define DIMM 1024
#define CCH 1024
#define NHH 16
#define HDD 64
#define MROWS (BSZ*SEQ)   // 4096

// ---------------- fp16 scratch (device globals) ----------------------------------
__device__ __half g_xh [MROWS*DIMM];
__device__ __half g_xlo[MROWS*DIMM];
__device__ __half g_w16[7][DIMM*CCH];          // wq,wk,wv,qpw,kpw,vpw,wo
__device__ __half g_q16[MROWS*CCH],  g_k16[MROWS*CCH];
__device__ __half g_vhi[MROWS*CCH],  g_vlo[MROWS*CCH];
__device__ __half g_qc16[MROWS*CCH], g_kc16[MROWS*CCH];
__device__ __half g_vchi[MROWS*CCH], g_vclo[MROWS*CCH];
__device__ __half g_qpw[MROWS*CCH],  g_kpw[MROWS*CCH], g_vpw[MROWS*CCH];
__device__ __half g_qn[MROWS*CCH],   g_kn[MROWS*CCH],  g_vt[MROWS*CCH];
__device__ __half g_aoh[MROWS*CCH],  g_aol[MROWS*CCH];

// ================= helpers =======================================================
__device__ __forceinline__ uint32_t smem_u32(const void* p) {
    uint32_t a;
    asm("{ .reg .u64 t; cvta.to.shared.u64 t, %1; cvt.u32.u64 %0, t; }" : "=r"(a) : "l"(p));
    return a;
}
__device__ __forceinline__ uint32_t pack2f16(float x, float y) {
    __half2 t = __floats2half2_rn(x, y);
    return *reinterpret_cast<uint32_t*>(&t);
}
__device__ __forceinline__ void split2h(float x, float y, uint32_t& h, uint32_t& l) {
    __half hx = __float2half_rn(x);
    __half hy = __float2half_rn(y);
    __half2 hp = __halves2half2(hx, hy);
    h = *reinterpret_cast<uint32_t*>(&hp);
    l = pack2f16(x - __half2float(hx), y - __half2float(hy));
}
__device__ __forceinline__ void mma_f16(float* d, const uint32_t* a, const uint32_t* b) {
    asm volatile(
        "mma.sync.aligned.m16n8k16.row.col.f32.f16.f16.f32 "
        "{%0,%1,%2,%3}, {%4,%5,%6,%7}, {%8,%9}, {%0,%1,%2,%3};"
        : "+f"(d[0]), "+f"(d[1]), "+f"(d[2]), "+f"(d[3])
        : "r"(a[0]), "r"(a[1]), "r"(a[2]), "r"(a[3]), "r"(b[0]), "r"(b[1]));
}
__device__ __forceinline__ void mma_f16_b(float* d, const uint32_t* a, uint32_t b0, uint32_t b1) {
    asm volatile(
        "mma.sync.aligned.m16n8k16.row.col.f32.f16.f16.f32 "
        "{%0,%1,%2,%3}, {%4,%5,%6,%7}, {%8,%9}, {%0,%1,%2,%3};"
        : "+f"(d[0]), "+f"(d[1]), "+f"(d[2]), "+f"(d[3])
        : "r"(a[0]), "r"(a[1]), "r"(a[2]), "r"(a[3]), "r"(b0), "r"(b1));
}
__device__ __forceinline__ void ldm_x4(uint32_t& r0, uint32_t& r1, uint32_t& r2, uint32_t& r3,
                                       uint32_t addr) {
    asm volatile("ldmatrix.sync.aligned.m8n8.x4.shared.b16 {%0,%1,%2,%3}, [%4];"
                 : "=r"(r0), "=r"(r1), "=r"(r2), "=r"(r3) : "r"(addr));
}
__device__ __forceinline__ float exp_small(float x) {   // |x| <= 0.125, rel err ~3e-8
    return 1.f + x * (1.f + x * (0.5f + x * (0.166666667f + x * 0.0416666667f)));
}

// ================= prep kernels ==================================================
struct WC { const float* s[7]; __half* d[7]; };
__global__ void wconv_k(WC wc)
{
    const float2* s = (const float2*)wc.s[blockIdx.y];
    __half2* d = (__half2*)wc.d[blockIdx.y];
    int i = blockIdx.x * 256 + threadIdx.x;    // < 512K
    float2 v = s[i];
    d[i] = __floats2half2_rn(v.x, v.y);
}
__global__ void xconv_k(const float2* x, uint32_t* xh, uint32_t* xl)
{
    int i = blockIdx.x * 256 + threadIdx.x;    // < 2M
    float2 v = x[i];
    uint32_t h, l;
    split2h(v.x, v.y, h, l);
    xh[i] = h; xl[i] = l;
}

// ================= fp16 GEMM: cp.async + ldmatrix + mma ==========================
// C[m,n] = sum_k A[m,k]*W[n,k] + bias[n]; M=4096, N=K=1024. fp16 inputs.
// PROD=2: A has hi+lo planes. OMODE: 0=f32 out, 1=f16 out, 2=f16 hi/lo out.
// CTA 64x128, KC=32, 256 threads (8 warps, 2x4), warp tile 32x32, 3-stage cp.async,
// 3 CTAs/SM (reg cap 85).
struct GH { const __half* A; const __half* Al; const __half* W; const float* bias;
            void* C; void* Cl; };

#define PL_A 5120                    // A plane: 64 rows x 80B
#define PL_B 10240                   // B plane: 128 rows x 80B

template<bool SILU, int PROD, int OMODE>
__global__ void __launch_bounds__(256, 3)
gemm_h_k(GH g0, GH g1, GH g2)
{
    constexpr int NST = 3;
    constexpr int STB = PROD * PL_A + PL_B;     // stage bytes
    GH g = (blockIdx.z == 0) ? g0 : ((blockIdx.z == 1) ? g1 : g2);
    extern __shared__ uint32_t smw[];
    const uint32_t sb = smem_u32(smw);

    const int tid = threadIdx.x, lane = tid & 31, wid = tid >> 5;
    const int wm = wid & 1, wn = wid >> 1;       // 2x4 warp grid
    const int gr = lane >> 2, gc = lane & 3;
    const int m0 = blockIdx.y * 64, n0 = blockIdx.x * 128;

    const int rr = tid >> 2, ch = tid & 3;       // cp.async geometry (64 rows x 4 chunks)
    const __half* pa  = g.A + (size_t)(m0 + rr) * DIMM + ch * 8;
    const __half* pl  = (PROD == 2) ? (g.Al + (size_t)(m0 + rr) * DIMM + ch * 8) : (const __half*)0;
    const __half* pw0 = g.W + (size_t)(n0 + rr) * DIMM + ch * 8;
    const __half* pw1 = g.W + (size_t)(n0 + rr + 64) * DIMM + ch * 8;
    const uint32_t dA  = sb + rr * 80 + ch * 16;
    const uint32_t dB0 = sb + PROD * PL_A + rr * 80 + ch * 16;
    const uint32_t dB1 = dB0 + 64 * 80;

    const uint32_t aoff = (uint32_t)(wm * 32 + (lane & 15)) * 80 + ((lane >> 4) << 4);
    const uint32_t boff = PROD * PL_A +
        (uint32_t)(wn * 32 + ((lane >> 4) << 3) + (lane & 7)) * 80 + (((lane >> 3) & 1) << 4);

    auto issue = [&](int i) {
        int kk = i * 32;
        uint32_t st = (i % NST) * STB;
        asm volatile("cp.async.cg.shared.global [%0], [%1], 16;" :: "r"(dA + st), "l"(pa + kk));
        if (PROD == 2)
            asm volatile("cp.async.cg.shared.global [%0], [%1], 16;" :: "r"(dA + PL_A + st), "l"(pl + kk));
        asm volatile("cp.async.cg.shared.global [%0], [%1], 16;" :: "r"(dB0 + st), "l"(pw0 + kk));
        asm volatile("cp.async.cg.shared.global [%0], [%1], 16;" :: "r"(dB1 + st), "l"(pw1 + kk));
        asm volatile("cp.async.commit_group;");
    };

    float acc[2][4][4];
    #pragma unroll
    for (int mi = 0; mi < 2; mi++)
        #pragma unroll
        for (int ni = 0; ni < 4; ni++)
            #pragma unroll
            for (int e = 0; e < 4; e++) acc[mi][ni][e] = 0.f;

    #pragma unroll
    for (int s = 0; s < NST - 1; s++) issue(s);

    #pragma unroll 1
    for (int i = 0; i < 32; i++) {
        if (31 - i >= NST - 2)      asm volatile("cp.async.wait_group %0;" :: "n"(NST - 2));
        else                        asm volatile("cp.async.wait_group 0;");
        __syncthreads();
        if (i + NST - 1 < 32) issue(i + NST - 1);

        uint32_t stb = sb + (i % NST) * STB;
        #pragma unroll
        for (int ki = 0; ki < 2; ki++) {
            uint32_t koff = ki * 32;
            uint32_t ah[2][4], al[2][4], bf[4][2];
            ldm_x4(ah[0][0], ah[0][1], ah[0][2], ah[0][3], stb + aoff + koff);
            ldm_x4(ah[1][0], ah[1][1], ah[1][2], ah[1][3], stb + aoff + 16 * 80 + koff);
            if (PROD == 2) {
                ldm_x4(al[0][0], al[0][1], al[0][2], al[0][3], stb + aoff + PL_A + koff);
                ldm_x4(al[1][0], al[1][1], al[1][2], al[1][3], stb + aoff + PL_A + 16 * 80 + koff);
            }
            ldm_x4(bf[0][0], bf[0][1], bf[1][0], bf[1][1], stb + boff + koff);
            ldm_x4(bf[2][0], bf[2][1], bf[3][0], bf[3][1], stb + boff + 16 * 80 + koff);
            #pragma unroll
            for (int ni = 0; ni < 4; ni++)
                #pragma unroll
                for (int mi = 0; mi < 2; mi++) {
                    mma_f16(acc[mi][ni], ah[mi], bf[ni]);
                    if (PROD == 2) mma_f16(acc[mi][ni], al[mi], bf[ni]);
                }
        }
    }

    #pragma unroll
    for (int ni = 0; ni < 4; ni++) {
        int cg = n0 + wn * 32 + ni * 8 + 2 * gc;
        float b0 = g.bias[cg], b1 = g.bias[cg + 1];
        #pragma unroll
        for (int mi = 0; mi < 2; mi++) {
            int r = m0 + wm * 32 + mi * 16 + gr;
            float v0 = acc[mi][ni][0] + b0;
            float v1 = acc[mi][ni][1] + b1;
            float v2 = acc[mi][ni][2] + b0;
            float v3 = acc[mi][ni][3] + b1;
            if (SILU) {
                v0 = v0 / (1.f + __expf(-v0));
                v1 = v1 / (1.f + __expf(-v1));
                v2 = v2 / (1.f + __expf(-v2));
                v3 = v3 / (1.f + __expf(-v3));
            }
            if (OMODE == 0) {
                float* C = (float*)g.C;
                *(float2*)(C + (size_t)r * CCH + cg)       = make_float2(v0, v1);
                *(float2*)(C + (size_t)(r + 8) * CCH + cg) = make_float2(v2, v3);
            } else if (OMODE == 1) {
                __half* C = (__half*)g.C;
                *(uint32_t*)(C + (size_t)r * CCH + cg)       = pack2f16(v0, v1);
                *(uint32_t*)(C + (size_t)(r + 8) * CCH + cg) = pack2f16(v2, v3);
            } else {
                __half* C  = (__half*)g.C;
                __half* Cl = (__half*)g.Cl;
                uint32_t h, l;
                split2h(v0, v1, h, l);
                *(uint32_t*)(C  + (size_t)r * CCH + cg) = h;
                *(uint32_t*)(Cl + (size_t)r * CCH + cg) = l;
                split2h(v2, v3, h, l);
                *(uint32_t*)(C  + (size_t)(r + 8) * CCH + cg) = h;
                *(uint32_t*)(Cl + (size_t)(r + 8) * CCH + cg) = l;
            }
        }
    }
}

// ---------------- depthwise conv k=3 (fp16 single; q,k) --------------------------
__global__ void dwconv_h_k(const __half2* i0, const __half2* i1,
                           const float* w0, const float* w1,
                           const float* bq, const float* bk,
                           __half2* o0, __half2* o1)
{
    const __half2* in = blockIdx.y ? i1 : i0;
    const float* w    = blockIdx.y ? w1 : w0;
    const float* bb   = blockIdx.y ? bk : bq;
    __half2* out      = blockIdx.y ? o1 : o0;
    int i2 = blockIdx.x * 256 + threadIdx.x;     // < 2M
    int c2 = i2 & 511, m = i2 >> 9, s = m & (SEQ - 1);
    int c0 = c2 * 2;
    float wa0 = w[c0*3], wa1 = w[c0*3+1], wa2 = w[c0*3+2];
    float wb0 = w[c0*3+3], wb1 = w[c0*3+4], wb2 = w[c0*3+5];
    float2 x  = __half22float2(in[i2]);
    float2 xm = make_float2(0.f, 0.f), xp = make_float2(0.f, 0.f);
    if (s > 0)       xm = __half22float2(in[i2 - 512]);
    if (s < SEQ - 1) xp = __half22float2(in[i2 + 512]);
    float va = xm.x*wa0 + x.x*wa1 + xp.x*wa2 + bb[c0];
    float vb = xm.y*wb0 + x.y*wb1 + xp.y*wb2 + bb[c0+1];
    out[i2] = __floats2half2_rn(va, vb);
}

// ---------------- depthwise conv k=3 (fp16 hi/lo; v) -----------------------------
__global__ void dwconv_hl_k(const __half2* ih, const __half2* il,
                            const float* w, const float* bb,
                            uint32_t* oh, uint32_t* ol)
{
    int i2 = blockIdx.x * 256 + threadIdx.x;
    int c2 = i2 & 511, m = i2 >> 9, s = m & (SEQ - 1);
    int c0 = c2 * 2;
    float wa0 = w[c0*3], wa1 = w[c0*3+1], wa2 = w[c0*3+2];
    float wb0 = w[c0*3+3], wb1 = w[c0*3+4], wb2 = w[c0*3+5];
    float2 xh = __half22float2(ih[i2]), xl = __half22float2(il[i2]);
    float2 x  = make_float2(xh.x + xl.x, xh.y + xl.y);
    float2 xm = make_float2(0.f, 0.f), xp = make_float2(0.f, 0.f);
    if (s > 0) {
        float2 a = __half22float2(ih[i2 - 512]), b = __half22float2(il[i2 - 512]);
        xm = make_float2(a.x + b.x, a.y + b.y);
    }
    if (s < SEQ - 1) {
        float2 a = __half22float2(ih[i2 + 512]), b = __half22float2(il[i2 + 512]);
        xp = make_float2(a.x + b.x, a.y + b.y);
    }
    float va = xm.x*wa0 + x.x*wa1 + xp.x*wa2 + bb[c0];
    float vb = xm.y*wb0 + x.y*wb1 + xp.y*wb2 + bb[c0+1];
    uint32_t h, l;
    split2h(va, vb, h, l);
    oh[i2] = h; ol[i2] = l;
}

// ---------------- per-head L2 normalize (fp16 in/out; q gets 0.125 folded) -------
__global__ void l2norm_f16_k(const __half2* q, const __half2* k, __half2* qn, __half2* kn)
{
    const __half2* src = blockIdx.y ? k : q;
    __half2* dst = blockIdx.y ? kn : qn;
    float sc = blockIdx.y ? 1.0f : 0.125f;
    int warp = threadIdx.x >> 5, lane = threadIdx.x & 31;
    size_t g = (size_t)blockIdx.x * 8 + warp;
    float2 x = __half22float2(src[g * 32 + lane]);
    float ss = x.x * x.x + x.y * x.y;
    #pragma unroll
    for (int o = 16; o; o >>= 1) ss += __shfl_xor_sync(0xffffffffu, ss, o);
    float inv = sc / fmaxf(sqrtf(ss), 1e-12f);
    dst[g * 32 + lane] = __floats2half2_rn(x.x * inv, x.y * inv);
}

// ---------------- V transpose fp16 [b][ch][s] ------------------------------------
__global__ void vtrans_k(const __half* v, __half* vt)
{
    __shared__ float t[32][33];
    int b = blockIdx.z;
    int s0 = blockIdx.y * 32, c0 = blockIdx.x * 32;
    int tx = threadIdx.x, ty = threadIdx.y;   // 32x8
    #pragma unroll
    for (int j = 0; j < 4; j++)
        t[ty + 8 * j][tx] = __half2float(v[(size_t)(b * SEQ + s0 + ty + 8 * j) * CCH + c0 + tx]);
    __syncthreads();
    #pragma unroll
    for (int j = 0; j < 4; j++)
        vt[(size_t)(b * CCH + c0 + ty + 8 * j) * SEQ + s0 + tx] = __float2half(t[tx][ty + 8 * j]);
}

// ================= flash attention: cp.async + ldmatrix fp16 pipeline ============
#define AT_STW 4608
#define AT_NST 3
#define AT_SMEM (AT_NST*AT_STW*4)    // 55296 B

__global__ void __launch_bounds__(256, 2) attn_mma_k(const __half* __restrict__ Qh,
                                                     const __half* __restrict__ Kh,
                                                     const __half* __restrict__ Vt,
                                                     const int* __restrict__ mask,
                                                     __half* __restrict__ AOh,
                                                     __half* __restrict__ AOl)
{
    const int qt = blockIdx.x, h = blockIdx.y, bb = blockIdx.z;
    extern __shared__ uint32_t asw[];
    __shared__ int s_mask[AT_NST][64];

    const int tid = threadIdx.x, lane = tid & 31, w = tid >> 5;
    const int gr = lane >> 2, gc = lane & 3;
    const uint32_t sbase = smem_u32(asw);

    const __half* kb = Kh + ((size_t)bb * SEQ) * CCH + h * HDD;
    const __half* vb = Vt + ((size_t)(bb * NHH + h)) * HDD * SEQ;

    const uint32_t ldmoff =
        (uint32_t)(((lane >> 4) << 3) + (lane & 7)) * 144 + (((lane >> 3) & 1) << 4);

    auto issue = [&](int jt) {
        int slot = jt % AT_NST;
        uint32_t kdst = sbase + slot * AT_STW * 4;
        uint32_t vdst = kdst + 2304 * 4;
        #pragma unroll
        for (int j = 0; j < 2; j++) {
            int c = tid + 256 * j;
            int row = c >> 3, ch = c & 7;
            uint32_t d = kdst + (row * 36 + ch * 4) * 4;
            const __half* s = kb + (size_t)(jt * 64 + row) * CCH + ch * 8;
            asm volatile("cp.async.cg.shared.global [%0], [%1], 16;" :: "r"(d), "l"(s));
        }
        #pragma unroll
        for (int j = 0; j < 2; j++) {
            int c = tid + 256 * j;
            int row = c >> 3, ch = c & 7;
            uint32_t d = vdst + (row * 36 + ch * 4) * 4;
            const __half* s = vb + (size_t)row * SEQ + jt * 64 + ch * 8;
            asm volatile("cp.async.cg.shared.global [%0], [%1], 16;" :: "r"(d), "l"(s));
        }
        if (tid < 16) {
            uint32_t d = smem_u32(&s_mask[slot][0]) + tid * 16;
            const int* s = mask + bb * SEQ + jt * 64 + tid * 4;
            asm volatile("cp.async.cg.shared.global [%0], [%1], 16;" :: "r"(d), "l"(s));
        }
        asm volatile("cp.async.commit_group;");
    };

    issue(0);
    issue(1);

    uint32_t qa[4][4];
    {
        const __half* qb = Qh + ((size_t)(bb * SEQ + qt * 128)) * CCH + h * HDD;
        int r0 = w * 16 + gr, r1 = r0 + 8;
        #pragma unroll
        for (int ks = 0; ks < 4; ks++) {
            int c = ks * 16 + 2 * gc;
            qa[ks][0] = *(const uint32_t*)(qb + (size_t)r0 * CCH + c);
            qa[ks][1] = *(const uint32_t*)(qb + (size_t)r1 * CCH + c);
            qa[ks][2] = *(const uint32_t*)(qb + (size_t)r0 * CCH + c + 8);
            qa[ks][3] = *(const uint32_t*)(qb + (size_t)r1 * CCH + c + 8);
        }
    }

    float o[8][4];
    #pragma unroll
    for (int ht = 0; ht < 8; ht++)
        #pragma unroll
        for (int e = 0; e < 4; e++) o[ht][e] = 0.f;
    float l0 = 0.f, l1 = 0.f;

    #pragma unroll 1
    for (int jt = 0; jt < 32; jt++) {
        const int slot = jt % AT_NST;
        if (jt < 31) asm volatile("cp.async.wait_group 1;");
        else         asm volatile("cp.async.wait_group 0;");
        __syncthreads();
        if (jt + 2 < 32) issue(jt + 2);

        uint32_t kaddr = sbase + slot * AT_STW * 4 + ldmoff;
        uint32_t vaddr = kaddr + 2304 * 4;

        float s[8][4];
        #pragma unroll
        for (int nt = 0; nt < 8; nt++)
            #pragma unroll
            for (int e = 0; e < 4; e++) s[nt][e] = 0.f;
        #pragma unroll
        for (int ks = 0; ks < 4; ks++) {
            uint32_t bf[8][2];
            #pragma unroll
            for (int p = 0; p < 4; p++)
                ldm_x4(bf[2 * p][0], bf[2 * p][1], bf[2 * p + 1][0], bf[2 * p + 1][1],
                       kaddr + p * (16 * 144) + ks * 32);
            #pragma unroll
            for (int nt = 0; nt < 8; nt++)
                mma_f16_b(s[nt], qa[ks], bf[nt][0], bf[nt][1]);
        }

        #pragma unroll
        for (int nt = 0; nt < 8; nt++) {
            int c0 = nt * 8 + 2 * gc;
            bool ok0 = s_mask[slot][c0] != 0;
            bool ok1 = s_mask[slot][c0 + 1] != 0;
            s[nt][0] = ok0 ? exp_small(s[nt][0]) : 0.f;
            s[nt][1] = ok1 ? exp_small(s[nt][1]) : 0.f;
            s[nt][2] = ok0 ? exp_small(s[nt][2]) : 0.f;
            s[nt][3] = ok1 ? exp_small(s[nt][3]) : 0.f;
            l0 += s[nt][0] + s[nt][1];
            l1 += s[nt][2] + s[nt][3];
        }

        #pragma unroll
        for (int ks = 0; ks < 4; ks++) {
            uint32_t aF[4];
            aF[0] = pack2f16(s[2 * ks][0],     s[2 * ks][1]);
            aF[1] = pack2f16(s[2 * ks][2],     s[2 * ks][3]);
            aF[2] = pack2f16(s[2 * ks + 1][0], s[2 * ks + 1][1]);
            aF[3] = pack2f16(s[2 * ks + 1][2], s[2 * ks + 1][3]);
            uint32_t vf[8][2];
            #pragma unroll
            for (int p = 0; p < 4; p++)
                ldm_x4(vf[2 * p][0], vf[2 * p][1], vf[2 * p + 1][0], vf[2 * p + 1][1],
                       vaddr + p * (16 * 144) + ks * 32);
            #pragma unroll
            for (int ht = 0; ht < 8; ht++)
                mma_f16_b(o[ht], aF, vf[ht][0], vf[ht][1]);
        }
    }

    l0 += __shfl_xor_sync(0xffffffffu, l0, 1);
    l0 += __shfl_xor_sync(0xffffffffu, l0, 2);
    l1 += __shfl_xor_sync(0xffffffffu, l1, 1);
    l1 += __shfl_xor_sync(0xffffffffu, l1, 2);
    {
        float inv0 = 1.f / l0, inv1 = 1.f / l1;
        int r0 = w * 16 + gr, r1 = r0 + 8;
        size_t base = ((size_t)(bb * SEQ + qt * 128)) * CCH + h * HDD;
        __half* Oh = AOh + base;
        __half* Ol = AOl + base;
        #pragma unroll
        for (int ht = 0; ht < 8; ht++) {
            int c = ht * 8 + 2 * gc;
            uint32_t hh, ll;
            split2h(o[ht][0] * inv0, o[ht][1] * inv0, hh, ll);
            *(uint32_t*)(Oh + (size_t)r0 * CCH + c) = hh;
            *(uint32_t*)(Ol + (size_t)r0 * CCH + c) = ll;
            split2h(o[ht][2] * inv1, o[ht][3] * inv1, hh, ll);
            *(uint32_t*)(Oh + (size_t)r1 * CCH + c) = hh;
            *(uint32_t*)(Ol + (size_t)r1 * CCH + c) = ll;
        }
    }
}

// ---------------- host launcher ---------------------------------------------------
extern "C" void kernel_launch(void* const* d_in, const int* in_sizes, int n_in,
                              void* d_out, int out_size)
{
    const float* x    = (const float*)d_in[0];
    const int*   mask = (const int*)d_in[1];
    const float* wq   = (const float*)d_in[2];
    const float* bq   = (const float*)d_in[3];
    const float* wk   = (const float*)d_in[4];
    const float* bk   = (const float*)d_in[5];
    const float* wv   = (const float*)d_in[6];
    const float* bv   = (const float*)d_in[7];
    const float* qdww = (const float*)d_in[8];
    const float* qdwb = (const float*)d_in[9];
    const float* qpww = (const float*)d_in[10];
    const float* qpwb = (const float*)d_in[11];
    const float* kdww = (const float*)d_in[12];
    const float* kdwb = (const float*)d_in[13];
    const float* kpww = (const float*)d_in[14];
    const float* kpwb = (const float*)d_in[15];
    const float* vdww = (const float*)d_in[16];
    const float* vdwb = (const float*)d_in[17];
    const float* vpww = (const float*)d_in[18];
    const float* vpwb = (const float*)d_in[19];
    const float* wo   = (const float*)d_in[20];
    const float* bo   = (const float*)d_in[21];
    float* out = (float*)d_out;

    __half *xh, *xlo, *w16, *q16, *k16, *vhi, *vlo, *qc16, *kc16, *vchi, *vclo;
    __half *qpw, *kpw, *vpw, *qn, *kn, *vt, *aoh, *aol;
    cudaGetSymbolAddress((void**)&xh,  g_xh);
    cudaGetSymbolAddress((void**)&xlo, g_xlo);
    cudaGetSymbolAddress((void**)&w16, g_w16);
    cudaGetSymbolAddress((void**)&q16, g_q16);
    cudaGetSymbolAddress((void**)&k16, g_k16);
    cudaGetSymbolAddress((void**)&vhi, g_vhi);
    cudaGetSymbolAddress((void**)&vlo, g_vlo);
    cudaGetSymbolAddress((void**)&qc16, g_qc16);
    cudaGetSymbolAddress((void**)&kc16, g_kc16);
    cudaGetSymbolAddress((void**)&vchi, g_vchi);
    cudaGetSymbolAddress((void**)&vclo, g_vclo);
    cudaGetSymbolAddress((void**)&qpw, g_qpw);
    cudaGetSymbolAddress((void**)&kpw, g_kpw);
    cudaGetSymbolAddress((void**)&vpw, g_vpw);
    cudaGetSymbolAddress((void**)&qn,  g_qn);
    cudaGetSymbolAddress((void**)&kn,  g_kn);
    cudaGetSymbolAddress((void**)&vt,  g_vt);
    cudaGetSymbolAddress((void**)&aoh, g_aoh);
    cudaGetSymbolAddress((void**)&aol, g_aol);

    __half* wqh  = w16 + 0 * (size_t)DIMM * CCH;
    __half* wkh  = w16 + 1 * (size_t)DIMM * CCH;
    __half* wvh  = w16 + 2 * (size_t)DIMM * CCH;
    __half* qpwh = w16 + 3 * (size_t)DIMM * CCH;
    __half* kpwh = w16 + 4 * (size_t)DIMM * CCH;
    __half* vpwh = w16 + 5 * (size_t)DIMM * CCH;
    __half* woh  = w16 + 6 * (size_t)DIMM * CCH;

    const int SMP1 = 3 * (PL_A + PL_B);      // 46080
    const int SMP2 = 3 * (2 * PL_A + PL_B);  // 61440
    cudaFuncSetAttribute(gemm_h_k<true, 1, 1>,  cudaFuncAttributeMaxDynamicSharedMemorySize, SMP1);
    cudaFuncSetAttribute(gemm_h_k<true, 2, 2>,  cudaFuncAttributeMaxDynamicSharedMemorySize, SMP2);
    cudaFuncSetAttribute(gemm_h_k<false, 1, 1>, cudaFuncAttributeMaxDynamicSharedMemorySize, SMP1);
    cudaFuncSetAttribute(gemm_h_k<false, 2, 1>, cudaFuncAttributeMaxDynamicSharedMemorySize, SMP2);
    cudaFuncSetAttribute(gemm_h_k<false, 2, 0>, cudaFuncAttributeMaxDynamicSharedMemorySize, SMP2);
    cudaFuncSetAttribute(attn_mma_k, cudaFuncAttributeMaxDynamicSharedMemorySize, AT_SMEM);

    // 0) prep: weights + x to fp16
    WC wc;
    wc.s[0] = wq;  wc.d[0] = wqh;
    wc.s[1] = wk;  wc.d[1] = wkh;
    wc.s[2] = wv;  wc.d[2] = wvh;
    wc.s[3] = qpww; wc.d[3] = qpwh;
    wc.s[4] = kpww; wc.d[4] = kpwh;
    wc.s[5] = vpww; wc.d[5] = vpwh;
    wc.s[6] = wo;  wc.d[6] = woh;
    wconv_k<<<dim3(2048, 7), 256>>>(wc);
    xconv_k<<<8192, 256>>>((const float2*)x, (uint32_t*)xh, (uint32_t*)xlo);

    dim3 grid_qk(8, 64, 2), grid_1(8, 64, 1);

    // 1) QKV projection + SiLU
    gemm_h_k<true, 1, 1><<<grid_qk, 256, SMP1>>>(
        GH{xh, 0, wqh, bq, q16, 0}, GH{xh, 0, wkh, bk, k16, 0}, GH{xh, 0, wkh, bk, k16, 0});
    gemm_h_k<true, 2, 2><<<grid_1, 256, SMP2>>>(
        GH{xh, xlo, wvh, bv, vhi, vlo}, GH{xh, xlo, wvh, bv, vhi, vlo}, GH{xh, xlo, wvh, bv, vhi, vlo});

    // 2) depthwise conv
    dwconv_h_k<<<dim3(8192, 2), 256>>>((const __half2*)q16, (const __half2*)k16,
                                       qdww, kdww, qdwb, kdwb,
                                       (__half2*)qc16, (__half2*)kc16);
    dwconv_hl_k<<<8192, 256>>>((const __half2*)vhi, (const __half2*)vlo,
                               vdww, vdwb, (uint32_t*)vchi, (uint32_t*)vclo);

    // 3) pointwise conv
    gemm_h_k<false, 1, 1><<<grid_qk, 256, SMP1>>>(
        GH{qc16, 0, qpwh, qpwb, qpw, 0}, GH{kc16, 0, kpwh, kpwb, kpw, 0}, GH{kc16, 0, kpwh, kpwb, kpw, 0});
    gemm_h_k<false, 2, 1><<<grid_1, 256, SMP2>>>(
        GH{vchi, vclo, vpwh, vpwb, vpw, 0}, GH{vchi, vclo, vpwh, vpwb, vpw, 0}, GH{vchi, vclo, vpwh, vpwb, vpw, 0});

    // 4) l2norm (q scaled by 0.125) + v transpose
    l2norm_f16_k<<<dim3((MROWS * NHH) / 8, 2), 256>>>((const __half2*)qpw, (const __half2*)kpw,
                                                      (__half2*)qn, (__half2*)kn);
    vtrans_k<<<dim3(32, 64, 2), dim3(32, 8)>>>(vpw, vt);

    // 5) flash attention -> fp16 hi/lo
    attn_mma_k<<<dim3(SEQ / 128, NHH, BSZ), 256, AT_SMEM>>>(qn, kn, vt, mask, aoh, aol);

    // 6) output projection -> d_out (fp32)
    gemm_h_k<false, 2, 0><<<grid_1, 256, SMP2>>>(
        GH{aoh, aol, woh, bo, out, 0}, GH{aoh, aol, woh, bo, out, 0}, GH{aoh, aol, woh, bo, out, 0});
}

// round 11
// speedup vs baseline: 4.8277x; 1.0180x over previous
#include <cuda_runtime.h>
#include <cuda_fp16.h>
#include <stdint.h>

#define BSZ 2
#define SEQ 2048
#define DIMM 1024
#define CCH 1024
#define NHH 16
#define HDD 64
#define MROWS (BSZ*SEQ)   // 4096

// ---------------- fp16 scratch (device globals) ----------------------------------
__device__ __half g_xh [MROWS*DIMM];
__device__ __half g_xlo[MROWS*DIMM];
__device__ __half g_w16[7][DIMM*CCH];          // wq,wk,wv,qpw,kpw,vpw,wo
__device__ __half g_q16[MROWS*CCH],  g_k16[MROWS*CCH];
__device__ __half g_vhi[MROWS*CCH],  g_vlo[MROWS*CCH];
__device__ __half g_qc16[MROWS*CCH], g_kc16[MROWS*CCH];
__device__ __half g_vchi[MROWS*CCH], g_vclo[MROWS*CCH];
__device__ __half g_qpw[MROWS*CCH],  g_kpw[MROWS*CCH], g_vpw[MROWS*CCH];
__device__ __half g_qn[MROWS*CCH],   g_kn[MROWS*CCH],  g_vt[MROWS*CCH];
__device__ __half g_aoh[MROWS*CCH],  g_aol[MROWS*CCH];

// ================= helpers =======================================================
__device__ __forceinline__ uint32_t smem_u32(const void* p) {
    uint32_t a;
    asm("{ .reg .u64 t; cvta.to.shared.u64 t, %1; cvt.u32.u64 %0, t; }" : "=r"(a) : "l"(p));
    return a;
}
__device__ __forceinline__ uint32_t pack2f16(float x, float y) {
    __half2 t = __floats2half2_rn(x, y);
    return *reinterpret_cast<uint32_t*>(&t);
}
__device__ __forceinline__ void split2h(float x, float y, uint32_t& h, uint32_t& l) {
    __half hx = __float2half_rn(x);
    __half hy = __float2half_rn(y);
    __half2 hp = __halves2half2(hx, hy);
    h = *reinterpret_cast<uint32_t*>(&hp);
    l = pack2f16(x - __half2float(hx), y - __half2float(hy));
}
__device__ __forceinline__ void mma_f16(float* d, const uint32_t* a, const uint32_t* b) {
    asm volatile(
        "mma.sync.aligned.m16n8k16.row.col.f32.f16.f16.f32 "
        "{%0,%1,%2,%3}, {%4,%5,%6,%7}, {%8,%9}, {%0,%1,%2,%3};"
        : "+f"(d[0]), "+f"(d[1]), "+f"(d[2]), "+f"(d[3])
        : "r"(a[0]), "r"(a[1]), "r"(a[2]), "r"(a[3]), "r"(b[0]), "r"(b[1]));
}
__device__ __forceinline__ void mma_f16_b(float* d, const uint32_t* a, uint32_t b0, uint32_t b1) {
    asm volatile(
        "mma.sync.aligned.m16n8k16.row.col.f32.f16.f16.f32 "
        "{%0,%1,%2,%3}, {%4,%5,%6,%7}, {%8,%9}, {%0,%1,%2,%3};"
        : "+f"(d[0]), "+f"(d[1]), "+f"(d[2]), "+f"(d[3])
        : "r"(a[0]), "r"(a[1]), "r"(a[2]), "r"(a[3]), "r"(b0), "r"(b1));
}
__device__ __forceinline__ void ldm_x4(uint32_t& r0, uint32_t& r1, uint32_t& r2, uint32_t& r3,
                                       uint32_t addr) {
    asm volatile("ldmatrix.sync.aligned.m8n8.x4.shared.b16 {%0,%1,%2,%3}, [%4];"
                 : "=r"(r0), "=r"(r1), "=r"(r2), "=r"(r3) : "r"(addr));
}
__device__ __forceinline__ float exp_small(float x) {   // |x| <= 0.125, rel err ~3e-8
    return 1.f + x * (1.f + x * (0.5f + x * (0.166666667f + x * 0.0416666667f)));
}

// ================= prep kernels ==================================================
struct WC { const float* s[7]; __half* d[7]; };
__global__ void wconv_k(WC wc)
{
    const float2* s = (const float2*)wc.s[blockIdx.y];
    __half2* d = (__half2*)wc.d[blockIdx.y];
    int i = blockIdx.x * 256 + threadIdx.x;    // < 512K
    float2 v = s[i];
    d[i] = __floats2half2_rn(v.x, v.y);
}
__global__ void xconv_k(const float2* x, uint32_t* xh, uint32_t* xl)
{
    int i = blockIdx.x * 256 + threadIdx.x;    // < 2M
    float2 v = x[i];
    uint32_t h, l;
    split2h(v.x, v.y, h, l);
    xh[i] = h; xl[i] = l;
}

// ================= fp16 GEMM: cp.async + ldmatrix + mma ==========================
// C[m,n] = sum_k A[m,k]*W[n,k] + bias[n]; M=4096, N=K=1024. fp16 inputs.
// prod/omode are RUNTIME per-z (uniform branches) so independent GEMMs fuse into
// one launch and overlap wave tails. Smem layout fixed at prod=2 footprint.
// CTA 64x128, KC=32, 256 threads (8 warps, 2x4), warp tile 32x32, 3 stages,
// 3 CTAs/SM.
struct GH { const __half* A; const __half* Al; const __half* W; const float* bias;
            void* C; void* Cl; int prod; int omode; };

#define PL_A 5120                    // A plane: 64 rows x 80B
#define PL_B 10240                   // B plane: 128 rows x 80B
#define G_STB (2*PL_A + PL_B)        // stage bytes (prod=2 layout)
#define G_NST 3
#define G_SMEM (G_NST*G_STB)         // 61440

template<bool SILU>
__global__ void __launch_bounds__(256, 3)
gemm_h_k(GH g0, GH g1, GH g2)
{
    GH g = (blockIdx.z == 0) ? g0 : ((blockIdx.z == 1) ? g1 : g2);
    const int prod = g.prod;
    extern __shared__ uint32_t smw[];
    const uint32_t sb = smem_u32(smw);

    const int tid = threadIdx.x, lane = tid & 31, wid = tid >> 5;
    const int wm = wid & 1, wn = wid >> 1;       // 2x4 warp grid
    const int gr = lane >> 2, gc = lane & 3;
    const int m0 = blockIdx.y * 64, n0 = blockIdx.x * 128;

    const int rr = tid >> 2, ch = tid & 3;       // cp.async geometry (64 rows x 4 chunks)
    const __half* pa  = g.A + (size_t)(m0 + rr) * DIMM + ch * 8;
    const __half* pl  = (prod == 2) ? (g.Al + (size_t)(m0 + rr) * DIMM + ch * 8) : g.A;
    const __half* pw0 = g.W + (size_t)(n0 + rr) * DIMM + ch * 8;
    const __half* pw1 = g.W + (size_t)(n0 + rr + 64) * DIMM + ch * 8;
    const uint32_t dA  = sb + rr * 80 + ch * 16;
    const uint32_t dB0 = sb + 2 * PL_A + rr * 80 + ch * 16;
    const uint32_t dB1 = dB0 + 64 * 80;

    const uint32_t aoff = (uint32_t)(wm * 32 + (lane & 15)) * 80 + ((lane >> 4) << 4);
    const uint32_t boff = 2 * PL_A +
        (uint32_t)(wn * 32 + ((lane >> 4) << 3) + (lane & 7)) * 80 + (((lane >> 3) & 1) << 4);

    auto issue = [&](int i) {
        int kk = i * 32;
        uint32_t st = (i % G_NST) * G_STB;
        asm volatile("cp.async.cg.shared.global [%0], [%1], 16;" :: "r"(dA + st), "l"(pa + kk));
        if (prod == 2)
            asm volatile("cp.async.cg.shared.global [%0], [%1], 16;" :: "r"(dA + PL_A + st), "l"(pl + kk));
        asm volatile("cp.async.cg.shared.global [%0], [%1], 16;" :: "r"(dB0 + st), "l"(pw0 + kk));
        asm volatile("cp.async.cg.shared.global [%0], [%1], 16;" :: "r"(dB1 + st), "l"(pw1 + kk));
        asm volatile("cp.async.commit_group;");
    };

    float acc[2][4][4];
    #pragma unroll
    for (int mi = 0; mi < 2; mi++)
        #pragma unroll
        for (int ni = 0; ni < 4; ni++)
            #pragma unroll
            for (int e = 0; e < 4; e++) acc[mi][ni][e] = 0.f;

    #pragma unroll
    for (int s = 0; s < G_NST - 1; s++) issue(s);

    #pragma unroll 1
    for (int i = 0; i < 32; i++) {
        if (31 - i >= G_NST - 2)    asm volatile("cp.async.wait_group %0;" :: "n"(G_NST - 2));
        else                        asm volatile("cp.async.wait_group 0;");
        __syncthreads();
        if (i + G_NST - 1 < 32) issue(i + G_NST - 1);

        uint32_t stb = sb + (i % G_NST) * G_STB;
        #pragma unroll
        for (int ki = 0; ki < 2; ki++) {
            uint32_t koff = ki * 32;
            uint32_t ah[2][4], al[2][4], bf[4][2];
            ldm_x4(ah[0][0], ah[0][1], ah[0][2], ah[0][3], stb + aoff + koff);
            ldm_x4(ah[1][0], ah[1][1], ah[1][2], ah[1][3], stb + aoff + 16 * 80 + koff);
            if (prod == 2) {
                ldm_x4(al[0][0], al[0][1], al[0][2], al[0][3], stb + aoff + PL_A + koff);
                ldm_x4(al[1][0], al[1][1], al[1][2], al[1][3], stb + aoff + PL_A + 16 * 80 + koff);
            }
            ldm_x4(bf[0][0], bf[0][1], bf[1][0], bf[1][1], stb + boff + koff);
            ldm_x4(bf[2][0], bf[2][1], bf[3][0], bf[3][1], stb + boff + 16 * 80 + koff);
            #pragma unroll
            for (int ni = 0; ni < 4; ni++)
                #pragma unroll
                for (int mi = 0; mi < 2; mi++)
                    mma_f16(acc[mi][ni], ah[mi], bf[ni]);
            if (prod == 2) {
                #pragma unroll
                for (int ni = 0; ni < 4; ni++)
                    #pragma unroll
                    for (int mi = 0; mi < 2; mi++)
                        mma_f16(acc[mi][ni], al[mi], bf[ni]);
            }
        }
    }

    const int omode = g.omode;
    #pragma unroll
    for (int ni = 0; ni < 4; ni++) {
        int cg = n0 + wn * 32 + ni * 8 + 2 * gc;
        float b0 = g.bias[cg], b1 = g.bias[cg + 1];
        #pragma unroll
        for (int mi = 0; mi < 2; mi++) {
            int r = m0 + wm * 32 + mi * 16 + gr;
            float v0 = acc[mi][ni][0] + b0;
            float v1 = acc[mi][ni][1] + b1;
            float v2 = acc[mi][ni][2] + b0;
            float v3 = acc[mi][ni][3] + b1;
            if (SILU) {
                v0 = v0 / (1.f + __expf(-v0));
                v1 = v1 / (1.f + __expf(-v1));
                v2 = v2 / (1.f + __expf(-v2));
                v3 = v3 / (1.f + __expf(-v3));
            }
            if (omode == 0) {
                float* C = (float*)g.C;
                *(float2*)(C + (size_t)r * CCH + cg)       = make_float2(v0, v1);
                *(float2*)(C + (size_t)(r + 8) * CCH + cg) = make_float2(v2, v3);
            } else if (omode == 1) {
                __half* C = (__half*)g.C;
                *(uint32_t*)(C + (size_t)r * CCH + cg)       = pack2f16(v0, v1);
                *(uint32_t*)(C + (size_t)(r + 8) * CCH + cg) = pack2f16(v2, v3);
            } else {
                __half* C  = (__half*)g.C;
                __half* Cl = (__half*)g.Cl;
                uint32_t h, l;
                split2h(v0, v1, h, l);
                *(uint32_t*)(C  + (size_t)r * CCH + cg) = h;
                *(uint32_t*)(Cl + (size_t)r * CCH + cg) = l;
                split2h(v2, v3, h, l);
                *(uint32_t*)(C  + (size_t)(r + 8) * CCH + cg) = h;
                *(uint32_t*)(Cl + (size_t)(r + 8) * CCH + cg) = l;
            }
        }
    }
}

// ---------------- fused depthwise conv k=3 (z=0:q, z=1:k single; z=2:v hi/lo) ----
__global__ void dwconv_all_k(const __half2* q, const __half2* k,
                             const __half2* vh, const __half2* vl,
                             const float* wq, const float* wk, const float* wv,
                             const float* bq, const float* bk, const float* bv,
                             __half2* oq, __half2* ok,
                             uint32_t* ovh, uint32_t* ovl)
{
    int z = blockIdx.y;
    int i2 = blockIdx.x * 256 + threadIdx.x;     // < 2M
    int c2 = i2 & 511, m = i2 >> 9, s = m & (SEQ - 1);
    int c0 = c2 * 2;
    const float* w  = (z == 0) ? wq : ((z == 1) ? wk : wv);
    const float* bb = (z == 0) ? bq : ((z == 1) ? bk : bv);
    float wa0 = w[c0*3], wa1 = w[c0*3+1], wa2 = w[c0*3+2];
    float wb0 = w[c0*3+3], wb1 = w[c0*3+4], wb2 = w[c0*3+5];

    if (z < 2) {
        const __half2* in = z ? k : q;
        __half2* out = z ? ok : oq;
        float2 x  = __half22float2(in[i2]);
        float2 xm = make_float2(0.f, 0.f), xp = make_float2(0.f, 0.f);
        if (s > 0)       xm = __half22float2(in[i2 - 512]);
        if (s < SEQ - 1) xp = __half22float2(in[i2 + 512]);
        float va = xm.x*wa0 + x.x*wa1 + xp.x*wa2 + bb[c0];
        float vb = xm.y*wb0 + x.y*wb1 + xp.y*wb2 + bb[c0+1];
        out[i2] = __floats2half2_rn(va, vb);
    } else {
        float2 xh = __half22float2(vh[i2]), xl = __half22float2(vl[i2]);
        float2 x  = make_float2(xh.x + xl.x, xh.y + xl.y);
        float2 xm = make_float2(0.f, 0.f), xp = make_float2(0.f, 0.f);
        if (s > 0) {
            float2 a = __half22float2(vh[i2 - 512]), b = __half22float2(vl[i2 - 512]);
            xm = make_float2(a.x + b.x, a.y + b.y);
        }
        if (s < SEQ - 1) {
            float2 a = __half22float2(vh[i2 + 512]), b = __half22float2(vl[i2 + 512]);
            xp = make_float2(a.x + b.x, a.y + b.y);
        }
        float va = xm.x*wa0 + x.x*wa1 + xp.x*wa2 + bb[c0];
        float vb = xm.y*wb0 + x.y*wb1 + xp.y*wb2 + bb[c0+1];
        uint32_t h, l;
        split2h(va, vb, h, l);
        ovh[i2] = h; ovl[i2] = l;
    }
}

// ---------------- per-head L2 normalize (fp16 in/out; q gets 0.125 folded) -------
__global__ void l2norm_f16_k(const __half2* q, const __half2* k, __half2* qn, __half2* kn)
{
    const __half2* src = blockIdx.y ? k : q;
    __half2* dst = blockIdx.y ? kn : qn;
    float sc = blockIdx.y ? 1.0f : 0.125f;
    int warp = threadIdx.x >> 5, lane = threadIdx.x & 31;
    size_t g = (size_t)blockIdx.x * 8 + warp;
    float2 x = __half22float2(src[g * 32 + lane]);
    float ss = x.x * x.x + x.y * x.y;
    #pragma unroll
    for (int o = 16; o; o >>= 1) ss += __shfl_xor_sync(0xffffffffu, ss, o);
    float inv = sc / fmaxf(sqrtf(ss), 1e-12f);
    dst[g * 32 + lane] = __floats2half2_rn(x.x * inv, x.y * inv);
}

// ---------------- V transpose fp16 [b][ch][s] ------------------------------------
__global__ void vtrans_k(const __half* v, __half* vt)
{
    __shared__ float t[32][33];
    int b = blockIdx.z;
    int s0 = blockIdx.y * 32, c0 = blockIdx.x * 32;
    int tx = threadIdx.x, ty = threadIdx.y;   // 32x8
    #pragma unroll
    for (int j = 0; j < 4; j++)
        t[ty + 8 * j][tx] = __half2float(v[(size_t)(b * SEQ + s0 + ty + 8 * j) * CCH + c0 + tx]);
    __syncthreads();
    #pragma unroll
    for (int j = 0; j < 4; j++)
        vt[(size_t)(b * CCH + c0 + ty + 8 * j) * SEQ + s0 + tx] = __float2half(t[tx][ty + 8 * j]);
}

// ================= flash attention: cp.async + ldmatrix fp16 pipeline ============
#define AT_STW 4608
#define AT_NST 3
#define AT_SMEM (AT_NST*AT_STW*4)    // 55296 B

__global__ void __launch_bounds__(256, 2) attn_mma_k(const __half* __restrict__ Qh,
                                                     const __half* __restrict__ Kh,
                                                     const __half* __restrict__ Vt,
                                                     const int* __restrict__ mask,
                                                     __half* __restrict__ AOh,
                                                     __half* __restrict__ AOl)
{
    const int qt = blockIdx.x, h = blockIdx.y, bb = blockIdx.z;
    extern __shared__ uint32_t asw[];
    __shared__ int s_mask[AT_NST][64];

    const int tid = threadIdx.x, lane = tid & 31, w = tid >> 5;
    const int gr = lane >> 2, gc = lane & 3;
    const uint32_t sbase = smem_u32(asw);

    const __half* kb = Kh + ((size_t)bb * SEQ) * CCH + h * HDD;
    const __half* vb = Vt + ((size_t)(bb * NHH + h)) * HDD * SEQ;

    const uint32_t ldmoff =
        (uint32_t)(((lane >> 4) << 3) + (lane & 7)) * 144 + (((lane >> 3) & 1) << 4);

    auto issue = [&](int jt) {
        int slot = jt % AT_NST;
        uint32_t kdst = sbase + slot * AT_STW * 4;
        uint32_t vdst = kdst + 2304 * 4;
        #pragma unroll
        for (int j = 0; j < 2; j++) {
            int c = tid + 256 * j;
            int row = c >> 3, ch = c & 7;
            uint32_t d = kdst + (row * 36 + ch * 4) * 4;
            const __half* s = kb + (size_t)(jt * 64 + row) * CCH + ch * 8;
            asm volatile("cp.async.cg.shared.global [%0], [%1], 16;" :: "r"(d), "l"(s));
        }
        #pragma unroll
        for (int j = 0; j < 2; j++) {
            int c = tid + 256 * j;
            int row = c >> 3, ch = c & 7;
            uint32_t d = vdst + (row * 36 + ch * 4) * 4;
            const __half* s = vb + (size_t)row * SEQ + jt * 64 + ch * 8;
            asm volatile("cp.async.cg.shared.global [%0], [%1], 16;" :: "r"(d), "l"(s));
        }
        if (tid < 16) {
            uint32_t d = smem_u32(&s_mask[slot][0]) + tid * 16;
            const int* s = mask + bb * SEQ + jt * 64 + tid * 4;
            asm volatile("cp.async.cg.shared.global [%0], [%1], 16;" :: "r"(d), "l"(s));
        }
        asm volatile("cp.async.commit_group;");
    };

    issue(0);
    issue(1);

    uint32_t qa[4][4];
    {
        const __half* qb = Qh + ((size_t)(bb * SEQ + qt * 128)) * CCH + h * HDD;
        int r0 = w * 16 + gr, r1 = r0 + 8;
        #pragma unroll
        for (int ks = 0; ks < 4; ks++) {
            int c = ks * 16 + 2 * gc;
            qa[ks][0] = *(const uint32_t*)(qb + (size_t)r0 * CCH + c);
            qa[ks][1] = *(const uint32_t*)(qb + (size_t)r1 * CCH + c);
            qa[ks][2] = *(const uint32_t*)(qb + (size_t)r0 * CCH + c + 8);
            qa[ks][3] = *(const uint32_t*)(qb + (size_t)r1 * CCH + c + 8);
        }
    }

    float o[8][4];
    #pragma unroll
    for (int ht = 0; ht < 8; ht++)
        #pragma unroll
        for (int e = 0; e < 4; e++) o[ht][e] = 0.f;
    float l0 = 0.f, l1 = 0.f;

    #pragma unroll 1
    for (int jt = 0; jt < 32; jt++) {
        const int slot = jt % AT_NST;
        if (jt < 31) asm volatile("cp.async.wait_group 1;");
        else         asm volatile("cp.async.wait_group 0;");
        __syncthreads();
        if (jt + 2 < 32) issue(jt + 2);

        uint32_t kaddr = sbase + slot * AT_STW * 4 + ldmoff;
        uint32_t vaddr = kaddr + 2304 * 4;

        float s[8][4];
        #pragma unroll
        for (int nt = 0; nt < 8; nt++)
            #pragma unroll
            for (int e = 0; e < 4; e++) s[nt][e] = 0.f;
        #pragma unroll
        for (int ks = 0; ks < 4; ks++) {
            uint32_t bf[8][2];
            #pragma unroll
            for (int p = 0; p < 4; p++)
                ldm_x4(bf[2 * p][0], bf[2 * p][1], bf[2 * p + 1][0], bf[2 * p + 1][1],
                       kaddr + p * (16 * 144) + ks * 32);
            #pragma unroll
            for (int nt = 0; nt < 8; nt++)
                mma_f16_b(s[nt], qa[ks], bf[nt][0], bf[nt][1]);
        }

        #pragma unroll
        for (int nt = 0; nt < 8; nt++) {
            int c0 = nt * 8 + 2 * gc;
            bool ok0 = s_mask[slot][c0] != 0;
            bool ok1 = s_mask[slot][c0 + 1] != 0;
            s[nt][0] = ok0 ? exp_small(s[nt][0]) : 0.f;
            s[nt][1] = ok1 ? exp_small(s[nt][1]) : 0.f;
            s[nt][2] = ok0 ? exp_small(s[nt][2]) : 0.f;
            s[nt][3] = ok1 ? exp_small(s[nt][3]) : 0.f;
            l0 += s[nt][0] + s[nt][1];
            l1 += s[nt][2] + s[nt][3];
        }

        #pragma unroll
        for (int ks = 0; ks < 4; ks++) {
            uint32_t aF[4];
            aF[0] = pack2f16(s[2 * ks][0],     s[2 * ks][1]);
            aF[1] = pack2f16(s[2 * ks][2],     s[2 * ks][3]);
            aF[2] = pack2f16(s[2 * ks + 1][0], s[2 * ks + 1][1]);
            aF[3] = pack2f16(s[2 * ks + 1][2], s[2 * ks + 1][3]);
            uint32_t vf[8][2];
            #pragma unroll
            for (int p = 0; p < 4; p++)
                ldm_x4(vf[2 * p][0], vf[2 * p][1], vf[2 * p + 1][0], vf[2 * p + 1][1],
                       vaddr + p * (16 * 144) + ks * 32);
            #pragma unroll
            for (int ht = 0; ht < 8; ht++)
                mma_f16_b(o[ht], aF, vf[ht][0], vf[ht][1]);
        }
    }

    l0 += __shfl_xor_sync(0xffffffffu, l0, 1);
    l0 += __shfl_xor_sync(0xffffffffu, l0, 2);
    l1 += __shfl_xor_sync(0xffffffffu, l1, 1);
    l1 += __shfl_xor_sync(0xffffffffu, l1, 2);
    {
        float inv0 = 1.f / l0, inv1 = 1.f / l1;
        int r0 = w * 16 + gr, r1 = r0 + 8;
        size_t base = ((size_t)(bb * SEQ + qt * 128)) * CCH + h * HDD;
        __half* Oh = AOh + base;
        __half* Ol = AOl + base;
        #pragma unroll
        for (int ht = 0; ht < 8; ht++) {
            int c = ht * 8 + 2 * gc;
            uint32_t hh, ll;
            split2h(o[ht][0] * inv0, o[ht][1] * inv0, hh, ll);
            *(uint32_t*)(Oh + (size_t)r0 * CCH + c) = hh;
            *(uint32_t*)(Ol + (size_t)r0 * CCH + c) = ll;
            split2h(o[ht][2] * inv1, o[ht][3] * inv1, hh, ll);
            *(uint32_t*)(Oh + (size_t)r1 * CCH + c) = hh;
            *(uint32_t*)(Ol + (size_t)r1 * CCH + c) = ll;
        }
    }
}

// ---------------- host launcher ---------------------------------------------------
extern "C" void kernel_launch(void* const* d_in, const int* in_sizes, int n_in,
                              void* d_out, int out_size)
{
    const float* x    = (const float*)d_in[0];
    const int*   mask = (const int*)d_in[1];
    const float* wq   = (const float*)d_in[2];
    const float* bq   = (const float*)d_in[3];
    const float* wk   = (const float*)d_in[4];
    const float* bk   = (const float*)d_in[5];
    const float* wv   = (const float*)d_in[6];
    const float* bv   = (const float*)d_in[7];
    const float* qdww = (const float*)d_in[8];
    const float* qdwb = (const float*)d_in[9];
    const float* qpww = (const float*)d_in[10];
    const float* qpwb = (const float*)d_in[11];
    const float* kdww = (const float*)d_in[12];
    const float* kdwb = (const float*)d_in[13];
    const float* kpww = (const float*)d_in[14];
    const float* kpwb = (const float*)d_in[15];
    const float* vdww = (const float*)d_in[16];
    const float* vdwb = (const float*)d_in[17];
    const float* vpww = (const float*)d_in[18];
    const float* vpwb = (const float*)d_in[19];
    const float* wo   = (const float*)d_in[20];
    const float* bo   = (const float*)d_in[21];
    float* out = (float*)d_out;

    __half *xh, *xlo, *w16, *q16, *k16, *vhi, *vlo, *qc16, *kc16, *vchi, *vclo;
    __half *qpw, *kpw, *vpw, *qn, *kn, *vt, *aoh, *aol;
    cudaGetSymbolAddress((void**)&xh,  g_xh);
    cudaGetSymbolAddress((void**)&xlo, g_xlo);
    cudaGetSymbolAddress((void**)&w16, g_w16);
    cudaGetSymbolAddress((void**)&q16, g_q16);
    cudaGetSymbolAddress((void**)&k16, g_k16);
    cudaGetSymbolAddress((void**)&vhi, g_vhi);
    cudaGetSymbolAddress((void**)&vlo, g_vlo);
    cudaGetSymbolAddress((void**)&qc16, g_qc16);
    cudaGetSymbolAddress((void**)&kc16, g_kc16);
    cudaGetSymbolAddress((void**)&vchi, g_vchi);
    cudaGetSymbolAddress((void**)&vclo, g_vclo);
    cudaGetSymbolAddress((void**)&qpw, g_qpw);
    cudaGetSymbolAddress((void**)&kpw, g_kpw);
    cudaGetSymbolAddress((void**)&vpw, g_vpw);
    cudaGetSymbolAddress((void**)&qn,  g_qn);
    cudaGetSymbolAddress((void**)&kn,  g_kn);
    cudaGetSymbolAddress((void**)&vt,  g_vt);
    cudaGetSymbolAddress((void**)&aoh, g_aoh);
    cudaGetSymbolAddress((void**)&aol, g_aol);

    __half* wqh  = w16 + 0 * (size_t)DIMM * CCH;
    __half* wkh  = w16 + 1 * (size_t)DIMM * CCH;
    __half* wvh  = w16 + 2 * (size_t)DIMM * CCH;
    __half* qpwh = w16 + 3 * (size_t)DIMM * CCH;
    __half* kpwh = w16 + 4 * (size_t)DIMM * CCH;
    __half* vpwh = w16 + 5 * (size_t)DIMM * CCH;
    __half* woh  = w16 + 6 * (size_t)DIMM * CCH;

    cudaFuncSetAttribute(gemm_h_k<true>,  cudaFuncAttributeMaxDynamicSharedMemorySize, G_SMEM);
    cudaFuncSetAttribute(gemm_h_k<false>, cudaFuncAttributeMaxDynamicSharedMemorySize, G_SMEM);
    cudaFuncSetAttribute(attn_mma_k, cudaFuncAttributeMaxDynamicSharedMemorySize, AT_SMEM);

    // 0) prep: weights + x to fp16
    WC wc;
    wc.s[0] = wq;  wc.d[0] = wqh;
    wc.s[1] = wk;  wc.d[1] = wkh;
    wc.s[2] = wv;  wc.d[2] = wvh;
    wc.s[3] = qpww; wc.d[3] = qpwh;
    wc.s[4] = kpww; wc.d[4] = kpwh;
    wc.s[5] = vpww; wc.d[5] = vpwh;
    wc.s[6] = wo;  wc.d[6] = woh;
    wconv_k<<<dim3(2048, 7), 256>>>(wc);
    xconv_k<<<8192, 256>>>((const float2*)x, (uint32_t*)xh, (uint32_t*)xlo);

    dim3 grid_3(8, 64, 3), grid_1(8, 64, 1);

    // 1) QKV projection + SiLU (single fused launch; q,k prod=1, v prod=2)
    gemm_h_k<true><<<grid_3, 256, G_SMEM>>>(
        GH{xh, 0, wqh, bq, q16, 0, 1, 1},
        GH{xh, 0, wkh, bk, k16, 0, 1, 1},
        GH{xh, xlo, wvh, bv, vhi, vlo, 2, 2});

    // 2) depthwise conv (fused q,k,v)
    dwconv_all_k<<<dim3(8192, 3), 256>>>((const __half2*)q16, (const __half2*)k16,
                                         (const __half2*)vhi, (const __half2*)vlo,
                                         qdww, kdww, vdww, qdwb, kdwb, vdwb,
                                         (__half2*)qc16, (__half2*)kc16,
                                         (uint32_t*)vchi, (uint32_t*)vclo);

    // 3) pointwise conv (single fused launch)
    gemm_h_k<false><<<grid_3, 256, G_SMEM>>>(
        GH{qc16, 0, qpwh, qpwb, qpw, 0, 1, 1},
        GH{kc16, 0, kpwh, kpwb, kpw, 0, 1, 1},
        GH{vchi, vclo, vpwh, vpwb, vpw, 0, 2, 1});

    // 4) l2norm (q scaled by 0.125) + v transpose
    l2norm_f16_k<<<dim3((MROWS * NHH) / 8, 2), 256>>>((const __half2*)qpw, (const __half2*)kpw,
                                                      (__half2*)qn, (__half2*)kn);
    vtrans_k<<<dim3(32, 64, 2), dim3(32, 8)>>>(vpw, vt);

    // 5) flash attention -> fp16 hi/lo
    attn_mma_k<<<dim3(SEQ / 128, NHH, BSZ), 256, AT_SMEM>>>(qn, kn, vt, mask, aoh, aol);

    // 6) output projection -> d_out (fp32)
    gemm_h_k<false><<<grid_1, 256, G_SMEM>>>(
        GH{aoh, aol, woh, bo, out, 0, 2, 0},
        GH{aoh, aol, woh, bo, out, 0, 2, 0},
        GH{aoh, aol, woh, bo, out, 0, 2, 0});
}

// round 12
// speedup vs baseline: 5.2901x; 1.0958x over previous
#include <cuda_runtime.h>
#include <cuda_fp16.h>
#include <stdint.h>

#define BSZ 2
#define SEQ 2048
#define DIMM 1024
#define CCH 1024
#define NHH 16
#define HDD 64
#define MROWS (BSZ*SEQ)   // 4096

// ---------------- fp16 scratch (device globals) ----------------------------------
__device__ __half g_xh [MROWS*DIMM];
__device__ __half g_xlo[MROWS*DIMM];
__device__ __half g_w16[7][DIMM*CCH];          // wq,wk,wv,qpw,kpw,vpw,wo
__device__ float  g_dwt[3*3*CCH];              // transposed dw weights [qkv][tap][C]
__device__ __half g_q16[MROWS*CCH],  g_k16[MROWS*CCH];
__device__ __half g_vhi[MROWS*CCH],  g_vlo[MROWS*CCH];
__device__ __half g_qc16[MROWS*CCH], g_kc16[MROWS*CCH];
__device__ __half g_vchi[MROWS*CCH], g_vclo[MROWS*CCH];
__device__ __half g_qpw[MROWS*CCH],  g_kpw[MROWS*CCH], g_vpw[MROWS*CCH];
__device__ __half g_qn[MROWS*CCH],   g_kn[MROWS*CCH],  g_vt[MROWS*CCH];
__device__ __half g_aoh[MROWS*CCH],  g_aol[MROWS*CCH];

// ================= helpers =======================================================
__device__ __forceinline__ uint32_t smem_u32(const void* p) {
    uint32_t a;
    asm("{ .reg .u64 t; cvta.to.shared.u64 t, %1; cvt.u32.u64 %0, t; }" : "=r"(a) : "l"(p));
    return a;
}
__device__ __forceinline__ uint32_t pack2f16(float x, float y) {
    __half2 t = __floats2half2_rn(x, y);
    return *reinterpret_cast<uint32_t*>(&t);
}
__device__ __forceinline__ void split2h(float x, float y, uint32_t& h, uint32_t& l) {
    __half hx = __float2half_rn(x);
    __half hy = __float2half_rn(y);
    __half2 hp = __halves2half2(hx, hy);
    h = *reinterpret_cast<uint32_t*>(&hp);
    l = pack2f16(x - __half2float(hx), y - __half2float(hy));
}
__device__ __forceinline__ void mma_f16(float* d, const uint32_t* a, const uint32_t* b) {
    asm volatile(
        "mma.sync.aligned.m16n8k16.row.col.f32.f16.f16.f32 "
        "{%0,%1,%2,%3}, {%4,%5,%6,%7}, {%8,%9}, {%0,%1,%2,%3};"
        : "+f"(d[0]), "+f"(d[1]), "+f"(d[2]), "+f"(d[3])
        : "r"(a[0]), "r"(a[1]), "r"(a[2]), "r"(a[3]), "r"(b[0]), "r"(b[1]));
}
__device__ __forceinline__ void mma_f16_b(float* d, const uint32_t* a, uint32_t b0, uint32_t b1) {
    asm volatile(
        "mma.sync.aligned.m16n8k16.row.col.f32.f16.f16.f32 "
        "{%0,%1,%2,%3}, {%4,%5,%6,%7}, {%8,%9}, {%0,%1,%2,%3};"
        : "+f"(d[0]), "+f"(d[1]), "+f"(d[2]), "+f"(d[3])
        : "r"(a[0]), "r"(a[1]), "r"(a[2]), "r"(a[3]), "r"(b0), "r"(b1));
}
__device__ __forceinline__ void ldm_x4(uint32_t& r0, uint32_t& r1, uint32_t& r2, uint32_t& r3,
                                       uint32_t addr) {
    asm volatile("ldmatrix.sync.aligned.m8n8.x4.shared.b16 {%0,%1,%2,%3}, [%4];"
                 : "=r"(r0), "=r"(r1), "=r"(r2), "=r"(r3) : "r"(addr));
}
__device__ __forceinline__ float exp_small(float x) {   // |x| <= 0.125, rel err ~3e-8
    return 1.f + x * (1.f + x * (0.5f + x * (0.166666667f + x * 0.0416666667f)));
}

// ================= prep kernels ==================================================
struct WC { const float* s[7]; __half* d[7]; const float* dw[3]; float* dwt; };
__global__ void wconv_k(WC wc)
{
    int z = blockIdx.y;
    int i = blockIdx.x * 256 + threadIdx.x;
    if (z < 7) {
        const float2* s = (const float2*)wc.s[z];
        __half2* d = (__half2*)wc.d[z];
        float2 v = s[i];
        d[i] = __floats2half2_rn(v.x, v.y);
    } else {
        if (i < 3 * 3 * CCH) {
            int plane = i / (3 * CCH);
            int r = i % (3 * CCH);
            int tap = r >> 10, c = r & (CCH - 1);
            wc.dwt[plane * 3 * CCH + tap * CCH + c] = wc.dw[plane][c * 3 + tap];
        }
    }
}
__global__ void xconv_k(const float2* x, uint32_t* xh, uint32_t* xl)
{
    int i = blockIdx.x * 256 + threadIdx.x;    // < 2M
    float2 v = x[i];
    uint32_t h, l;
    split2h(v.x, v.y, h, l);
    xh[i] = h; xl[i] = l;
}

// ================= fp16 GEMM: cp.async + ldmatrix + mma ==========================
// C[m,n] = sum_k A[m,k]*W[n,k] + bias[n]; M=4096, N=K=1024. fp16 inputs.
// prod/omode runtime per-z (uniform). CTA 64x128, KC=32, 256 thr, 3 stages, 3 CTA/SM.
struct GH { const __half* A; const __half* Al; const __half* W; const float* bias;
            void* C; void* Cl; int prod; int omode; };

#define PL_A 5120
#define PL_B 10240
#define G_STB (2*PL_A + PL_B)
#define G_NST 3
#define G_SMEM (G_NST*G_STB)         // 61440

template<bool SILU>
__global__ void __launch_bounds__(256, 3)
gemm_h_k(GH g0, GH g1, GH g2)
{
    GH g = (blockIdx.z == 0) ? g0 : ((blockIdx.z == 1) ? g1 : g2);
    const int prod = g.prod;
    extern __shared__ uint32_t smw[];
    const uint32_t sb = smem_u32(smw);

    const int tid = threadIdx.x, lane = tid & 31, wid = tid >> 5;
    const int wm = wid & 1, wn = wid >> 1;
    const int gr = lane >> 2, gc = lane & 3;
    const int m0 = blockIdx.y * 64, n0 = blockIdx.x * 128;

    const int rr = tid >> 2, ch = tid & 3;
    const __half* pa  = g.A + (size_t)(m0 + rr) * DIMM + ch * 8;
    const __half* pl  = (prod == 2) ? (g.Al + (size_t)(m0 + rr) * DIMM + ch * 8) : g.A;
    const __half* pw0 = g.W + (size_t)(n0 + rr) * DIMM + ch * 8;
    const __half* pw1 = g.W + (size_t)(n0 + rr + 64) * DIMM + ch * 8;
    const uint32_t dA  = sb + rr * 80 + ch * 16;
    const uint32_t dB0 = sb + 2 * PL_A + rr * 80 + ch * 16;
    const uint32_t dB1 = dB0 + 64 * 80;

    const uint32_t aoff = (uint32_t)(wm * 32 + (lane & 15)) * 80 + ((lane >> 4) << 4);
    const uint32_t boff = 2 * PL_A +
        (uint32_t)(wn * 32 + ((lane >> 4) << 3) + (lane & 7)) * 80 + (((lane >> 3) & 1) << 4);

    auto issue = [&](int i) {
        int kk = i * 32;
        uint32_t st = (i % G_NST) * G_STB;
        asm volatile("cp.async.cg.shared.global [%0], [%1], 16;" :: "r"(dA + st), "l"(pa + kk));
        if (prod == 2)
            asm volatile("cp.async.cg.shared.global [%0], [%1], 16;" :: "r"(dA + PL_A + st), "l"(pl + kk));
        asm volatile("cp.async.cg.shared.global [%0], [%1], 16;" :: "r"(dB0 + st), "l"(pw0 + kk));
        asm volatile("cp.async.cg.shared.global [%0], [%1], 16;" :: "r"(dB1 + st), "l"(pw1 + kk));
        asm volatile("cp.async.commit_group;");
    };

    float acc[2][4][4];
    #pragma unroll
    for (int mi = 0; mi < 2; mi++)
        #pragma unroll
        for (int ni = 0; ni < 4; ni++)
            #pragma unroll
            for (int e = 0; e < 4; e++) acc[mi][ni][e] = 0.f;

    #pragma unroll
    for (int s = 0; s < G_NST - 1; s++) issue(s);

    #pragma unroll 1
    for (int i = 0; i < 32; i++) {
        if (31 - i >= G_NST - 2)    asm volatile("cp.async.wait_group %0;" :: "n"(G_NST - 2));
        else                        asm volatile("cp.async.wait_group 0;");
        __syncthreads();
        if (i + G_NST - 1 < 32) issue(i + G_NST - 1);

        uint32_t stb = sb + (i % G_NST) * G_STB;
        #pragma unroll
        for (int ki = 0; ki < 2; ki++) {
            uint32_t koff = ki * 32;
            uint32_t ah[2][4], al[2][4], bf[4][2];
            ldm_x4(ah[0][0], ah[0][1], ah[0][2], ah[0][3], stb + aoff + koff);
            ldm_x4(ah[1][0], ah[1][1], ah[1][2], ah[1][3], stb + aoff + 16 * 80 + koff);
            if (prod == 2) {
                ldm_x4(al[0][0], al[0][1], al[0][2], al[0][3], stb + aoff + PL_A + koff);
                ldm_x4(al[1][0], al[1][1], al[1][2], al[1][3], stb + aoff + PL_A + 16 * 80 + koff);
            }
            ldm_x4(bf[0][0], bf[0][1], bf[1][0], bf[1][1], stb + boff + koff);
            ldm_x4(bf[2][0], bf[2][1], bf[3][0], bf[3][1], stb + boff + 16 * 80 + koff);
            #pragma unroll
            for (int ni = 0; ni < 4; ni++)
                #pragma unroll
                for (int mi = 0; mi < 2; mi++)
                    mma_f16(acc[mi][ni], ah[mi], bf[ni]);
            if (prod == 2) {
                #pragma unroll
                for (int ni = 0; ni < 4; ni++)
                    #pragma unroll
                    for (int mi = 0; mi < 2; mi++)
                        mma_f16(acc[mi][ni], al[mi], bf[ni]);
            }
        }
    }

    const int omode = g.omode;
    #pragma unroll
    for (int ni = 0; ni < 4; ni++) {
        int cg = n0 + wn * 32 + ni * 8 + 2 * gc;
        float b0 = g.bias[cg], b1 = g.bias[cg + 1];
        #pragma unroll
        for (int mi = 0; mi < 2; mi++) {
            int r = m0 + wm * 32 + mi * 16 + gr;
            float v0 = acc[mi][ni][0] + b0;
            float v1 = acc[mi][ni][1] + b1;
            float v2 = acc[mi][ni][2] + b0;
            float v3 = acc[mi][ni][3] + b1;
            if (SILU) {
                v0 = v0 / (1.f + __expf(-v0));
                v1 = v1 / (1.f + __expf(-v1));
                v2 = v2 / (1.f + __expf(-v2));
                v3 = v3 / (1.f + __expf(-v3));
            }
            if (omode == 0) {
                float* C = (float*)g.C;
                *(float2*)(C + (size_t)r * CCH + cg)       = make_float2(v0, v1);
                *(float2*)(C + (size_t)(r + 8) * CCH + cg) = make_float2(v2, v3);
            } else if (omode == 1) {
                __half* C = (__half*)g.C;
                *(uint32_t*)(C + (size_t)r * CCH + cg)       = pack2f16(v0, v1);
                *(uint32_t*)(C + (size_t)(r + 8) * CCH + cg) = pack2f16(v2, v3);
            } else {
                __half* C  = (__half*)g.C;
                __half* Cl = (__half*)g.Cl;
                uint32_t h, l;
                split2h(v0, v1, h, l);
                *(uint32_t*)(C  + (size_t)r * CCH + cg) = h;
                *(uint32_t*)(Cl + (size_t)r * CCH + cg) = l;
                split2h(v2, v3, h, l);
                *(uint32_t*)(C  + (size_t)(r + 8) * CCH + cg) = h;
                *(uint32_t*)(Cl + (size_t)(r + 8) * CCH + cg) = l;
            }
        }
    }
}

// ---------------- fused depthwise conv k=3, vectorized (8 ch/thread) -------------
// z=0:q, z=1:k (fp16 single) ; z=2: v (fp16 hi/lo). Weights pre-transposed [tap][C].
__global__ void __launch_bounds__(256) dwconv_all_k(
    const uint4* q, const uint4* k, const uint4* vh, const uint4* vl,
    const float* dwt, const float* bq, const float* bk, const float* bv,
    uint4* oq, uint4* ok, uint4* ovh, uint4* ovl)
{
    const int z = blockIdx.y;
    const int i4 = blockIdx.x * 256 + threadIdx.x;   // < 524288
    const int c8 = i4 & 127, m = i4 >> 7, s = m & (SEQ - 1);
    const int c0 = c8 * 8;

    const float* wt = dwt + z * 3 * CCH;
    const float* bb = (z == 0) ? bq : ((z == 1) ? bk : bv);

    float w0[8], w1[8], w2[8], bvv[8];
    *(float4*)&w0[0] = *(const float4*)(wt + c0);
    *(float4*)&w0[4] = *(const float4*)(wt + c0 + 4);
    *(float4*)&w1[0] = *(const float4*)(wt + CCH + c0);
    *(float4*)&w1[4] = *(const float4*)(wt + CCH + c0 + 4);
    *(float4*)&w2[0] = *(const float4*)(wt + 2 * CCH + c0);
    *(float4*)&w2[4] = *(const float4*)(wt + 2 * CCH + c0 + 4);
    *(float4*)&bvv[0] = *(const float4*)(bb + c0);
    *(float4*)&bvv[4] = *(const float4*)(bb + c0 + 4);

    const uint4 zero4 = make_uint4(0, 0, 0, 0);
    float xc_[8], xm_[8], xp_[8];

    if (z < 2) {
        const uint4* in = z ? k : q;
        uint4 xc = in[i4];
        uint4 xm = (s > 0) ? in[i4 - 128] : zero4;
        uint4 xp = (s < SEQ - 1) ? in[i4 + 128] : zero4;
        #pragma unroll
        for (int j = 0; j < 4; j++) {
            float2 a = __half22float2(((const __half2*)&xc)[j]); xc_[2*j] = a.x; xc_[2*j+1] = a.y;
            float2 b = __half22float2(((const __half2*)&xm)[j]); xm_[2*j] = b.x; xm_[2*j+1] = b.y;
            float2 c = __half22float2(((const __half2*)&xp)[j]); xp_[2*j] = c.x; xp_[2*j+1] = c.y;
        }
        uint4 out;
        #pragma unroll
        for (int j = 0; j < 4; j++) {
            float r0 = xm_[2*j]   * w0[2*j]   + xc_[2*j]   * w1[2*j]   + xp_[2*j]   * w2[2*j]   + bvv[2*j];
            float r1 = xm_[2*j+1] * w0[2*j+1] + xc_[2*j+1] * w1[2*j+1] + xp_[2*j+1] * w2[2*j+1] + bvv[2*j+1];
            ((uint32_t*)&out)[j] = pack2f16(r0, r1);
        }
        (z ? ok : oq)[i4] = out;
    } else {
        uint4 xch = vh[i4], xcl = vl[i4];
        uint4 xmh = zero4, xml = zero4, xph = zero4, xpl = zero4;
        if (s > 0)       { xmh = vh[i4 - 128]; xml = vl[i4 - 128]; }
        if (s < SEQ - 1) { xph = vh[i4 + 128]; xpl = vl[i4 + 128]; }
        #pragma unroll
        for (int j = 0; j < 4; j++) {
            float2 ah = __half22float2(((const __half2*)&xch)[j]);
            float2 al = __half22float2(((const __half2*)&xcl)[j]);
            xc_[2*j] = ah.x + al.x; xc_[2*j+1] = ah.y + al.y;
            float2 bh = __half22float2(((const __half2*)&xmh)[j]);
            float2 bl = __half22float2(((const __half2*)&xml)[j]);
            xm_[2*j] = bh.x + bl.x; xm_[2*j+1] = bh.y + bl.y;
            float2 ch = __half22float2(((const __half2*)&xph)[j]);
            float2 cl = __half22float2(((const __half2*)&xpl)[j]);
            xp_[2*j] = ch.x + cl.x; xp_[2*j+1] = ch.y + cl.y;
        }
        uint4 oh, ol;
        #pragma unroll
        for (int j = 0; j < 4; j++) {
            float r0 = xm_[2*j]   * w0[2*j]   + xc_[2*j]   * w1[2*j]   + xp_[2*j]   * w2[2*j]   + bvv[2*j];
            float r1 = xm_[2*j+1] * w0[2*j+1] + xc_[2*j+1] * w1[2*j+1] + xp_[2*j+1] * w2[2*j+1] + bvv[2*j+1];
            uint32_t h, l;
            split2h(r0, r1, h, l);
            ((uint32_t*)&oh)[j] = h;
            ((uint32_t*)&ol)[j] = l;
        }
        ovh[i4] = oh;
        ovl[i4] = ol;
    }
}

// ---------------- merged l2norm (z=0:q, z=1:k) + vtrans (z=2) --------------------
__global__ void l2vt_k(const __half2* q, const __half2* k, __half2* qn, __half2* kn,
                       const __half* v, __half* vt)
{
    int z = blockIdx.y;
    if (z < 2) {
        const __half2* src = z ? k : q;
        __half2* dst = z ? kn : qn;
        float sc = z ? 1.0f : 0.125f;
        int warp = threadIdx.x >> 5, lane = threadIdx.x & 31;
        size_t g = (size_t)blockIdx.x * 8 + warp;
        float2 x = __half22float2(src[g * 32 + lane]);
        float ss = x.x * x.x + x.y * x.y;
        #pragma unroll
        for (int o = 16; o; o >>= 1) ss += __shfl_xor_sync(0xffffffffu, ss, o);
        float inv = sc / fmaxf(sqrtf(ss), 1e-12f);
        dst[g * 32 + lane] = __floats2half2_rn(x.x * inv, x.y * inv);
    } else {
        int bx = blockIdx.x;
        if (bx >= 4096) return;
        __shared__ float t[32][33];
        int cB = bx & 31, sB = (bx >> 5) & 63, b = bx >> 11;
        int tx = threadIdx.x & 31, ty = threadIdx.x >> 5;   // 32x8
        int s0 = sB * 32, c0 = cB * 32;
        #pragma unroll
        for (int j = 0; j < 4; j++)
            t[ty + 8 * j][tx] = __half2float(v[(size_t)(b * SEQ + s0 + ty + 8 * j) * CCH + c0 + tx]);
        __syncthreads();
        #pragma unroll
        for (int j = 0; j < 4; j++)
            vt[(size_t)(b * CCH + c0 + ty + 8 * j) * SEQ + s0 + tx] = __float2half(t[tx][ty + 8 * j]);
    }
}

// ================= flash attention: cp.async + ldmatrix fp16, 4-stage ============
#define AT_STW 4608
#define AT_NST 4
#define AT_SMEM (AT_NST*AT_STW*4)    // 73728 B

__global__ void __launch_bounds__(256, 2) attn_mma_k(const __half* __restrict__ Qh,
                                                     const __half* __restrict__ Kh,
                                                     const __half* __restrict__ Vt,
                                                     const int* __restrict__ mask,
                                                     __half* __restrict__ AOh,
                                                     __half* __restrict__ AOl)
{
    const int qt = blockIdx.x, h = blockIdx.y, bb = blockIdx.z;
    extern __shared__ uint32_t asw[];
    __shared__ int s_mask[AT_NST][64];

    const int tid = threadIdx.x, lane = tid & 31, w = tid >> 5;
    const int gr = lane >> 2, gc = lane & 3;
    const uint32_t sbase = smem_u32(asw);

    const __half* kb = Kh + ((size_t)bb * SEQ) * CCH + h * HDD;
    const __half* vb = Vt + ((size_t)(bb * NHH + h)) * HDD * SEQ;

    const uint32_t ldmoff =
        (uint32_t)(((lane >> 4) << 3) + (lane & 7)) * 144 + (((lane >> 3) & 1) << 4);

    auto issue = [&](int jt) {
        int slot = jt % AT_NST;
        uint32_t kdst = sbase + slot * AT_STW * 4;
        uint32_t vdst = kdst + 2304 * 4;
        #pragma unroll
        for (int j = 0; j < 2; j++) {
            int c = tid + 256 * j;
            int row = c >> 3, ch = c & 7;
            uint32_t d = kdst + (row * 36 + ch * 4) * 4;
            const __half* s = kb + (size_t)(jt * 64 + row) * CCH + ch * 8;
            asm volatile("cp.async.cg.shared.global [%0], [%1], 16;" :: "r"(d), "l"(s));
        }
        #pragma unroll
        for (int j = 0; j < 2; j++) {
            int c = tid + 256 * j;
            int row = c >> 3, ch = c & 7;
            uint32_t d = vdst + (row * 36 + ch * 4) * 4;
            const __half* s = vb + (size_t)row * SEQ + jt * 64 + ch * 8;
            asm volatile("cp.async.cg.shared.global [%0], [%1], 16;" :: "r"(d), "l"(s));
        }
        if (tid < 16) {
            uint32_t d = smem_u32(&s_mask[slot][0]) + tid * 16;
            const int* s = mask + bb * SEQ + jt * 64 + tid * 4;
            asm volatile("cp.async.cg.shared.global [%0], [%1], 16;" :: "r"(d), "l"(s));
        }
        asm volatile("cp.async.commit_group;");
    };

    issue(0);
    issue(1);
    issue(2);

    uint32_t qa[4][4];
    {
        const __half* qb = Qh + ((size_t)(bb * SEQ + qt * 128)) * CCH + h * HDD;
        int r0 = w * 16 + gr, r1 = r0 + 8;
        #pragma unroll
        for (int ks = 0; ks < 4; ks++) {
            int c = ks * 16 + 2 * gc;
            qa[ks][0] = *(const uint32_t*)(qb + (size_t)r0 * CCH + c);
            qa[ks][1] = *(const uint32_t*)(qb + (size_t)r1 * CCH + c);
            qa[ks][2] = *(const uint32_t*)(qb + (size_t)r0 * CCH + c + 8);
            qa[ks][3] = *(const uint32_t*)(qb + (size_t)r1 * CCH + c + 8);
        }
    }

    float o[8][4];
    #pragma unroll
    for (int ht = 0; ht < 8; ht++)
        #pragma unroll
        for (int e = 0; e < 4; e++) o[ht][e] = 0.f;
    float l0 = 0.f, l1 = 0.f;

    #pragma unroll 1
    for (int jt = 0; jt < 32; jt++) {
        const int slot = jt % AT_NST;
        int rem = 31 - jt;
        if (rem >= 2)      asm volatile("cp.async.wait_group 2;");
        else if (rem == 1) asm volatile("cp.async.wait_group 1;");
        else               asm volatile("cp.async.wait_group 0;");
        __syncthreads();
        if (jt + 3 < 32) issue(jt + 3);

        uint32_t kaddr = sbase + slot * AT_STW * 4 + ldmoff;
        uint32_t vaddr = kaddr + 2304 * 4;

        float s[8][4];
        #pragma unroll
        for (int nt = 0; nt < 8; nt++)
            #pragma unroll
            for (int e = 0; e < 4; e++) s[nt][e] = 0.f;
        #pragma unroll
        for (int ks = 0; ks < 4; ks++) {
            uint32_t bf[8][2];
            #pragma unroll
            for (int p = 0; p < 4; p++)
                ldm_x4(bf[2 * p][0], bf[2 * p][1], bf[2 * p + 1][0], bf[2 * p + 1][1],
                       kaddr + p * (16 * 144) + ks * 32);
            #pragma unroll
            for (int nt = 0; nt < 8; nt++)
                mma_f16_b(s[nt], qa[ks], bf[nt][0], bf[nt][1]);
        }

        #pragma unroll
        for (int nt = 0; nt < 8; nt++) {
            int c0 = nt * 8 + 2 * gc;
            bool ok0 = s_mask[slot][c0] != 0;
            bool ok1 = s_mask[slot][c0 + 1] != 0;
            s[nt][0] = ok0 ? exp_small(s[nt][0]) : 0.f;
            s[nt][1] = ok1 ? exp_small(s[nt][1]) : 0.f;
            s[nt][2] = ok0 ? exp_small(s[nt][2]) : 0.f;
            s[nt][3] = ok1 ? exp_small(s[nt][3]) : 0.f;
            l0 += s[nt][0] + s[nt][1];
            l1 += s[nt][2] + s[nt][3];
        }

        #pragma unroll
        for (int ks = 0; ks < 4; ks++) {
            uint32_t aF[4];
            aF[0] = pack2f16(s[2 * ks][0],     s[2 * ks][1]);
            aF[1] = pack2f16(s[2 * ks][2],     s[2 * ks][3]);
            aF[2] = pack2f16(s[2 * ks + 1][0], s[2 * ks + 1][1]);
            aF[3] = pack2f16(s[2 * ks + 1][2], s[2 * ks + 1][3]);
            uint32_t vf[8][2];
            #pragma unroll
            for (int p = 0; p < 4; p++)
                ldm_x4(vf[2 * p][0], vf[2 * p][1], vf[2 * p + 1][0], vf[2 * p + 1][1],
                       vaddr + p * (16 * 144) + ks * 32);
            #pragma unroll
            for (int ht = 0; ht < 8; ht++)
                mma_f16_b(o[ht], aF, vf[ht][0], vf[ht][1]);
        }
    }

    l0 += __shfl_xor_sync(0xffffffffu, l0, 1);
    l0 += __shfl_xor_sync(0xffffffffu, l0, 2);
    l1 += __shfl_xor_sync(0xffffffffu, l1, 1);
    l1 += __shfl_xor_sync(0xffffffffu, l1, 2);
    {
        float inv0 = 1.f / l0, inv1 = 1.f / l1;
        int r0 = w * 16 + gr, r1 = r0 + 8;
        size_t base = ((size_t)(bb * SEQ + qt * 128)) * CCH + h * HDD;
        __half* Oh = AOh + base;
        __half* Ol = AOl + base;
        #pragma unroll
        for (int ht = 0; ht < 8; ht++) {
            int c = ht * 8 + 2 * gc;
            uint32_t hh, ll;
            split2h(o[ht][0] * inv0, o[ht][1] * inv0, hh, ll);
            *(uint32_t*)(Oh + (size_t)r0 * CCH + c) = hh;
            *(uint32_t*)(Ol + (size_t)r0 * CCH + c) = ll;
            split2h(o[ht][2] * inv1, o[ht][3] * inv1, hh, ll);
            *(uint32_t*)(Oh + (size_t)r1 * CCH + c) = hh;
            *(uint32_t*)(Ol + (size_t)r1 * CCH + c) = ll;
        }
    }
}

// ---------------- host launcher ---------------------------------------------------
extern "C" void kernel_launch(void* const* d_in, const int* in_sizes, int n_in,
                              void* d_out, int out_size)
{
    const float* x    = (const float*)d_in[0];
    const int*   mask = (const int*)d_in[1];
    const float* wq   = (const float*)d_in[2];
    const float* bq   = (const float*)d_in[3];
    const float* wk   = (const float*)d_in[4];
    const float* bk   = (const float*)d_in[5];
    const float* wv   = (const float*)d_in[6];
    const float* bv   = (const float*)d_in[7];
    const float* qdww = (const float*)d_in[8];
    const float* qdwb = (const float*)d_in[9];
    const float* qpww = (const float*)d_in[10];
    const float* qpwb = (const float*)d_in[11];
    const float* kdww = (const float*)d_in[12];
    const float* kdwb = (const float*)d_in[13];
    const float* kpww = (const float*)d_in[14];
    const float* kpwb = (const float*)d_in[15];
    const float* vdww = (const float*)d_in[16];
    const float* vdwb = (const float*)d_in[17];
    const float* vpww = (const float*)d_in[18];
    const float* vpwb = (const float*)d_in[19];
    const float* wo   = (const float*)d_in[20];
    const float* bo   = (const float*)d_in[21];
    float* out = (float*)d_out;

    __half *xh, *xlo, *w16, *q16, *k16, *vhi, *vlo, *qc16, *kc16, *vchi, *vclo;
    __half *qpw, *kpw, *vpw, *qn, *kn, *vt, *aoh, *aol;
    float* dwt;
    cudaGetSymbolAddress((void**)&xh,  g_xh);
    cudaGetSymbolAddress((void**)&xlo, g_xlo);
    cudaGetSymbolAddress((void**)&w16, g_w16);
    cudaGetSymbolAddress((void**)&dwt, g_dwt);
    cudaGetSymbolAddress((void**)&q16, g_q16);
    cudaGetSymbolAddress((void**)&k16, g_k16);
    cudaGetSymbolAddress((void**)&vhi, g_vhi);
    cudaGetSymbolAddress((void**)&vlo, g_vlo);
    cudaGetSymbolAddress((void**)&qc16, g_qc16);
    cudaGetSymbolAddress((void**)&kc16, g_kc16);
    cudaGetSymbolAddress((void**)&vchi, g_vchi);
    cudaGetSymbolAddress((void**)&vclo, g_vclo);
    cudaGetSymbolAddress((void**)&qpw, g_qpw);
    cudaGetSymbolAddress((void**)&kpw, g_kpw);
    cudaGetSymbolAddress((void**)&vpw, g_vpw);
    cudaGetSymbolAddress((void**)&qn,  g_qn);
    cudaGetSymbolAddress((void**)&kn,  g_kn);
    cudaGetSymbolAddress((void**)&vt,  g_vt);
    cudaGetSymbolAddress((void**)&aoh, g_aoh);
    cudaGetSymbolAddress((void**)&aol, g_aol);

    __half* wqh  = w16 + 0 * (size_t)DIMM * CCH;
    __half* wkh  = w16 + 1 * (size_t)DIMM * CCH;
    __half* wvh  = w16 + 2 * (size_t)DIMM * CCH;
    __half* qpwh = w16 + 3 * (size_t)DIMM * CCH;
    __half* kpwh = w16 + 4 * (size_t)DIMM * CCH;
    __half* vpwh = w16 + 5 * (size_t)DIMM * CCH;
    __half* woh  = w16 + 6 * (size_t)DIMM * CCH;

    cudaFuncSetAttribute(gemm_h_k<true>,  cudaFuncAttributeMaxDynamicSharedMemorySize, G_SMEM);
    cudaFuncSetAttribute(gemm_h_k<false>, cudaFuncAttributeMaxDynamicSharedMemorySize, G_SMEM);
    cudaFuncSetAttribute(attn_mma_k, cudaFuncAttributeMaxDynamicSharedMemorySize, AT_SMEM);

    // 0) prep: weights (+ transposed dw weights) + x to fp16
    WC wc;
    wc.s[0] = wq;  wc.d[0] = wqh;
    wc.s[1] = wk;  wc.d[1] = wkh;
    wc.s[2] = wv;  wc.d[2] = wvh;
    wc.s[3] = qpww; wc.d[3] = qpwh;
    wc.s[4] = kpww; wc.d[4] = kpwh;
    wc.s[5] = vpww; wc.d[5] = vpwh;
    wc.s[6] = wo;  wc.d[6] = woh;
    wc.dw[0] = qdww; wc.dw[1] = kdww; wc.dw[2] = vdww;
    wc.dwt = dwt;
    wconv_k<<<dim3(2048, 8), 256>>>(wc);
    xconv_k<<<8192, 256>>>((const float2*)x, (uint32_t*)xh, (uint32_t*)xlo);

    dim3 grid_3(8, 64, 3), grid_1(8, 64, 1);

    // 1) QKV projection + SiLU (fused; q,k prod=1, v prod=2)
    gemm_h_k<true><<<grid_3, 256, G_SMEM>>>(
        GH{xh, 0, wqh, bq, q16, 0, 1, 1},
        GH{xh, 0, wkh, bk, k16, 0, 1, 1},
        GH{xh, xlo, wvh, bv, vhi, vlo, 2, 2});

    // 2) depthwise conv (fused q,k,v; vectorized)
    dwconv_all_k<<<dim3(2048, 3), 256>>>(
        (const uint4*)q16, (const uint4*)k16, (const uint4*)vhi, (const uint4*)vlo,
        dwt, qdwb, kdwb, vdwb,
        (uint4*)qc16, (uint4*)kc16, (uint4*)vchi, (uint4*)vclo);

    // 3) pointwise conv (fused)
    gemm_h_k<false><<<grid_3, 256, G_SMEM>>>(
        GH{qc16, 0, qpwh, qpwb, qpw, 0, 1, 1},
        GH{kc16, 0, kpwh, kpwb, kpw, 0, 1, 1},
        GH{vchi, vclo, vpwh, vpwb, vpw, 0, 2, 1});

    // 4) merged l2norm (q scaled 0.125) + v transpose
    l2vt_k<<<dim3(8192, 3), 256>>>((const __half2*)qpw, (const __half2*)kpw,
                                   (__half2*)qn, (__half2*)kn, vpw, vt);

    // 5) flash attention -> fp16 hi/lo
    attn_mma_k<<<dim3(SEQ / 128, NHH, BSZ), 256, AT_SMEM>>>(qn, kn, vt, mask, aoh, aol);

    // 6) output projection -> d_out (fp32)
    gemm_h_k<false><<<grid_1, 256, G_SMEM>>>(
        GH{aoh, aol, woh, bo, out, 0, 2, 0},
        GH{aoh, aol, woh, bo, out, 0, 2, 0},
        GH{aoh, aol, woh, bo, out, 0, 2, 0});
}